// round 1
// baseline (speedup 1.0000x reference)
#include <cuda_runtime.h>
#include <math.h>

// Problem dims (fixed by the dataset)
#define BB   8
#define HHH  64
#define WWW  64
#define VV   4096      // HHH*WWW
#define CIN  256
#define FF   128
#define EE   256
#define COUT 256
#define SPLITK 16

// ---------------- scratch (static device globals; no allocation allowed) ----
__device__ float g_phi [BB*VV*FF];        // 16 MB
__device__ float g_M   [BB*VV*EE];        // 32 MB
__device__ float g_t   [BB*FF*EE];
__device__ float g_H   [BB*VV*EE];        // 32 MB (|H|)
__device__ float g_D   [BB*VV];           // holds D^-1/2 after k_degD
__device__ float g_Be  [BB*EE];           // holds 1/Be after k_finishBe
__device__ float g_tmp [BB*EE*CIN];
__device__ float g_R   [BB*VV*CIN];       // 32 MB  (x - agg)
__device__ float g_a   [BB*FF];
__device__ float g_xpart[BB*32*CIN];
__device__ float g_bpart[BB*16*EE];
__device__ float g_part1[SPLITK*BB*FF*EE];   // ~17 MB  (t partials)
__device__ float g_part2[SPLITK*BB*EE*CIN];  // ~34 MB  (tmp partials)

// ---------------------------------------------------------------------------
// Generic tiled SGEMM, C[M,N] = (rowScaleA ⊙ A[M,K]) * (kScaleB ⊙ B[K,N])
// mode 0: C = acc (+bias)
// mode 1: C = |acc|
// mode 2: C = resid - acc
// 64x64 tile, 256 threads, 4x4 micro-tile, K-chunk 16. M%64==0, N%64==0, K%16==0.
// ---------------------------------------------------------------------------
__global__ __launch_bounds__(256) void sgemm_nn(
    const float* __restrict__ A, const float* __restrict__ Bm, float* __restrict__ C,
    int M, int N, int K,
    long aB, long bB, long cB,
    const float* __restrict__ aRS, int aRSb,
    const float* __restrict__ bKS, int bKSb,
    const float* __restrict__ bias,
    int mode, const float* __restrict__ resid, long rB)
{
    __shared__ float As[64][20];   // [row][k] padded: row stride 80B (16B aligned)
    __shared__ float Bs[16][64];   // [k][col]

    const int b  = blockIdx.z;
    const float* Ab = A + (long)b * aB;
    const float* Bb = Bm + (long)b * bB;
    float* Cb = C + (long)b * cB;

    const int m0 = blockIdx.y * 64, n0 = blockIdx.x * 64;
    const int tid = threadIdx.x;
    const int tx = tid & 15, ty = tid >> 4;
    const int lr = tid >> 2, lk = (tid & 3) * 4;   // A-tile load coords
    const int bk = tid >> 4, bn = (tid & 15) * 4;  // B-tile load coords

    float acc[4][4] = {};

    for (int k0 = 0; k0 < K; k0 += 16) {
        float4 av = *(const float4*)&Ab[(long)(m0 + lr) * K + k0 + lk];
        if (aRS) { float s = aRS[b * aRSb + m0 + lr]; av.x*=s; av.y*=s; av.z*=s; av.w*=s; }
        *(float4*)&As[lr][lk] = av;

        float4 bv = *(const float4*)&Bb[(long)(k0 + bk) * N + n0 + bn];
        if (bKS) { float s = bKS[b * bKSb + k0 + bk]; bv.x*=s; bv.y*=s; bv.z*=s; bv.w*=s; }
        *(float4*)&Bs[bk][bn] = bv;

        __syncthreads();
        #pragma unroll
        for (int kk = 0; kk < 16; kk++) {
            float ar[4];
            ar[0] = As[ty*4+0][kk]; ar[1] = As[ty*4+1][kk];
            ar[2] = As[ty*4+2][kk]; ar[3] = As[ty*4+3][kk];
            float4 bq = *(float4*)&Bs[kk][tx*4];
            #pragma unroll
            for (int i = 0; i < 4; i++) {
                acc[i][0] += ar[i]*bq.x; acc[i][1] += ar[i]*bq.y;
                acc[i][2] += ar[i]*bq.z; acc[i][3] += ar[i]*bq.w;
            }
        }
        __syncthreads();
    }

    #pragma unroll
    for (int i = 0; i < 4; i++) {
        long m   = m0 + ty*4 + i;
        long off = m * N + n0 + tx*4;
        float4 cv = make_float4(acc[i][0], acc[i][1], acc[i][2], acc[i][3]);
        if (bias) {
            float4 bb4 = *(const float4*)&bias[n0 + tx*4];
            cv.x += bb4.x; cv.y += bb4.y; cv.z += bb4.z; cv.w += bb4.w;
        }
        if (mode == 1) {
            cv.x = fabsf(cv.x); cv.y = fabsf(cv.y); cv.z = fabsf(cv.z); cv.w = fabsf(cv.w);
        } else if (mode == 2) {
            float4 rv = *(const float4*)&resid[(long)b * rB + off];
            cv.x = rv.x - cv.x; cv.y = rv.y - cv.y; cv.z = rv.z - cv.z; cv.w = rv.w - cv.w;
        }
        *(float4*)&Cb[off] = cv;
    }
}

// ---------------------------------------------------------------------------
// Transposed-A GEMM with split-K: C[M,N] = A^T * B over a K-slice.
// A stored as [Kd, lda] (row-major, columns are the M dim). blockIdx.z = b*split+s.
// Writes its own partial slice at C + blockIdx.z*cB (deterministic, no atomics).
// ---------------------------------------------------------------------------
__global__ __launch_bounds__(256) void sgemm_tn(
    const float* __restrict__ A, const float* __restrict__ Bm, float* __restrict__ C,
    int M, int N, int Kd, int lda,
    long aB, long bB, long cB,
    const float* __restrict__ kS, int kSb,
    int split)
{
    __shared__ float As[16][68];   // [k][m] padded: row stride 272B (16B aligned)
    __shared__ float Bs[16][64];

    const int zb = blockIdx.z;
    const int b = zb / split, s = zb % split;
    const int kchunk = Kd / split;
    const int kbeg = s * kchunk, kend = kbeg + kchunk;

    const float* Ab = A + (long)b * aB;
    const float* Bb = Bm + (long)b * bB;
    float* Cb = C + (long)zb * cB;

    const int m0 = blockIdx.y * 64, n0 = blockIdx.x * 64;
    const int tid = threadIdx.x, tx = tid & 15, ty = tid >> 4;
    const int lk = tid >> 4, lm = (tid & 15) * 4;

    float acc[4][4] = {};

    for (int k0 = kbeg; k0 < kend; k0 += 16) {
        float4 av = *(const float4*)&Ab[(long)(k0 + lk) * lda + m0 + lm];
        if (kS) { float sc = kS[b * kSb + k0 + lk]; av.x*=sc; av.y*=sc; av.z*=sc; av.w*=sc; }
        *(float4*)&As[lk][lm] = av;
        *(float4*)&Bs[lk][lm] = *(const float4*)&Bb[(long)(k0 + lk) * N + n0 + lm];

        __syncthreads();
        #pragma unroll
        for (int kk = 0; kk < 16; kk++) {
            float4 aq = *(float4*)&As[kk][ty*4];
            float4 bq = *(float4*)&Bs[kk][tx*4];
            acc[0][0]+=aq.x*bq.x; acc[0][1]+=aq.x*bq.y; acc[0][2]+=aq.x*bq.z; acc[0][3]+=aq.x*bq.w;
            acc[1][0]+=aq.y*bq.x; acc[1][1]+=aq.y*bq.y; acc[1][2]+=aq.y*bq.z; acc[1][3]+=aq.y*bq.w;
            acc[2][0]+=aq.z*bq.x; acc[2][1]+=aq.z*bq.y; acc[2][2]+=aq.z*bq.z; acc[2][3]+=aq.z*bq.w;
            acc[3][0]+=aq.w*bq.x; acc[3][1]+=aq.w*bq.y; acc[3][2]+=aq.w*bq.z; acc[3][3]+=aq.w*bq.w;
        }
        __syncthreads();
    }

    #pragma unroll
    for (int i = 0; i < 4; i++) {
        long off = (long)(m0 + ty*4 + i) * N + n0 + tx*4;
        *(float4*)&Cb[off] = make_float4(acc[i][0], acc[i][1], acc[i][2], acc[i][3]);
    }
}

// Deterministic reduction of split-K partial slices
__global__ void k_reduce_split(const float* __restrict__ part, float* __restrict__ out,
                               int mn, int batches, int split)
{
    long i = (long)blockIdx.x * 256 + threadIdx.x;
    if (i >= (long)batches * mn) return;
    int b = (int)(i / mn), r = (int)(i % mn);
    float sum = 0.f;
    for (int s = 0; s < split; s++)
        sum += part[((long)(b * split + s)) * mn + r];
    out[i] = sum;
}

// ---------------------------------------------------------------------------
// 7x7 SAME conv as 49 shifted K-chunked GEMM accumulations.
// out[b,v,e] = bias[e] + sum_{tap,c} x[b, v_shift(tap), c] * w[tap, c, e]
// ---------------------------------------------------------------------------
__global__ __launch_bounds__(256) void conv7(const float* __restrict__ x,
                                             const float* __restrict__ w,
                                             const float* __restrict__ bias,
                                             float* __restrict__ out)
{
    __shared__ float As[64][20];
    __shared__ float Bs[16][64];

    const int b  = blockIdx.z;
    const int v0 = blockIdx.y * 64, e0 = blockIdx.x * 64;
    const int tid = threadIdx.x, tx = tid & 15, ty = tid >> 4;
    const int lr = tid >> 2, lk = (tid & 3) * 4;
    const int bk = tid >> 4, bn = (tid & 15) * 4;

    const int vh = (v0 + lr) >> 6, vw = (v0 + lr) & 63;
    const float* xb = x + (long)b * VV * CIN;

    float acc[4][4] = {};

    for (int tap = 0; tap < 49; tap++) {
        const int dy = tap / 7 - 3, dx = tap % 7 - 3;
        const int hh = vh + dy, ww2 = vw + dx;
        const bool ok = ((unsigned)hh < 64u) && ((unsigned)ww2 < 64u);
        const float* xrow = xb + (long)(hh * 64 + ww2) * CIN;
        const float* wrow = w + (long)tap * CIN * EE;

        for (int k0 = 0; k0 < CIN; k0 += 16) {
            float4 av = ok ? *(const float4*)&xrow[k0 + lk] : make_float4(0.f,0.f,0.f,0.f);
            *(float4*)&As[lr][lk] = av;
            *(float4*)&Bs[bk][bn] = *(const float4*)&wrow[(long)(k0 + bk) * EE + e0 + bn];

            __syncthreads();
            #pragma unroll
            for (int kk = 0; kk < 16; kk++) {
                float ar[4];
                ar[0] = As[ty*4+0][kk]; ar[1] = As[ty*4+1][kk];
                ar[2] = As[ty*4+2][kk]; ar[3] = As[ty*4+3][kk];
                float4 bq = *(float4*)&Bs[kk][tx*4];
                #pragma unroll
                for (int i = 0; i < 4; i++) {
                    acc[i][0] += ar[i]*bq.x; acc[i][1] += ar[i]*bq.y;
                    acc[i][2] += ar[i]*bq.z; acc[i][3] += ar[i]*bq.w;
                }
            }
            __syncthreads();
        }
    }

    float4 bb4 = *(const float4*)&bias[e0 + tx*4];
    #pragma unroll
    for (int i = 0; i < 4; i++) {
        long off = (long)b * VV * EE + (long)(v0 + ty*4 + i) * EE + e0 + tx*4;
        *(float4*)&out[off] = make_float4(acc[i][0] + bb4.x, acc[i][1] + bb4.y,
                                          acc[i][2] + bb4.z, acc[i][3] + bb4.w);
    }
}

// -------------------- small reduction / pointwise kernels -------------------
// partial channel sums of x over V (deterministic; each block owns a slice)
__global__ void k_xpart(const float* __restrict__ x, float* __restrict__ P)
{
    const int b = blockIdx.x, p = blockIdx.y, c = threadIdx.x;
    const float* base = x + ((long)b * VV + p * 128) * CIN + c;
    float s = 0.f;
    for (int v = 0; v < 128; v++) s += base[(long)v * CIN];
    P[(b * 32 + p) * CIN + c] = s;
}

// a[b,f] = mean_c(x) @ w_a + b_a
__global__ void k_a(const float* __restrict__ P, const float* __restrict__ wa,
                    const float* __restrict__ ba, float* __restrict__ a)
{
    __shared__ float xm[CIN];
    const int b = blockIdx.x, f = threadIdx.x;   // 128 threads
    for (int c = f; c < CIN; c += 128) {
        float s = 0.f;
        for (int p = 0; p < 32; p++) s += P[(b * 32 + p) * CIN + c];
        xm[c] = s * (1.0f / VV);
    }
    __syncthreads();
    float s = ba[f];
    for (int c = 0; c < CIN; c++) s += xm[c] * wa[c * FF + f];
    a[b * FF + f] = s;
}

// D[b,v] = rsqrt( sum_e H[b,v,e] )   (H already >= 0)
__global__ void k_degD(const float* __restrict__ H, float* __restrict__ D)
{
    const int row  = blockIdx.x * 8 + (threadIdx.x >> 5);
    const int lane = threadIdx.x & 31;
    if (row >= BB * VV) return;
    const float* r = H + (long)row * EE;
    float s = 0.f;
    for (int c = lane; c < EE; c += 32) s += r[c];
    for (int o = 16; o; o >>= 1) s += __shfl_xor_sync(0xFFFFFFFFu, s, o);
    if (lane == 0) D[row] = rsqrtf(s);
}

// partial column sums of H over V
__global__ void k_bpart(const float* __restrict__ H, float* __restrict__ P)
{
    const int b = blockIdx.x, p = blockIdx.y, e = threadIdx.x;
    const float* base = H + ((long)b * VV + p * 256) * EE + e;
    float s = 0.f;
    for (int v = 0; v < 256; v++) s += base[(long)v * EE];
    P[(b * 16 + p) * EE + e] = s;
}

// Be[b,e] = 1 / sum_p partials
__global__ void k_finishBe(const float* __restrict__ P, float* __restrict__ Be)
{
    const int b = blockIdx.x, e = threadIdx.x;
    float s = 0.f;
    for (int p = 0; p < 16; p++) s += P[(b * 16 + p) * EE + e];
    Be[b * EE + e] = 1.0f / s;
}

// ---------------------------------------------------------------------------
extern "C" void kernel_launch(void* const* d_in, const int* in_sizes, int n_in,
                              void* d_out, int out_size)
{
    const float* x   = (const float*)d_in[0];
    const float* wph = (const float*)d_in[1];
    const float* bph = (const float*)d_in[2];
    const float* wa  = (const float*)d_in[3];
    const float* ba  = (const float*)d_in[4];
    const float* wm  = (const float*)d_in[5];
    const float* bm  = (const float*)d_in[6];
    const float* w2  = (const float*)d_in[7];
    const float* b2  = (const float*)d_in[8];
    float* out = (float*)d_out;

    float *phi, *Mb, *tb, *Hb, *Db, *Beb, *tmpb, *Rb, *ab, *xp, *bp, *p1, *p2;
    cudaGetSymbolAddress((void**)&phi,  g_phi);
    cudaGetSymbolAddress((void**)&Mb,   g_M);
    cudaGetSymbolAddress((void**)&tb,   g_t);
    cudaGetSymbolAddress((void**)&Hb,   g_H);
    cudaGetSymbolAddress((void**)&Db,   g_D);
    cudaGetSymbolAddress((void**)&Beb,  g_Be);
    cudaGetSymbolAddress((void**)&tmpb, g_tmp);
    cudaGetSymbolAddress((void**)&Rb,   g_R);
    cudaGetSymbolAddress((void**)&ab,   g_a);
    cudaGetSymbolAddress((void**)&xp,   g_xpart);
    cudaGetSymbolAddress((void**)&bp,   g_bpart);
    cudaGetSymbolAddress((void**)&p1,   g_part1);
    cudaGetSymbolAddress((void**)&p2,   g_part2);

    // 1) pooled mean + a vector
    k_xpart<<<dim3(BB, 32), 256>>>(x, xp);
    k_a<<<BB, 128>>>(xp, wa, ba, ab);

    // 2) phi = x @ w_phi + b_phi        [32768,256]x[256,128]
    sgemm_nn<<<dim3(FF/64, (BB*VV)/64, 1), 256>>>(
        x, wph, phi, BB*VV, FF, CIN, 0, 0, 0,
        nullptr, 0, nullptr, 0, bph, 0, nullptr, 0);

    // 3) M = conv7x7(x) + b_m
    conv7<<<dim3(EE/64, VV/64, BB), 256>>>(x, wm, bm, Mb);

    // 4) t = phi^T @ M  (per batch, K=4096, split-K)
    sgemm_tn<<<dim3(EE/64, FF/64, BB*SPLITK), 256>>>(
        phi, Mb, p1, FF, EE, VV, FF,
        (long)VV*FF, (long)VV*EE, (long)FF*EE, nullptr, 0, SPLITK);
    k_reduce_split<<<(BB*FF*EE + 255)/256, 256>>>(p1, tb, FF*EE, BB, SPLITK);

    // 5) H = | phi @ (diag(a) t) |   (a folded as k-scale on B)
    sgemm_nn<<<dim3(EE/64, VV/64, BB), 256>>>(
        phi, tb, Hb, VV, EE, FF,
        (long)VV*FF, (long)FF*EE, (long)VV*EE,
        nullptr, 0, ab, FF, nullptr, 1, nullptr, 0);

    // 6) degrees: D^-1/2 (per v) and 1/Be (per e), deterministic
    k_degD<<<(BB*VV)/8, 256>>>(Hb, Db);
    k_bpart<<<dim3(BB, 16), 256>>>(Hb, bp);
    k_finishBe<<<BB, 256>>>(bp, Beb);

    // 7) tmp = (D^-1/2 H)^T @ x  (K=4096, split-K; D^-1/2 as k-scale)
    sgemm_tn<<<dim3(CIN/64, EE/64, BB*SPLITK), 256>>>(
        Hb, x, p2, EE, CIN, VV, EE,
        (long)VV*EE, (long)VV*CIN, (long)EE*CIN, Db, VV, SPLITK);
    k_reduce_split<<<(BB*EE*CIN + 255)/256, 256>>>(p2, tmpb, EE*CIN, BB, SPLITK);

    // 8) R = x - (D^-1/2 H) @ (diag(1/Be) tmp)
    sgemm_nn<<<dim3(CIN/64, VV/64, BB), 256>>>(
        Hb, tmpb, Rb, VV, CIN, EE,
        (long)VV*EE, (long)EE*CIN, (long)VV*CIN,
        Db, VV, Beb, EE, nullptr, 2, x, (long)VV*CIN);

    // 9) out = R @ weight_2 + bias_2
    sgemm_nn<<<dim3(COUT/64, (BB*VV)/64, 1), 256>>>(
        Rb, w2, out, BB*VV, COUT, CIN, 0, 0, 0,
        nullptr, 0, nullptr, 0, b2, 0, nullptr, 0);
}

// round 2
// speedup vs baseline: 1.2431x; 1.2431x over previous
#include <cuda_runtime.h>
#include <math.h>

// Problem dims (fixed by the dataset)
#define BB   8
#define HHH  64
#define WWW  64
#define VV   4096      // HHH*WWW
#define CIN  256
#define FF   128
#define EE   256
#define COUT 256
#define SPLITK 16

// ---------------- scratch (static device globals; no allocation allowed) ----
__device__ float g_phi [BB*VV*FF];
__device__ float g_M   [BB*VV*EE];
__device__ float g_t   [BB*FF*EE];
__device__ float g_H   [BB*VV*EE];
__device__ float g_D   [BB*VV];
__device__ float g_Be  [BB*EE];
__device__ float g_tmp [BB*EE*CIN];
__device__ float g_R   [BB*VV*CIN];
__device__ float g_a   [BB*FF];
__device__ float g_xpart[BB*32*CIN];
__device__ float g_bpart[BB*16*EE];
__device__ float g_part1[SPLITK*BB*FF*EE];
__device__ float g_part2[SPLITK*BB*EE*CIN];

// ------------------------- FFMA2 helpers ------------------------------------
typedef unsigned long long ull;

__device__ __forceinline__ void ffma2(ull &d, ull a, ull b) {
    asm("fma.rn.f32x2 %0, %1, %2, %0;" : "+l"(d) : "l"(a), "l"(b));
}
__device__ __forceinline__ ull bcast2(float v) {
    ull r;
    asm("mov.b64 %0, {%1, %1};" : "=l"(r) : "f"(v));
    return r;
}
__device__ __forceinline__ float lof(ull v){ return __uint_as_float((unsigned)v); }
__device__ __forceinline__ float hif(ull v){ return __uint_as_float((unsigned)(v>>32)); }

// Shared inner product step: 16 kk over As[k][m], Bs[k][n]
#define INNER_16(As, Bs, acc, tx, ty)                                          \
    _Pragma("unroll")                                                          \
    for (int kk = 0; kk < 16; kk++) {                                          \
        ulonglong2 A0 = *(const ulonglong2*)&As[kk][ty*4];                     \
        ulonglong2 A1 = *(const ulonglong2*)&As[kk][64 + ty*4];                \
        float4 bv0 = *(const float4*)&Bs[kk][tx*4];                            \
        float4 bv1 = *(const float4*)&Bs[kk][64 + tx*4];                       \
        ull bb0 = bcast2(bv0.x), bb1 = bcast2(bv0.y);                          \
        ull bb2 = bcast2(bv0.z), bb3 = bcast2(bv0.w);                          \
        ull bb4 = bcast2(bv1.x), bb5 = bcast2(bv1.y);                          \
        ull bb6 = bcast2(bv1.z), bb7 = bcast2(bv1.w);                          \
        ffma2(acc[0][0], A0.x, bb0); ffma2(acc[0][1], A0.x, bb1);              \
        ffma2(acc[0][2], A0.x, bb2); ffma2(acc[0][3], A0.x, bb3);              \
        ffma2(acc[0][4], A0.x, bb4); ffma2(acc[0][5], A0.x, bb5);              \
        ffma2(acc[0][6], A0.x, bb6); ffma2(acc[0][7], A0.x, bb7);              \
        ffma2(acc[1][0], A0.y, bb0); ffma2(acc[1][1], A0.y, bb1);              \
        ffma2(acc[1][2], A0.y, bb2); ffma2(acc[1][3], A0.y, bb3);              \
        ffma2(acc[1][4], A0.y, bb4); ffma2(acc[1][5], A0.y, bb5);              \
        ffma2(acc[1][6], A0.y, bb6); ffma2(acc[1][7], A0.y, bb7);              \
        ffma2(acc[2][0], A1.x, bb0); ffma2(acc[2][1], A1.x, bb1);              \
        ffma2(acc[2][2], A1.x, bb2); ffma2(acc[2][3], A1.x, bb3);              \
        ffma2(acc[2][4], A1.x, bb4); ffma2(acc[2][5], A1.x, bb5);              \
        ffma2(acc[2][6], A1.x, bb6); ffma2(acc[2][7], A1.x, bb7);              \
        ffma2(acc[3][0], A1.y, bb0); ffma2(acc[3][1], A1.y, bb1);              \
        ffma2(acc[3][2], A1.y, bb2); ffma2(acc[3][3], A1.y, bb3);              \
        ffma2(acc[3][4], A1.y, bb4); ffma2(acc[3][5], A1.y, bb5);              \
        ffma2(acc[3][6], A1.y, bb6); ffma2(acc[3][7], A1.y, bb7);              \
    }

// ---------------------------------------------------------------------------
// 128x128x16 FFMA2 SGEMM, C = (rowScaleA ⊙ A[M,K]) * (kScaleB ⊙ B[K,N])
// mode 0: C = acc (+bias)   mode 1: C = |acc|   mode 2: C = resid - acc
// 256 threads, 8x8 micro-tile (4 M-pairs x 8 N). All dims: M%128, N%128, K%16.
// ---------------------------------------------------------------------------
__global__ __launch_bounds__(256) void sgemm_nn_v2(
    const float* __restrict__ A, const float* __restrict__ Bm, float* __restrict__ C,
    int M, int N, int K,
    long aB, long bB, long cB,
    const float* __restrict__ aRS, int aRSb,
    const float* __restrict__ bKS, int bKSb,
    const float* __restrict__ bias,
    int mode, const float* __restrict__ resid, long rB)
{
    __shared__ float As[16][132];   // [k][m]
    __shared__ float Bs[16][132];   // [k][n]

    const int b  = blockIdx.z;
    const float* Ab = A + (long)b * aB;
    const float* Bb = Bm + (long)b * bB;
    float* Cb = C + (long)b * cB;

    const int m0 = blockIdx.y * 128, n0 = blockIdx.x * 128;
    const int tid = threadIdx.x;
    const int tx = tid & 15, ty = tid >> 4;
    const int lr  = tid >> 1, lkh = (tid & 1) * 8;   // A load: row, k-half
    const int bk  = tid >> 4, bn  = (tid & 15) * 4;  // B load: k-row, col

    ull acc[4][8] = {};
    const int nk = K / 16;

    float4 ra0, ra1, rb0, rb1;
    {
        const float* ap = &Ab[(long)(m0 + lr) * K + lkh];
        ra0 = *(const float4*)ap; ra1 = *(const float4*)(ap + 4);
        if (aRS) {
            float s = aRS[b * aRSb + m0 + lr];
            ra0.x*=s; ra0.y*=s; ra0.z*=s; ra0.w*=s;
            ra1.x*=s; ra1.y*=s; ra1.z*=s; ra1.w*=s;
        }
        const float* bp = &Bb[(long)bk * N + n0];
        rb0 = *(const float4*)(bp + bn); rb1 = *(const float4*)(bp + 64 + bn);
        if (bKS) {
            float s = bKS[b * bKSb + bk];
            rb0.x*=s; rb0.y*=s; rb0.z*=s; rb0.w*=s;
            rb1.x*=s; rb1.y*=s; rb1.z*=s; rb1.w*=s;
        }
    }

    for (int c = 0; c < nk; c++) {
        __syncthreads();
        As[lkh+0][lr] = ra0.x; As[lkh+1][lr] = ra0.y;
        As[lkh+2][lr] = ra0.z; As[lkh+3][lr] = ra0.w;
        As[lkh+4][lr] = ra1.x; As[lkh+5][lr] = ra1.y;
        As[lkh+6][lr] = ra1.z; As[lkh+7][lr] = ra1.w;
        *(float4*)&Bs[bk][bn]      = rb0;
        *(float4*)&Bs[bk][64 + bn] = rb1;
        __syncthreads();

        if (c + 1 < nk) {
            int k0 = (c + 1) * 16;
            const float* ap = &Ab[(long)(m0 + lr) * K + k0 + lkh];
            ra0 = *(const float4*)ap; ra1 = *(const float4*)(ap + 4);
            if (aRS) {
                float s = aRS[b * aRSb + m0 + lr];
                ra0.x*=s; ra0.y*=s; ra0.z*=s; ra0.w*=s;
                ra1.x*=s; ra1.y*=s; ra1.z*=s; ra1.w*=s;
            }
            const float* bp = &Bb[(long)(k0 + bk) * N + n0];
            rb0 = *(const float4*)(bp + bn); rb1 = *(const float4*)(bp + 64 + bn);
            if (bKS) {
                float s = bKS[b * bKSb + k0 + bk];
                rb0.x*=s; rb0.y*=s; rb0.z*=s; rb0.w*=s;
                rb1.x*=s; rb1.y*=s; rb1.z*=s; rb1.w*=s;
            }
        }

        INNER_16(As, Bs, acc, tx, ty)
    }

    float4 biasA = make_float4(0.f,0.f,0.f,0.f), biasB = biasA;
    if (bias) {
        biasA = *(const float4*)&bias[n0 + tx*4];
        biasB = *(const float4*)&bias[n0 + 64 + tx*4];
    }

    #pragma unroll
    for (int p = 0; p < 4; p++) {
        int mbase = m0 + ((p < 2) ? 0 : 64) + ty*4 + (p & 1) * 2;
        #pragma unroll
        for (int h = 0; h < 2; h++) {
            long m = mbase + h;
            float4 c0, c1;
            if (h == 0) {
                c0 = make_float4(lof(acc[p][0]), lof(acc[p][1]), lof(acc[p][2]), lof(acc[p][3]));
                c1 = make_float4(lof(acc[p][4]), lof(acc[p][5]), lof(acc[p][6]), lof(acc[p][7]));
            } else {
                c0 = make_float4(hif(acc[p][0]), hif(acc[p][1]), hif(acc[p][2]), hif(acc[p][3]));
                c1 = make_float4(hif(acc[p][4]), hif(acc[p][5]), hif(acc[p][6]), hif(acc[p][7]));
            }
            c0.x += biasA.x; c0.y += biasA.y; c0.z += biasA.z; c0.w += biasA.w;
            c1.x += biasB.x; c1.y += biasB.y; c1.z += biasB.z; c1.w += biasB.w;
            long off0 = m * N + n0 + tx*4;
            long off1 = m * N + n0 + 64 + tx*4;
            if (mode == 1) {
                c0.x=fabsf(c0.x); c0.y=fabsf(c0.y); c0.z=fabsf(c0.z); c0.w=fabsf(c0.w);
                c1.x=fabsf(c1.x); c1.y=fabsf(c1.y); c1.z=fabsf(c1.z); c1.w=fabsf(c1.w);
            } else if (mode == 2) {
                float4 r0 = *(const float4*)&resid[(long)b * rB + off0];
                float4 r1 = *(const float4*)&resid[(long)b * rB + off1];
                c0.x = r0.x - c0.x; c0.y = r0.y - c0.y; c0.z = r0.z - c0.z; c0.w = r0.w - c0.w;
                c1.x = r1.x - c1.x; c1.y = r1.y - c1.y; c1.z = r1.z - c1.z; c1.w = r1.w - c1.w;
            }
            *(float4*)&Cb[off0] = c0;
            *(float4*)&Cb[off1] = c1;
        }
    }
}

// ---------------------------------------------------------------------------
// 7x7 SAME conv, 128x128 tile (N over E), FFMA2, tap-major chunk loop.
// out[b,v,e] = bias[e] + sum_{tap,c} x[b, shift(v,tap), c] * w[tap, c, e]
// ---------------------------------------------------------------------------
__global__ __launch_bounds__(256) void conv7_v2(const float* __restrict__ x,
                                                const float* __restrict__ w,
                                                const float* __restrict__ bias,
                                                float* __restrict__ out)
{
    __shared__ float As[16][132];
    __shared__ float Bs[16][132];

    const int b  = blockIdx.z;
    const int v0 = blockIdx.y * 128, e0 = blockIdx.x * 128;
    const int tid = threadIdx.x;
    const int tx = tid & 15, ty = tid >> 4;
    const int lr  = tid >> 1, lkh = (tid & 1) * 8;
    const int bk  = tid >> 4, bn  = (tid & 15) * 4;

    const int vh = (v0 + lr) >> 6, vw = (v0 + lr) & 63;
    const float* xb = x + (long)b * VV * CIN;

    ull acc[4][8] = {};

    float4 ra0, ra1, rb0, rb1;

    // chunk iterator: it = tap*16 + kchunk   (CIN/16 == 16 chunks per tap)
    auto loadA = [&](int it, float4 &r0, float4 &r1) {
        int tap = it >> 4, k0 = (it & 15) * 16;
        int dy = tap / 7 - 3, dx = tap % 7 - 3;
        int hh = vh + dy, ww2 = vw + dx;
        if (((unsigned)hh < 64u) && ((unsigned)ww2 < 64u)) {
            const float* p = xb + (long)((hh << 6) + ww2) * CIN + k0 + lkh;
            r0 = *(const float4*)p; r1 = *(const float4*)(p + 4);
        } else {
            r0 = make_float4(0.f,0.f,0.f,0.f); r1 = r0;
        }
    };
    auto loadB = [&](int it, float4 &r0, float4 &r1) {
        int tap = it >> 4, k0 = (it & 15) * 16;
        const float* p = w + ((long)tap * CIN + k0 + bk) * EE + e0;
        r0 = *(const float4*)(p + bn); r1 = *(const float4*)(p + 64 + bn);
    };

    loadA(0, ra0, ra1);
    loadB(0, rb0, rb1);

    for (int it = 0; it < 49 * 16; it++) {
        __syncthreads();
        As[lkh+0][lr] = ra0.x; As[lkh+1][lr] = ra0.y;
        As[lkh+2][lr] = ra0.z; As[lkh+3][lr] = ra0.w;
        As[lkh+4][lr] = ra1.x; As[lkh+5][lr] = ra1.y;
        As[lkh+6][lr] = ra1.z; As[lkh+7][lr] = ra1.w;
        *(float4*)&Bs[bk][bn]      = rb0;
        *(float4*)&Bs[bk][64 + bn] = rb1;
        __syncthreads();

        if (it + 1 < 49 * 16) {
            loadA(it + 1, ra0, ra1);
            loadB(it + 1, rb0, rb1);
        }

        INNER_16(As, Bs, acc, tx, ty)
    }

    float4 biasA = *(const float4*)&bias[e0 + tx*4];
    float4 biasB = *(const float4*)&bias[e0 + 64 + tx*4];

    #pragma unroll
    for (int p = 0; p < 4; p++) {
        int mbase = v0 + ((p < 2) ? 0 : 64) + ty*4 + (p & 1) * 2;
        #pragma unroll
        for (int h = 0; h < 2; h++) {
            long m = mbase + h;
            float4 c0, c1;
            if (h == 0) {
                c0 = make_float4(lof(acc[p][0]), lof(acc[p][1]), lof(acc[p][2]), lof(acc[p][3]));
                c1 = make_float4(lof(acc[p][4]), lof(acc[p][5]), lof(acc[p][6]), lof(acc[p][7]));
            } else {
                c0 = make_float4(hif(acc[p][0]), hif(acc[p][1]), hif(acc[p][2]), hif(acc[p][3]));
                c1 = make_float4(hif(acc[p][4]), hif(acc[p][5]), hif(acc[p][6]), hif(acc[p][7]));
            }
            long off = (long)b * VV * EE + m * EE + e0;
            *(float4*)&out[off + tx*4] = make_float4(c0.x+biasA.x, c0.y+biasA.y,
                                                     c0.z+biasA.z, c0.w+biasA.w);
            *(float4*)&out[off + 64 + tx*4] = make_float4(c1.x+biasB.x, c1.y+biasB.y,
                                                          c1.z+biasB.z, c1.w+biasB.w);
        }
    }
}

// ---------------------------------------------------------------------------
// Transposed-A GEMM with split-K (unchanged from R1)
// ---------------------------------------------------------------------------
__global__ __launch_bounds__(256) void sgemm_tn(
    const float* __restrict__ A, const float* __restrict__ Bm, float* __restrict__ C,
    int M, int N, int Kd, int lda,
    long aB, long bB, long cB,
    const float* __restrict__ kS, int kSb,
    int split)
{
    __shared__ float As[16][68];
    __shared__ float Bs[16][64];

    const int zb = blockIdx.z;
    const int b = zb / split, s = zb % split;
    const int kchunk = Kd / split;
    const int kbeg = s * kchunk, kend = kbeg + kchunk;

    const float* Ab = A + (long)b * aB;
    const float* Bb = Bm + (long)b * bB;
    float* Cb = C + (long)zb * cB;

    const int m0 = blockIdx.y * 64, n0 = blockIdx.x * 64;
    const int tid = threadIdx.x, tx = tid & 15, ty = tid >> 4;
    const int lk = tid >> 4, lm = (tid & 15) * 4;

    float acc[4][4] = {};

    for (int k0 = kbeg; k0 < kend; k0 += 16) {
        float4 av = *(const float4*)&Ab[(long)(k0 + lk) * lda + m0 + lm];
        if (kS) { float sc = kS[b * kSb + k0 + lk]; av.x*=sc; av.y*=sc; av.z*=sc; av.w*=sc; }
        *(float4*)&As[lk][lm] = av;
        *(float4*)&Bs[lk][lm] = *(const float4*)&Bb[(long)(k0 + lk) * N + n0 + lm];

        __syncthreads();
        #pragma unroll
        for (int kk = 0; kk < 16; kk++) {
            float4 aq = *(float4*)&As[kk][ty*4];
            float4 bq = *(float4*)&Bs[kk][tx*4];
            acc[0][0]+=aq.x*bq.x; acc[0][1]+=aq.x*bq.y; acc[0][2]+=aq.x*bq.z; acc[0][3]+=aq.x*bq.w;
            acc[1][0]+=aq.y*bq.x; acc[1][1]+=aq.y*bq.y; acc[1][2]+=aq.y*bq.z; acc[1][3]+=aq.y*bq.w;
            acc[2][0]+=aq.z*bq.x; acc[2][1]+=aq.z*bq.y; acc[2][2]+=aq.z*bq.z; acc[2][3]+=aq.z*bq.w;
            acc[3][0]+=aq.w*bq.x; acc[3][1]+=aq.w*bq.y; acc[3][2]+=aq.w*bq.z; acc[3][3]+=aq.w*bq.w;
        }
        __syncthreads();
    }

    #pragma unroll
    for (int i = 0; i < 4; i++) {
        long off = (long)(m0 + ty*4 + i) * N + n0 + tx*4;
        *(float4*)&Cb[off] = make_float4(acc[i][0], acc[i][1], acc[i][2], acc[i][3]);
    }
}

__global__ void k_reduce_split(const float* __restrict__ part, float* __restrict__ out,
                               int mn, int batches, int split)
{
    long i = (long)blockIdx.x * 256 + threadIdx.x;
    if (i >= (long)batches * mn) return;
    int b = (int)(i / mn), r = (int)(i % mn);
    float sum = 0.f;
    for (int s = 0; s < split; s++)
        sum += part[((long)(b * split + s)) * mn + r];
    out[i] = sum;
}

// -------------------- small reduction / pointwise kernels -------------------
__global__ void k_xpart(const float* __restrict__ x, float* __restrict__ P)
{
    const int b = blockIdx.x, p = blockIdx.y, c = threadIdx.x;
    const float* base = x + ((long)b * VV + p * 128) * CIN + c;
    float s = 0.f;
    for (int v = 0; v < 128; v++) s += base[(long)v * CIN];
    P[(b * 32 + p) * CIN + c] = s;
}

__global__ void k_a(const float* __restrict__ P, const float* __restrict__ wa,
                    const float* __restrict__ ba, float* __restrict__ a)
{
    __shared__ float xm[CIN];
    const int b = blockIdx.x, f = threadIdx.x;
    for (int c = f; c < CIN; c += 128) {
        float s = 0.f;
        for (int p = 0; p < 32; p++) s += P[(b * 32 + p) * CIN + c];
        xm[c] = s * (1.0f / VV);
    }
    __syncthreads();
    float s = ba[f];
    for (int c = 0; c < CIN; c++) s += xm[c] * wa[c * FF + f];
    a[b * FF + f] = s;
}

__global__ void k_degD(const float* __restrict__ H, float* __restrict__ D)
{
    const int row  = blockIdx.x * 8 + (threadIdx.x >> 5);
    const int lane = threadIdx.x & 31;
    if (row >= BB * VV) return;
    const float* r = H + (long)row * EE;
    float s = 0.f;
    for (int c = lane; c < EE; c += 32) s += r[c];
    for (int o = 16; o; o >>= 1) s += __shfl_xor_sync(0xFFFFFFFFu, s, o);
    if (lane == 0) D[row] = rsqrtf(s);
}

__global__ void k_bpart(const float* __restrict__ H, float* __restrict__ P)
{
    const int b = blockIdx.x, p = blockIdx.y, e = threadIdx.x;
    const float* base = H + ((long)b * VV + p * 256) * EE + e;
    float s = 0.f;
    for (int v = 0; v < 256; v++) s += base[(long)v * EE];
    P[(b * 16 + p) * EE + e] = s;
}

__global__ void k_finishBe(const float* __restrict__ P, float* __restrict__ Be)
{
    const int b = blockIdx.x, e = threadIdx.x;
    float s = 0.f;
    for (int p = 0; p < 16; p++) s += P[(b * 16 + p) * EE + e];
    Be[b * EE + e] = 1.0f / s;
}

// ---------------------------------------------------------------------------
extern "C" void kernel_launch(void* const* d_in, const int* in_sizes, int n_in,
                              void* d_out, int out_size)
{
    const float* x   = (const float*)d_in[0];
    const float* wph = (const float*)d_in[1];
    const float* bph = (const float*)d_in[2];
    const float* wa  = (const float*)d_in[3];
    const float* ba  = (const float*)d_in[4];
    const float* wm  = (const float*)d_in[5];
    const float* bm  = (const float*)d_in[6];
    const float* w2  = (const float*)d_in[7];
    const float* b2  = (const float*)d_in[8];
    float* out = (float*)d_out;

    float *phi, *Mb, *tb, *Hb, *Db, *Beb, *tmpb, *Rb, *ab, *xp, *bp, *p1, *p2;
    cudaGetSymbolAddress((void**)&phi,  g_phi);
    cudaGetSymbolAddress((void**)&Mb,   g_M);
    cudaGetSymbolAddress((void**)&tb,   g_t);
    cudaGetSymbolAddress((void**)&Hb,   g_H);
    cudaGetSymbolAddress((void**)&Db,   g_D);
    cudaGetSymbolAddress((void**)&Beb,  g_Be);
    cudaGetSymbolAddress((void**)&tmpb, g_tmp);
    cudaGetSymbolAddress((void**)&Rb,   g_R);
    cudaGetSymbolAddress((void**)&ab,   g_a);
    cudaGetSymbolAddress((void**)&xp,   g_xpart);
    cudaGetSymbolAddress((void**)&bp,   g_bpart);
    cudaGetSymbolAddress((void**)&p1,   g_part1);
    cudaGetSymbolAddress((void**)&p2,   g_part2);

    // 1) pooled mean + a vector
    k_xpart<<<dim3(BB, 32), 256>>>(x, xp);
    k_a<<<BB, 128>>>(xp, wa, ba, ab);

    // 2) phi = x @ w_phi + b_phi
    sgemm_nn_v2<<<dim3(FF/128, (BB*VV)/128, 1), 256>>>(
        x, wph, phi, BB*VV, FF, CIN, 0, 0, 0,
        nullptr, 0, nullptr, 0, bph, 0, nullptr, 0);

    // 3) M = conv7x7(x) + b_m
    conv7_v2<<<dim3(EE/128, VV/128, BB), 256>>>(x, wm, bm, Mb);

    // 4) t = phi^T @ M  (split-K)
    sgemm_tn<<<dim3(EE/64, FF/64, BB*SPLITK), 256>>>(
        phi, Mb, p1, FF, EE, VV, FF,
        (long)VV*FF, (long)VV*EE, (long)FF*EE, nullptr, 0, SPLITK);
    k_reduce_split<<<(BB*FF*EE + 255)/256, 256>>>(p1, tb, FF*EE, BB, SPLITK);

    // 5) H = | phi @ (diag(a) t) |
    sgemm_nn_v2<<<dim3(EE/128, VV/128, BB), 256>>>(
        phi, tb, Hb, VV, EE, FF,
        (long)VV*FF, (long)FF*EE, (long)VV*EE,
        nullptr, 0, ab, FF, nullptr, 1, nullptr, 0);

    // 6) degrees
    k_degD<<<(BB*VV)/8, 256>>>(Hb, Db);
    k_bpart<<<dim3(BB, 16), 256>>>(Hb, bp);
    k_finishBe<<<BB, 256>>>(bp, Beb);

    // 7) tmp = (D^-1/2 H)^T @ x  (split-K)
    sgemm_tn<<<dim3(CIN/64, EE/64, BB*SPLITK), 256>>>(
        Hb, x, p2, EE, CIN, VV, EE,
        (long)VV*EE, (long)VV*CIN, (long)EE*CIN, Db, VV, SPLITK);
    k_reduce_split<<<(BB*EE*CIN + 255)/256, 256>>>(p2, tmpb, EE*CIN, BB, SPLITK);

    // 8) R = x - (D^-1/2 H) @ (diag(1/Be) tmp)
    sgemm_nn_v2<<<dim3(CIN/128, VV/128, BB), 256>>>(
        Hb, tmpb, Rb, VV, CIN, EE,
        (long)VV*EE, (long)EE*CIN, (long)VV*CIN,
        Db, VV, Beb, EE, nullptr, 2, x, (long)VV*CIN);

    // 9) out = R @ weight_2 + bias_2
    sgemm_nn_v2<<<dim3(COUT/128, (BB*VV)/128, 1), 256>>>(
        Rb, w2, out, BB*VV, COUT, CIN, 0, 0, 0,
        nullptr, 0, nullptr, 0, b2, 0, nullptr, 0);
}

// round 5
// speedup vs baseline: 1.8786x; 1.5112x over previous
#include <cuda_runtime.h>
#include <cuda_bf16.h>
#include <math.h>
#include <stdint.h>

// Problem dims (fixed by the dataset)
#define BB   8
#define HHH  64
#define WWW  64
#define VV   4096      // HHH*WWW
#define CIN  256
#define FF   128
#define EE   256
#define COUT 256
#define SPLITK 16

// ---------------- scratch (static device globals; no allocation allowed) ----
__device__ float g_phi [BB*VV*FF];
__device__ float g_M   [BB*VV*EE];
__device__ float g_t   [BB*FF*EE];
__device__ float g_H   [BB*VV*EE];
__device__ float g_D   [BB*VV];
__device__ float g_Be  [BB*EE];
__device__ float g_tmp [BB*EE*CIN];
__device__ float g_R   [BB*VV*CIN];
__device__ float g_a   [BB*FF];
__device__ float g_xpart[BB*32*CIN];
__device__ float g_bpart[BB*16*EE];
__device__ float g_part1[SPLITK*BB*FF*EE];
__device__ float g_part2[SPLITK*BB*EE*CIN];
__device__ __nv_bfloat16 g_xhi[BB*VV*CIN];
__device__ __nv_bfloat16 g_xlo[BB*VV*CIN];
__device__ __nv_bfloat16 g_whi[49*EE*CIN];   // transposed: [tap][e][c]
__device__ __nv_bfloat16 g_wlo[49*EE*CIN];

// ======================= PTX helpers (mma.sync / cp.async) ==================
__device__ __forceinline__ uint32_t smem_u32(const void* p) {
    uint32_t a;
    asm("{ .reg .u64 t; cvta.to.shared.u64 t, %1; cvt.u32.u64 %0, t; }" : "=r"(a) : "l"(p));
    return a;
}
#define CP_ASYNC16(dst, src, sz) \
    asm volatile("cp.async.cg.shared.global [%0], [%1], 16, %2;" \
                 :: "r"(dst), "l"(src), "r"(sz) : "memory")
#define CP_COMMIT() asm volatile("cp.async.commit_group;" ::: "memory")
#define CP_WAIT(n)  asm volatile("cp.async.wait_group %0;" :: "n"(n) : "memory")
#define LDSM4(r, addr) \
    asm volatile("ldmatrix.sync.aligned.m8n8.x4.shared.b16 {%0,%1,%2,%3}, [%4];" \
                 : "=r"((r)[0]), "=r"((r)[1]), "=r"((r)[2]), "=r"((r)[3]) : "r"(addr))
#define MMA16816(d, a, b0, b1) \
    asm volatile("mma.sync.aligned.m16n8k16.row.col.f32.bf16.bf16.f32 " \
                 "{%0,%1,%2,%3}, {%4,%5,%6,%7}, {%8,%9}, {%0,%1,%2,%3};" \
                 : "+f"((d)[0]), "+f"((d)[1]), "+f"((d)[2]), "+f"((d)[3]) \
                 : "r"((a)[0]), "r"((a)[1]), "r"((a)[2]), "r"((a)[3]), \
                   "r"(b0), "r"(b1))

// ======================= bf16 split preprocessing ===========================
__global__ void k_split_x(const float* __restrict__ x,
                          __nv_bfloat16* __restrict__ xhi, __nv_bfloat16* __restrict__ xlo)
{
    long i = (long)blockIdx.x * 256 + threadIdx.x;
    if (i >= (long)BB*VV*CIN) return;
    float f = x[i];
    __nv_bfloat16 h = __float2bfloat16(f);
    xhi[i] = h;
    xlo[i] = __float2bfloat16(f - __bfloat162float(h));
}

__global__ void k_split_wt(const float* __restrict__ wm,
                           __nv_bfloat16* __restrict__ whi, __nv_bfloat16* __restrict__ wlo)
{
    long i = (long)blockIdx.x * 256 + threadIdx.x;   // (tap, e, c)
    if (i >= 49L*EE*CIN) return;
    int tap = (int)(i / (EE*CIN));
    int r   = (int)(i % (EE*CIN));
    int e = r / CIN, c = r % CIN;
    float f = wm[((long)tap*CIN + c)*EE + e];
    __nv_bfloat16 h = __float2bfloat16(f);
    whi[i] = h;
    wlo[i] = __float2bfloat16(f - __bfloat162float(h));
}

// ======================= HMMA 7x7 conv ======================================
// Implicit GEMM: block tile 128(v) x 128(e), K = 49 taps x 256 ch, 64-ch chunks.
// bf16 hi/lo split, 3 products, fp32 accum via mma.sync.m16n8k16.
// smem rows padded to 72 bf16 (144 B) -> conflict-free ldmatrix.
#define ROWB   144                   // bytes per padded row (72 bf16)
#define TILE_B (128*ROWB)            // 18432 B, one 128x64 bf16 tile
#define OFF_AHI 0
#define OFF_ALO (TILE_B)
#define OFF_BHI (2*TILE_B)
#define OFF_BLO (3*TILE_B)
#define STAGE_B (4*TILE_B)           // 73728 B per stage
#define NCHUNK  196                  // 49 taps * 4 ch-chunks

__global__ __launch_bounds__(256, 1) void conv7_mma(
    const __nv_bfloat16* __restrict__ xhi, const __nv_bfloat16* __restrict__ xlo,
    const __nv_bfloat16* __restrict__ whi, const __nv_bfloat16* __restrict__ wlo,
    const float* __restrict__ bias, float* __restrict__ out)
{
    extern __shared__ __align__(128) char smem[];
    const uint32_t sbase = smem_u32(smem);
    const int tid = threadIdx.x;
    const int wid = tid >> 5, lane = tid & 31;
    const int e0 = blockIdx.x * 128, v0 = blockIdx.y * 128, b = blockIdx.z;
    const int warpm = wid >> 1, warpn = wid & 1;

    // producer coords: each thread owns (row, 32-ch half) of each 128x64 tile
    const int rowA = tid >> 1, half = (tid & 1) * 32;
    const int vh = (v0 + rowA) >> 6, vw = (v0 + rowA) & 63;
    const uint32_t dstRow = rowA * ROWB + half * 2;   // byte offset in tile

    auto issue = [&](int it) {
        const int tap = it >> 2, kc = (it & 3) * 64;
        const int dy = tap / 7 - 3, dx = tap % 7 - 3;
        const int hh = vh + dy, ww = vw + dx;
        const bool okA = ((unsigned)hh < 64u) && ((unsigned)ww < 64u);
        const uint32_t szA = okA ? 16u : 0u;
        const long aoff = okA ? ((long)b*VV + (hh<<6) + ww)*CIN + kc + half
                              : 0;                       // clamped when zfill
        const long boff = ((long)tap*EE + e0 + rowA)*CIN + kc + half;
        const uint32_t stg = sbase + (it & 1) * STAGE_B;
        #pragma unroll
        for (int j = 0; j < 4; j++) {
            CP_ASYNC16(stg + OFF_AHI + dstRow + j*16, xhi + aoff + j*8, szA);
            CP_ASYNC16(stg + OFF_ALO + dstRow + j*16, xlo + aoff + j*8, szA);
            CP_ASYNC16(stg + OFF_BHI + dstRow + j*16, whi + boff + j*8, 16u);
            CP_ASYNC16(stg + OFF_BLO + dstRow + j*16, wlo + boff + j*8, 16u);
        }
        CP_COMMIT();
    };

    float acc[2][8][4];
    #pragma unroll
    for (int mt = 0; mt < 2; mt++)
        #pragma unroll
        for (int nt = 0; nt < 8; nt++)
            #pragma unroll
            for (int q = 0; q < 4; q++) acc[mt][nt][q] = 0.f;

    // per-lane ldmatrix byte offsets (within a tile)
    const uint32_t aLdOff = (warpm*32 + (lane & 15)) * ROWB + (lane >> 4) * 16;
    const uint32_t bLdOff = (warpn*64 + (lane & 7) + ((lane >> 4) & 1) * 8) * ROWB
                          + (((lane >> 3) & 1) * 8) * 2;

    issue(0);

    for (int it = 0; it < NCHUNK; it++) {
        if (it + 1 < NCHUNK) { issue(it + 1); CP_WAIT(1); }
        else                 { CP_WAIT(0); }
        __syncthreads();

        const uint32_t stg = sbase + (it & 1) * STAGE_B;
        #pragma unroll
        for (int k16 = 0; k16 < 4; k16++) {
            const uint32_t kByte = k16 * 32;   // 16 bf16
            uint32_t ah[2][4], al[2][4];
            #pragma unroll
            for (int mt = 0; mt < 2; mt++) {
                uint32_t o = aLdOff + mt * 16 * ROWB + kByte;
                LDSM4(ah[mt], stg + OFF_AHI + o);
                LDSM4(al[mt], stg + OFF_ALO + o);
            }
            #pragma unroll
            for (int np = 0; np < 4; np++) {
                uint32_t o = bLdOff + np * 16 * ROWB + kByte;
                uint32_t bh[4], bl[4];
                LDSM4(bh, stg + OFF_BHI + o);
                LDSM4(bl, stg + OFF_BLO + o);
                #pragma unroll
                for (int mt = 0; mt < 2; mt++) {
                    MMA16816(acc[mt][2*np],   ah[mt], bh[0], bh[1]);
                    MMA16816(acc[mt][2*np+1], ah[mt], bh[2], bh[3]);
                    MMA16816(acc[mt][2*np],   ah[mt], bl[0], bl[1]);
                    MMA16816(acc[mt][2*np+1], ah[mt], bl[2], bl[3]);
                    MMA16816(acc[mt][2*np],   al[mt], bh[0], bh[1]);
                    MMA16816(acc[mt][2*np+1], al[mt], bh[2], bh[3]);
                }
            }
        }
        __syncthreads();
    }

    // epilogue: +bias, store fp32
    const int r = lane >> 2, c2 = (lane & 3) * 2;
    #pragma unroll
    for (int mt = 0; mt < 2; mt++) {
        #pragma unroll
        for (int nt = 0; nt < 8; nt++) {
            const int v = v0 + warpm*32 + mt*16 + r;
            const int e = e0 + warpn*64 + nt*8 + c2;
            const float bx = bias[e], by = bias[e+1];
            float* p0 = out + ((long)b*VV + v)*EE + e;
            float* p1 = p0 + 8L*EE;
            *(float2*)p0 = make_float2(acc[mt][nt][0] + bx, acc[mt][nt][1] + by);
            *(float2*)p1 = make_float2(acc[mt][nt][2] + bx, acc[mt][nt][3] + by);
        }
    }
}

// ------------------------- FFMA2 helpers ------------------------------------
typedef unsigned long long ull;

__device__ __forceinline__ void ffma2(ull &d, ull a, ull b) {
    asm("fma.rn.f32x2 %0, %1, %2, %0;" : "+l"(d) : "l"(a), "l"(b));
}
__device__ __forceinline__ ull bcast2(float v) {
    ull r;
    asm("mov.b64 %0, {%1, %1};" : "=l"(r) : "f"(v));
    return r;
}
__device__ __forceinline__ float lof(ull v){ return __uint_as_float((unsigned)v); }
__device__ __forceinline__ float hif(ull v){ return __uint_as_float((unsigned)(v>>32)); }

#define INNER_16(As, Bs, acc, tx, ty)                                          \
    _Pragma("unroll")                                                          \
    for (int kk = 0; kk < 16; kk++) {                                          \
        ulonglong2 A0 = *(const ulonglong2*)&As[kk][ty*4];                     \
        ulonglong2 A1 = *(const ulonglong2*)&As[kk][64 + ty*4];                \
        float4 bv0 = *(const float4*)&Bs[kk][tx*4];                            \
        float4 bv1 = *(const float4*)&Bs[kk][64 + tx*4];                       \
        ull bb0 = bcast2(bv0.x), bb1 = bcast2(bv0.y);                          \
        ull bb2 = bcast2(bv0.z), bb3 = bcast2(bv0.w);                          \
        ull bb4 = bcast2(bv1.x), bb5 = bcast2(bv1.y);                          \
        ull bb6 = bcast2(bv1.z), bb7 = bcast2(bv1.w);                          \
        ffma2(acc[0][0], A0.x, bb0); ffma2(acc[0][1], A0.x, bb1);              \
        ffma2(acc[0][2], A0.x, bb2); ffma2(acc[0][3], A0.x, bb3);              \
        ffma2(acc[0][4], A0.x, bb4); ffma2(acc[0][5], A0.x, bb5);              \
        ffma2(acc[0][6], A0.x, bb6); ffma2(acc[0][7], A0.x, bb7);              \
        ffma2(acc[1][0], A0.y, bb0); ffma2(acc[1][1], A0.y, bb1);              \
        ffma2(acc[1][2], A0.y, bb2); ffma2(acc[1][3], A0.y, bb3);              \
        ffma2(acc[1][4], A0.y, bb4); ffma2(acc[1][5], A0.y, bb5);              \
        ffma2(acc[1][6], A0.y, bb6); ffma2(acc[1][7], A0.y, bb7);              \
        ffma2(acc[2][0], A1.x, bb0); ffma2(acc[2][1], A1.x, bb1);              \
        ffma2(acc[2][2], A1.x, bb2); ffma2(acc[2][3], A1.x, bb3);              \
        ffma2(acc[2][4], A1.x, bb4); ffma2(acc[2][5], A1.x, bb5);              \
        ffma2(acc[2][6], A1.x, bb6); ffma2(acc[2][7], A1.x, bb7);              \
        ffma2(acc[3][0], A1.y, bb0); ffma2(acc[3][1], A1.y, bb1);              \
        ffma2(acc[3][2], A1.y, bb2); ffma2(acc[3][3], A1.y, bb3);              \
        ffma2(acc[3][4], A1.y, bb4); ffma2(acc[3][5], A1.y, bb5);              \
        ffma2(acc[3][6], A1.y, bb6); ffma2(acc[3][7], A1.y, bb7);              \
    }

// ---------------------------------------------------------------------------
// 128x128x16 FFMA2 SGEMM (modes: 0 bias, 1 abs, 2 resid-minus)
// ---------------------------------------------------------------------------
__global__ __launch_bounds__(256) void sgemm_nn_v2(
    const float* __restrict__ A, const float* __restrict__ Bm, float* __restrict__ C,
    int M, int N, int K,
    long aB, long bB, long cB,
    const float* __restrict__ aRS, int aRSb,
    const float* __restrict__ bKS, int bKSb,
    const float* __restrict__ bias,
    int mode, const float* __restrict__ resid, long rB)
{
    __shared__ float As[16][132];
    __shared__ float Bs[16][132];

    const int b  = blockIdx.z;
    const float* Ab = A + (long)b * aB;
    const float* Bb = Bm + (long)b * bB;
    float* Cb = C + (long)b * cB;

    const int m0 = blockIdx.y * 128, n0 = blockIdx.x * 128;
    const int tid = threadIdx.x;
    const int tx = tid & 15, ty = tid >> 4;
    const int lr  = tid >> 1, lkh = (tid & 1) * 8;
    const int bk  = tid >> 4, bn  = (tid & 15) * 4;

    ull acc[4][8] = {};
    const int nk = K / 16;

    float4 ra0, ra1, rb0, rb1;
    {
        const float* ap = &Ab[(long)(m0 + lr) * K + lkh];
        ra0 = *(const float4*)ap; ra1 = *(const float4*)(ap + 4);
        if (aRS) {
            float s = aRS[b * aRSb + m0 + lr];
            ra0.x*=s; ra0.y*=s; ra0.z*=s; ra0.w*=s;
            ra1.x*=s; ra1.y*=s; ra1.z*=s; ra1.w*=s;
        }
        const float* bp = &Bb[(long)bk * N + n0];
        rb0 = *(const float4*)(bp + bn); rb1 = *(const float4*)(bp + 64 + bn);
        if (bKS) {
            float s = bKS[b * bKSb + bk];
            rb0.x*=s; rb0.y*=s; rb0.z*=s; rb0.w*=s;
            rb1.x*=s; rb1.y*=s; rb1.z*=s; rb1.w*=s;
        }
    }

    for (int c = 0; c < nk; c++) {
        __syncthreads();
        As[lkh+0][lr] = ra0.x; As[lkh+1][lr] = ra0.y;
        As[lkh+2][lr] = ra0.z; As[lkh+3][lr] = ra0.w;
        As[lkh+4][lr] = ra1.x; As[lkh+5][lr] = ra1.y;
        As[lkh+6][lr] = ra1.z; As[lkh+7][lr] = ra1.w;
        *(float4*)&Bs[bk][bn]      = rb0;
        *(float4*)&Bs[bk][64 + bn] = rb1;
        __syncthreads();

        if (c + 1 < nk) {
            int k0 = (c + 1) * 16;
            const float* ap = &Ab[(long)(m0 + lr) * K + k0 + lkh];
            ra0 = *(const float4*)ap; ra1 = *(const float4*)(ap + 4);
            if (aRS) {
                float s = aRS[b * aRSb + m0 + lr];
                ra0.x*=s; ra0.y*=s; ra0.z*=s; ra0.w*=s;
                ra1.x*=s; ra1.y*=s; ra1.z*=s; ra1.w*=s;
            }
            const float* bp = &Bb[(long)(k0 + bk) * N + n0];
            rb0 = *(const float4*)(bp + bn); rb1 = *(const float4*)(bp + 64 + bn);
            if (bKS) {
                float s = bKS[b * bKSb + k0 + bk];
                rb0.x*=s; rb0.y*=s; rb0.z*=s; rb0.w*=s;
                rb1.x*=s; rb1.y*=s; rb1.z*=s; rb1.w*=s;
            }
        }

        INNER_16(As, Bs, acc, tx, ty)
    }

    float4 biasA = make_float4(0.f,0.f,0.f,0.f), biasB = biasA;
    if (bias) {
        biasA = *(const float4*)&bias[n0 + tx*4];
        biasB = *(const float4*)&bias[n0 + 64 + tx*4];
    }

    #pragma unroll
    for (int p = 0; p < 4; p++) {
        int mbase = m0 + ((p < 2) ? 0 : 64) + ty*4 + (p & 1) * 2;
        #pragma unroll
        for (int h = 0; h < 2; h++) {
            long m = mbase + h;
            float4 c0, c1;
            if (h == 0) {
                c0 = make_float4(lof(acc[p][0]), lof(acc[p][1]), lof(acc[p][2]), lof(acc[p][3]));
                c1 = make_float4(lof(acc[p][4]), lof(acc[p][5]), lof(acc[p][6]), lof(acc[p][7]));
            } else {
                c0 = make_float4(hif(acc[p][0]), hif(acc[p][1]), hif(acc[p][2]), hif(acc[p][3]));
                c1 = make_float4(hif(acc[p][4]), hif(acc[p][5]), hif(acc[p][6]), hif(acc[p][7]));
            }
            c0.x += biasA.x; c0.y += biasA.y; c0.z += biasA.z; c0.w += biasA.w;
            c1.x += biasB.x; c1.y += biasB.y; c1.z += biasB.z; c1.w += biasB.w;
            long off0 = m * N + n0 + tx*4;
            long off1 = m * N + n0 + 64 + tx*4;
            if (mode == 1) {
                c0.x=fabsf(c0.x); c0.y=fabsf(c0.y); c0.z=fabsf(c0.z); c0.w=fabsf(c0.w);
                c1.x=fabsf(c1.x); c1.y=fabsf(c1.y); c1.z=fabsf(c1.z); c1.w=fabsf(c1.w);
            } else if (mode == 2) {
                float4 r0 = *(const float4*)&resid[(long)b * rB + off0];
                float4 r1 = *(const float4*)&resid[(long)b * rB + off1];
                c0.x = r0.x - c0.x; c0.y = r0.y - c0.y; c0.z = r0.z - c0.z; c0.w = r0.w - c0.w;
                c1.x = r1.x - c1.x; c1.y = r1.y - c1.y; c1.z = r1.z - c1.z; c1.w = r1.w - c1.w;
            }
            *(float4*)&Cb[off0] = c0;
            *(float4*)&Cb[off1] = c1;
        }
    }
}

// ---------------------------------------------------------------------------
// Transposed-A GEMM with split-K
// ---------------------------------------------------------------------------
__global__ __launch_bounds__(256) void sgemm_tn(
    const float* __restrict__ A, const float* __restrict__ Bm, float* __restrict__ C,
    int M, int N, int Kd, int lda,
    long aB, long bB, long cB,
    const float* __restrict__ kS, int kSb,
    int split)
{
    __shared__ float As[16][68];
    __shared__ float Bs[16][64];

    const int zb = blockIdx.z;
    const int b = zb / split, s = zb % split;
    const int kchunk = Kd / split;
    const int kbeg = s * kchunk, kend = kbeg + kchunk;

    const float* Ab = A + (long)b * aB;
    const float* Bb = Bm + (long)b * bB;
    float* Cb = C + (long)zb * cB;

    const int m0 = blockIdx.y * 64, n0 = blockIdx.x * 64;
    const int tid = threadIdx.x, tx = tid & 15, ty = tid >> 4;
    const int lk = tid >> 4, lm = (tid & 15) * 4;

    float acc[4][4] = {};

    for (int k0 = kbeg; k0 < kend; k0 += 16) {
        float4 av = *(const float4*)&Ab[(long)(k0 + lk) * lda + m0 + lm];
        if (kS) { float sc = kS[b * kSb + k0 + lk]; av.x*=sc; av.y*=sc; av.z*=sc; av.w*=sc; }
        *(float4*)&As[lk][lm] = av;
        *(float4*)&Bs[lk][lm] = *(const float4*)&Bb[(long)(k0 + lk) * N + n0 + lm];

        __syncthreads();
        #pragma unroll
        for (int kk = 0; kk < 16; kk++) {
            float4 aq = *(float4*)&As[kk][ty*4];
            float4 bq = *(float4*)&Bs[kk][tx*4];
            acc[0][0]+=aq.x*bq.x; acc[0][1]+=aq.x*bq.y; acc[0][2]+=aq.x*bq.z; acc[0][3]+=aq.x*bq.w;
            acc[1][0]+=aq.y*bq.x; acc[1][1]+=aq.y*bq.y; acc[1][2]+=aq.y*bq.z; acc[1][3]+=aq.y*bq.w;
            acc[2][0]+=aq.z*bq.x; acc[2][1]+=aq.z*bq.y; acc[2][2]+=aq.z*bq.z; acc[2][3]+=aq.z*bq.w;
            acc[3][0]+=aq.w*bq.x; acc[3][1]+=aq.w*bq.y; acc[3][2]+=aq.w*bq.z; acc[3][3]+=aq.w*bq.w;
        }
        __syncthreads();
    }

    #pragma unroll
    for (int i = 0; i < 4; i++) {
        long off = (long)(m0 + ty*4 + i) * N + n0 + tx*4;
        *(float4*)&Cb[off] = make_float4(acc[i][0], acc[i][1], acc[i][2], acc[i][3]);
    }
}

__global__ void k_reduce_split(const float* __restrict__ part, float* __restrict__ out,
                               int mn, int batches, int split)
{
    long i = (long)blockIdx.x * 256 + threadIdx.x;
    if (i >= (long)batches * mn) return;
    int b = (int)(i / mn), r = (int)(i % mn);
    float sum = 0.f;
    for (int s = 0; s < split; s++)
        sum += part[((long)(b * split + s)) * mn + r];
    out[i] = sum;
}

// -------------------- small reduction / pointwise kernels -------------------
__global__ void k_xpart(const float* __restrict__ x, float* __restrict__ P)
{
    const int b = blockIdx.x, p = blockIdx.y, c = threadIdx.x;
    const float* base = x + ((long)b * VV + p * 128) * CIN + c;
    float s = 0.f;
    for (int v = 0; v < 128; v++) s += base[(long)v * CIN];
    P[(b * 32 + p) * CIN + c] = s;
}

__global__ void k_a(const float* __restrict__ P, const float* __restrict__ wa,
                    const float* __restrict__ ba, float* __restrict__ a)
{
    __shared__ float xm[CIN];
    const int b = blockIdx.x, f = threadIdx.x;
    for (int c = f; c < CIN; c += 128) {
        float s = 0.f;
        for (int p = 0; p < 32; p++) s += P[(b * 32 + p) * CIN + c];
        xm[c] = s * (1.0f / VV);
    }
    __syncthreads();
    float s = ba[f];
    for (int c = 0; c < CIN; c++) s += xm[c] * wa[c * FF + f];
    a[b * FF + f] = s;
}

__global__ void k_degD(const float* __restrict__ H, float* __restrict__ D)
{
    const int row  = blockIdx.x * 8 + (threadIdx.x >> 5);
    const int lane = threadIdx.x & 31;
    if (row >= BB * VV) return;
    const float* r = H + (long)row * EE;
    float s = 0.f;
    for (int c = lane; c < EE; c += 32) s += r[c];
    for (int o = 16; o; o >>= 1) s += __shfl_xor_sync(0xFFFFFFFFu, s, o);
    if (lane == 0) D[row] = rsqrtf(s);
}

__global__ void k_bpart(const float* __restrict__ H, float* __restrict__ P)
{
    const int b = blockIdx.x, p = blockIdx.y, e = threadIdx.x;
    const float* base = H + ((long)b * VV + p * 256) * EE + e;
    float s = 0.f;
    for (int v = 0; v < 256; v++) s += base[(long)v * EE];
    P[(b * 16 + p) * EE + e] = s;
}

__global__ void k_finishBe(const float* __restrict__ P, float* __restrict__ Be)
{
    const int b = blockIdx.x, e = threadIdx.x;
    float s = 0.f;
    for (int p = 0; p < 16; p++) s += P[(b * 16 + p) * EE + e];
    Be[b * EE + e] = 1.0f / s;
}

// ---------------------------------------------------------------------------
extern "C" void kernel_launch(void* const* d_in, const int* in_sizes, int n_in,
                              void* d_out, int out_size)
{
    const float* x   = (const float*)d_in[0];
    const float* wph = (const float*)d_in[1];
    const float* bph = (const float*)d_in[2];
    const float* wa  = (const float*)d_in[3];
    const float* ba  = (const float*)d_in[4];
    const float* wm  = (const float*)d_in[5];
    const float* bm  = (const float*)d_in[6];
    const float* w2  = (const float*)d_in[7];
    const float* b2  = (const float*)d_in[8];
    float* out = (float*)d_out;

    float *phi, *Mb, *tb, *Hb, *Db, *Beb, *tmpb, *Rb, *ab, *xp, *bp, *p1, *p2;
    __nv_bfloat16 *xhi, *xlo, *whi, *wlo;
    cudaGetSymbolAddress((void**)&phi,  g_phi);
    cudaGetSymbolAddress((void**)&Mb,   g_M);
    cudaGetSymbolAddress((void**)&tb,   g_t);
    cudaGetSymbolAddress((void**)&Hb,   g_H);
    cudaGetSymbolAddress((void**)&Db,   g_D);
    cudaGetSymbolAddress((void**)&Beb,  g_Be);
    cudaGetSymbolAddress((void**)&tmpb, g_tmp);
    cudaGetSymbolAddress((void**)&Rb,   g_R);
    cudaGetSymbolAddress((void**)&ab,   g_a);
    cudaGetSymbolAddress((void**)&xp,   g_xpart);
    cudaGetSymbolAddress((void**)&bp,   g_bpart);
    cudaGetSymbolAddress((void**)&p1,   g_part1);
    cudaGetSymbolAddress((void**)&p2,   g_part2);
    cudaGetSymbolAddress((void**)&xhi,  g_xhi);
    cudaGetSymbolAddress((void**)&xlo,  g_xlo);
    cudaGetSymbolAddress((void**)&whi,  g_whi);
    cudaGetSymbolAddress((void**)&wlo,  g_wlo);

    // 0) bf16 hi/lo splits for the tensor-core conv
    {
        long nx = (long)BB*VV*CIN;
        k_split_x<<<(unsigned)((nx + 255)/256), 256>>>(x, xhi, xlo);
        long nw = 49L*EE*CIN;
        k_split_wt<<<(unsigned)((nw + 255)/256), 256>>>(wm, whi, wlo);
    }

    // 1) pooled mean + a vector
    k_xpart<<<dim3(BB, 32), 256>>>(x, xp);
    k_a<<<BB, 128>>>(xp, wa, ba, ab);

    // 2) phi = x @ w_phi + b_phi
    sgemm_nn_v2<<<dim3(FF/128, (BB*VV)/128, 1), 256>>>(
        x, wph, phi, BB*VV, FF, CIN, 0, 0, 0,
        nullptr, 0, nullptr, 0, bph, 0, nullptr, 0);

    // 3) M = conv7x7(x) + b_m   — HMMA bf16-split implicit GEMM
    {
        const int smem_bytes = 2 * STAGE_B;   // 147456
        cudaFuncSetAttribute(conv7_mma, cudaFuncAttributeMaxDynamicSharedMemorySize, smem_bytes);
        conv7_mma<<<dim3(EE/128, VV/128, BB), 256, smem_bytes>>>(xhi, xlo, whi, wlo, bm, Mb);
    }

    // 4) t = phi^T @ M  (split-K)
    sgemm_tn<<<dim3(EE/64, FF/64, BB*SPLITK), 256>>>(
        phi, Mb, p1, FF, EE, VV, FF,
        (long)VV*FF, (long)VV*EE, (long)FF*EE, nullptr, 0, SPLITK);
    k_reduce_split<<<(BB*FF*EE + 255)/256, 256>>>(p1, tb, FF*EE, BB, SPLITK);

    // 5) H = | phi @ (diag(a) t) |
    sgemm_nn_v2<<<dim3(EE/128, VV/128, BB), 256>>>(
        phi, tb, Hb, VV, EE, FF,
        (long)VV*FF, (long)FF*EE, (long)VV*EE,
        nullptr, 0, ab, FF, nullptr, 1, nullptr, 0);

    // 6) degrees
    k_degD<<<(BB*VV)/8, 256>>>(Hb, Db);
    k_bpart<<<dim3(BB, 16), 256>>>(Hb, bp);
    k_finishBe<<<BB, 256>>>(bp, Beb);

    // 7) tmp = (D^-1/2 H)^T @ x  (split-K)
    sgemm_tn<<<dim3(CIN/64, EE/64, BB*SPLITK), 256>>>(
        Hb, x, p2, EE, CIN, VV, EE,
        (long)VV*EE, (long)VV*CIN, (long)EE*CIN, Db, VV, SPLITK);
    k_reduce_split<<<(BB*EE*CIN + 255)/256, 256>>>(p2, tmpb, EE*CIN, BB, SPLITK);

    // 8) R = x - (D^-1/2 H) @ (diag(1/Be) tmp)
    sgemm_nn_v2<<<dim3(CIN/128, VV/128, BB), 256>>>(
        Hb, tmpb, Rb, VV, CIN, EE,
        (long)VV*EE, (long)EE*CIN, (long)VV*CIN,
        Db, VV, Beb, EE, nullptr, 2, x, (long)VV*CIN);

    // 9) out = R @ weight_2 + bias_2
    sgemm_nn_v2<<<dim3(COUT/128, (BB*VV)/128, 1), 256>>>(
        Rb, w2, out, BB*VV, COUT, CIN, 0, 0, 0,
        nullptr, 0, nullptr, 0, b2, 0, nullptr, 0);
}

// round 6
// speedup vs baseline: 2.6947x; 1.4345x over previous
#include <cuda_runtime.h>
#include <cuda_fp16.h>
#include <math.h>
#include <stdint.h>

// Problem dims (fixed by the dataset)
#define BB   8
#define HHH  64
#define WWW  64
#define VV   4096      // HHH*WWW
#define CIN  256
#define FF   128
#define EE   256
#define COUT 256
#define SPLITK 16

// ---------------- scratch (static device globals; no allocation allowed) ----
__device__ float g_phi [BB*VV*FF];
__device__ float g_M   [BB*VV*EE];
__device__ float g_t   [BB*FF*EE];
__device__ float g_H   [BB*VV*EE];
__device__ float g_D   [BB*VV];
__device__ float g_Be  [BB*EE];
__device__ float g_tmp [BB*EE*CIN];
__device__ float g_R   [BB*VV*CIN];
__device__ float g_a   [BB*FF];
__device__ float g_xpart[BB*32*CIN];
__device__ float g_bpart[BB*16*EE];
__device__ float g_part1[SPLITK*BB*FF*EE];
__device__ float g_part2[SPLITK*BB*EE*CIN];
__device__ __half g_xhi[BB*VV*CIN];
__device__ __half g_xlo[BB*VV*CIN];
__device__ __half g_wh [49*EE*CIN];   // transposed: [tap][e][c], single fp16

// ======================= PTX helpers (mma.sync / cp.async) ==================
__device__ __forceinline__ uint32_t smem_u32(const void* p) {
    uint32_t a;
    asm("{ .reg .u64 t; cvta.to.shared.u64 t, %1; cvt.u32.u64 %0, t; }" : "=r"(a) : "l"(p));
    return a;
}
#define CP_ASYNC16(dst, src, sz) \
    asm volatile("cp.async.cg.shared.global [%0], [%1], 16, %2;" \
                 :: "r"(dst), "l"(src), "r"(sz) : "memory")
#define CP_COMMIT() asm volatile("cp.async.commit_group;" ::: "memory")
#define CP_WAIT(n)  asm volatile("cp.async.wait_group %0;" :: "n"(n) : "memory")
#define LDSM4(r, addr) \
    asm volatile("ldmatrix.sync.aligned.m8n8.x4.shared.b16 {%0,%1,%2,%3}, [%4];" \
                 : "=r"((r)[0]), "=r"((r)[1]), "=r"((r)[2]), "=r"((r)[3]) : "r"(addr))
#define MMA16816H(d, a, b0, b1) \
    asm volatile("mma.sync.aligned.m16n8k16.row.col.f32.f16.f16.f32 " \
                 "{%0,%1,%2,%3}, {%4,%5,%6,%7}, {%8,%9}, {%0,%1,%2,%3};" \
                 : "+f"((d)[0]), "+f"((d)[1]), "+f"((d)[2]), "+f"((d)[3]) \
                 : "r"((a)[0]), "r"((a)[1]), "r"((a)[2]), "r"((a)[3]), \
                   "r"(b0), "r"(b1))

// ======================= fp16 split preprocessing ===========================
__global__ void k_split_x(const float* __restrict__ x,
                          __half* __restrict__ xhi, __half* __restrict__ xlo)
{
    long i = (long)blockIdx.x * 256 + threadIdx.x;
    if (i >= (long)BB*VV*CIN) return;
    float f = x[i];
    __half h = __float2half(f);
    xhi[i] = h;
    xlo[i] = __float2half(f - __half2float(h));
}

__global__ void k_split_wt(const float* __restrict__ wm, __half* __restrict__ wh)
{
    long i = (long)blockIdx.x * 256 + threadIdx.x;   // (tap, e, c)
    if (i >= 49L*EE*CIN) return;
    int tap = (int)(i / (EE*CIN));
    int r   = (int)(i % (EE*CIN));
    int e = r / CIN, c = r % CIN;
    wh[i] = __float2half(wm[((long)tap*CIN + c)*EE + e]);
}

// ======================= HMMA 7x7 conv ======================================
// Implicit GEMM: block tile 128(v) x 128(e), K = 49 taps x 256 ch, 64-ch chunks.
// fp16 2-product: out = (x_hi + x_lo) * w_fp16, fp32 accum. Error = x*(w - w_fp16)
// ~ 2^-12 rms, attenuated downstream.
#define ROWB   144                   // bytes per padded row (72 fp16)
#define TILE_B (128*ROWB)            // 18432 B, one 128x64 fp16 tile
#define OFF_AHI 0
#define OFF_ALO (TILE_B)
#define OFF_B   (2*TILE_B)
#define STAGE_B (3*TILE_B)           // 55296 B per stage
#define NCHUNK  196                  // 49 taps * 4 ch-chunks

__global__ __launch_bounds__(256, 2) void conv7_mma(
    const __half* __restrict__ xhi, const __half* __restrict__ xlo,
    const __half* __restrict__ wh,
    const float* __restrict__ bias, float* __restrict__ out)
{
    extern __shared__ __align__(128) char smem[];
    const uint32_t sbase = smem_u32(smem);
    const int tid = threadIdx.x;
    const int wid = tid >> 5, lane = tid & 31;
    const int e0 = blockIdx.x * 128, v0 = blockIdx.y * 128, b = blockIdx.z;
    const int warpm = wid >> 1, warpn = wid & 1;

    // producer coords: each thread owns (row, 32-ch half) of each 128x64 tile
    const int rowA = tid >> 1, half = (tid & 1) * 32;
    const int vh = (v0 + rowA) >> 6, vw = (v0 + rowA) & 63;
    const uint32_t dstRow = rowA * ROWB + half * 2;   // byte offset in tile

    auto issue = [&](int it) {
        const int tap = it >> 2, kc = (it & 3) * 64;
        const int dy = tap / 7 - 3, dx = tap % 7 - 3;
        const int hh = vh + dy, ww = vw + dx;
        const bool okA = ((unsigned)hh < 64u) && ((unsigned)ww < 64u);
        const uint32_t szA = okA ? 16u : 0u;
        const long aoff = okA ? ((long)b*VV + (hh<<6) + ww)*CIN + kc + half
                              : 0;                       // clamped when zfill
        const long boff = ((long)tap*EE + e0 + rowA)*CIN + kc + half;
        const uint32_t stg = sbase + (it & 1) * STAGE_B;
        #pragma unroll
        for (int j = 0; j < 4; j++) {
            CP_ASYNC16(stg + OFF_AHI + dstRow + j*16, xhi + aoff + j*8, szA);
            CP_ASYNC16(stg + OFF_ALO + dstRow + j*16, xlo + aoff + j*8, szA);
            CP_ASYNC16(stg + OFF_B   + dstRow + j*16, wh  + boff + j*8, 16u);
        }
        CP_COMMIT();
    };

    float acc[2][8][4];
    #pragma unroll
    for (int mt = 0; mt < 2; mt++)
        #pragma unroll
        for (int nt = 0; nt < 8; nt++)
            #pragma unroll
            for (int q = 0; q < 4; q++) acc[mt][nt][q] = 0.f;

    // per-lane ldmatrix byte offsets (within a tile)
    const uint32_t aLdOff = (warpm*32 + (lane & 15)) * ROWB + (lane >> 4) * 16;
    const uint32_t bLdOff = (warpn*64 + (lane & 7) + ((lane >> 4) & 1) * 8) * ROWB
                          + (((lane >> 3) & 1) * 8) * 2;

    issue(0);

    for (int it = 0; it < NCHUNK; it++) {
        if (it + 1 < NCHUNK) { issue(it + 1); CP_WAIT(1); }
        else                 { CP_WAIT(0); }
        __syncthreads();

        const uint32_t stg = sbase + (it & 1) * STAGE_B;
        #pragma unroll
        for (int k16 = 0; k16 < 4; k16++) {
            const uint32_t kByte = k16 * 32;   // 16 fp16
            uint32_t ah[2][4], al[2][4];
            #pragma unroll
            for (int mt = 0; mt < 2; mt++) {
                uint32_t o = aLdOff + mt * 16 * ROWB + kByte;
                LDSM4(ah[mt], stg + OFF_AHI + o);
                LDSM4(al[mt], stg + OFF_ALO + o);
            }
            #pragma unroll
            for (int np = 0; np < 4; np++) {
                uint32_t o = bLdOff + np * 16 * ROWB + kByte;
                uint32_t bb[4];
                LDSM4(bb, stg + OFF_B + o);
                #pragma unroll
                for (int mt = 0; mt < 2; mt++) {
                    MMA16816H(acc[mt][2*np],   ah[mt], bb[0], bb[1]);
                    MMA16816H(acc[mt][2*np+1], ah[mt], bb[2], bb[3]);
                    MMA16816H(acc[mt][2*np],   al[mt], bb[0], bb[1]);
                    MMA16816H(acc[mt][2*np+1], al[mt], bb[2], bb[3]);
                }
            }
        }
        __syncthreads();
    }

    // epilogue: +bias, store fp32
    const int r = lane >> 2, c2 = (lane & 3) * 2;
    #pragma unroll
    for (int mt = 0; mt < 2; mt++) {
        #pragma unroll
        for (int nt = 0; nt < 8; nt++) {
            const int v = v0 + warpm*32 + mt*16 + r;
            const int e = e0 + warpn*64 + nt*8 + c2;
            const float bx = bias[e], by = bias[e+1];
            float* p0 = out + ((long)b*VV + v)*EE + e;
            float* p1 = p0 + 8L*EE;
            *(float2*)p0 = make_float2(acc[mt][nt][0] + bx, acc[mt][nt][1] + by);
            *(float2*)p1 = make_float2(acc[mt][nt][2] + bx, acc[mt][nt][3] + by);
        }
    }
}

// ------------------------- FFMA2 helpers ------------------------------------
typedef unsigned long long ull;

__device__ __forceinline__ void ffma2(ull &d, ull a, ull b) {
    asm("fma.rn.f32x2 %0, %1, %2, %0;" : "+l"(d) : "l"(a), "l"(b));
}
__device__ __forceinline__ ull bcast2(float v) {
    ull r;
    asm("mov.b64 %0, {%1, %1};" : "=l"(r) : "f"(v));
    return r;
}
__device__ __forceinline__ float lof(ull v){ return __uint_as_float((unsigned)v); }
__device__ __forceinline__ float hif(ull v){ return __uint_as_float((unsigned)(v>>32)); }

#define INNER_16(As, Bs, acc, tx, ty)                                          \
    _Pragma("unroll")                                                          \
    for (int kk = 0; kk < 16; kk++) {                                          \
        ulonglong2 A0 = *(const ulonglong2*)&As[kk][ty*4];                     \
        ulonglong2 A1 = *(const ulonglong2*)&As[kk][64 + ty*4];                \
        float4 bv0 = *(const float4*)&Bs[kk][tx*4];                            \
        float4 bv1 = *(const float4*)&Bs[kk][64 + tx*4];                       \
        ull bb0 = bcast2(bv0.x), bb1 = bcast2(bv0.y);                          \
        ull bb2 = bcast2(bv0.z), bb3 = bcast2(bv0.w);                          \
        ull bb4 = bcast2(bv1.x), bb5 = bcast2(bv1.y);                          \
        ull bb6 = bcast2(bv1.z), bb7 = bcast2(bv1.w);                          \
        ffma2(acc[0][0], A0.x, bb0); ffma2(acc[0][1], A0.x, bb1);              \
        ffma2(acc[0][2], A0.x, bb2); ffma2(acc[0][3], A0.x, bb3);              \
        ffma2(acc[0][4], A0.x, bb4); ffma2(acc[0][5], A0.x, bb5);              \
        ffma2(acc[0][6], A0.x, bb6); ffma2(acc[0][7], A0.x, bb7);              \
        ffma2(acc[1][0], A0.y, bb0); ffma2(acc[1][1], A0.y, bb1);              \
        ffma2(acc[1][2], A0.y, bb2); ffma2(acc[1][3], A0.y, bb3);              \
        ffma2(acc[1][4], A0.y, bb4); ffma2(acc[1][5], A0.y, bb5);              \
        ffma2(acc[1][6], A0.y, bb6); ffma2(acc[1][7], A0.y, bb7);              \
        ffma2(acc[2][0], A1.x, bb0); ffma2(acc[2][1], A1.x, bb1);              \
        ffma2(acc[2][2], A1.x, bb2); ffma2(acc[2][3], A1.x, bb3);              \
        ffma2(acc[2][4], A1.x, bb4); ffma2(acc[2][5], A1.x, bb5);              \
        ffma2(acc[2][6], A1.x, bb6); ffma2(acc[2][7], A1.x, bb7);              \
        ffma2(acc[3][0], A1.y, bb0); ffma2(acc[3][1], A1.y, bb1);              \
        ffma2(acc[3][2], A1.y, bb2); ffma2(acc[3][3], A1.y, bb3);              \
        ffma2(acc[3][4], A1.y, bb4); ffma2(acc[3][5], A1.y, bb5);              \
        ffma2(acc[3][6], A1.y, bb6); ffma2(acc[3][7], A1.y, bb7);              \
    }

// ---------------------------------------------------------------------------
// 128x128x16 FFMA2 SGEMM (modes: 0 bias, 1 abs, 2 resid-minus)
// ---------------------------------------------------------------------------
__global__ __launch_bounds__(256) void sgemm_nn_v2(
    const float* __restrict__ A, const float* __restrict__ Bm, float* __restrict__ C,
    int M, int N, int K,
    long aB, long bB, long cB,
    const float* __restrict__ aRS, int aRSb,
    const float* __restrict__ bKS, int bKSb,
    const float* __restrict__ bias,
    int mode, const float* __restrict__ resid, long rB)
{
    __shared__ float As[16][132];
    __shared__ float Bs[16][132];

    const int b  = blockIdx.z;
    const float* Ab = A + (long)b * aB;
    const float* Bb = Bm + (long)b * bB;
    float* Cb = C + (long)b * cB;

    const int m0 = blockIdx.y * 128, n0 = blockIdx.x * 128;
    const int tid = threadIdx.x;
    const int tx = tid & 15, ty = tid >> 4;
    const int lr  = tid >> 1, lkh = (tid & 1) * 8;
    const int bk  = tid >> 4, bn  = (tid & 15) * 4;

    ull acc[4][8] = {};
    const int nk = K / 16;

    float4 ra0, ra1, rb0, rb1;
    {
        const float* ap = &Ab[(long)(m0 + lr) * K + lkh];
        ra0 = *(const float4*)ap; ra1 = *(const float4*)(ap + 4);
        if (aRS) {
            float s = aRS[b * aRSb + m0 + lr];
            ra0.x*=s; ra0.y*=s; ra0.z*=s; ra0.w*=s;
            ra1.x*=s; ra1.y*=s; ra1.z*=s; ra1.w*=s;
        }
        const float* bp = &Bb[(long)bk * N + n0];
        rb0 = *(const float4*)(bp + bn); rb1 = *(const float4*)(bp + 64 + bn);
        if (bKS) {
            float s = bKS[b * bKSb + bk];
            rb0.x*=s; rb0.y*=s; rb0.z*=s; rb0.w*=s;
            rb1.x*=s; rb1.y*=s; rb1.z*=s; rb1.w*=s;
        }
    }

    for (int c = 0; c < nk; c++) {
        __syncthreads();
        As[lkh+0][lr] = ra0.x; As[lkh+1][lr] = ra0.y;
        As[lkh+2][lr] = ra0.z; As[lkh+3][lr] = ra0.w;
        As[lkh+4][lr] = ra1.x; As[lkh+5][lr] = ra1.y;
        As[lkh+6][lr] = ra1.z; As[lkh+7][lr] = ra1.w;
        *(float4*)&Bs[bk][bn]      = rb0;
        *(float4*)&Bs[bk][64 + bn] = rb1;
        __syncthreads();

        if (c + 1 < nk) {
            int k0 = (c + 1) * 16;
            const float* ap = &Ab[(long)(m0 + lr) * K + k0 + lkh];
            ra0 = *(const float4*)ap; ra1 = *(const float4*)(ap + 4);
            if (aRS) {
                float s = aRS[b * aRSb + m0 + lr];
                ra0.x*=s; ra0.y*=s; ra0.z*=s; ra0.w*=s;
                ra1.x*=s; ra1.y*=s; ra1.z*=s; ra1.w*=s;
            }
            const float* bp = &Bb[(long)(k0 + bk) * N + n0];
            rb0 = *(const float4*)(bp + bn); rb1 = *(const float4*)(bp + 64 + bn);
            if (bKS) {
                float s = bKS[b * bKSb + k0 + bk];
                rb0.x*=s; rb0.y*=s; rb0.z*=s; rb0.w*=s;
                rb1.x*=s; rb1.y*=s; rb1.z*=s; rb1.w*=s;
            }
        }

        INNER_16(As, Bs, acc, tx, ty)
    }

    float4 biasA = make_float4(0.f,0.f,0.f,0.f), biasB = biasA;
    if (bias) {
        biasA = *(const float4*)&bias[n0 + tx*4];
        biasB = *(const float4*)&bias[n0 + 64 + tx*4];
    }

    #pragma unroll
    for (int p = 0; p < 4; p++) {
        int mbase = m0 + ((p < 2) ? 0 : 64) + ty*4 + (p & 1) * 2;
        #pragma unroll
        for (int h = 0; h < 2; h++) {
            long m = mbase + h;
            float4 c0, c1;
            if (h == 0) {
                c0 = make_float4(lof(acc[p][0]), lof(acc[p][1]), lof(acc[p][2]), lof(acc[p][3]));
                c1 = make_float4(lof(acc[p][4]), lof(acc[p][5]), lof(acc[p][6]), lof(acc[p][7]));
            } else {
                c0 = make_float4(hif(acc[p][0]), hif(acc[p][1]), hif(acc[p][2]), hif(acc[p][3]));
                c1 = make_float4(hif(acc[p][4]), hif(acc[p][5]), hif(acc[p][6]), hif(acc[p][7]));
            }
            c0.x += biasA.x; c0.y += biasA.y; c0.z += biasA.z; c0.w += biasA.w;
            c1.x += biasB.x; c1.y += biasB.y; c1.z += biasB.z; c1.w += biasB.w;
            long off0 = m * N + n0 + tx*4;
            long off1 = m * N + n0 + 64 + tx*4;
            if (mode == 1) {
                c0.x=fabsf(c0.x); c0.y=fabsf(c0.y); c0.z=fabsf(c0.z); c0.w=fabsf(c0.w);
                c1.x=fabsf(c1.x); c1.y=fabsf(c1.y); c1.z=fabsf(c1.z); c1.w=fabsf(c1.w);
            } else if (mode == 2) {
                float4 r0 = *(const float4*)&resid[(long)b * rB + off0];
                float4 r1 = *(const float4*)&resid[(long)b * rB + off1];
                c0.x = r0.x - c0.x; c0.y = r0.y - c0.y; c0.z = r0.z - c0.z; c0.w = r0.w - c0.w;
                c1.x = r1.x - c1.x; c1.y = r1.y - c1.y; c1.z = r1.z - c1.z; c1.w = r1.w - c1.w;
            }
            *(float4*)&Cb[off0] = c0;
            *(float4*)&Cb[off1] = c1;
        }
    }
}

// ---------------------------------------------------------------------------
// 128x128x16 FFMA2 transposed-A GEMM with split-K.
// A stored [Kd, lda] (k rows, m columns) — natural layout for As[k][m].
// blockIdx.z = b*split + s; each slice writes its own partial (deterministic).
// ---------------------------------------------------------------------------
__global__ __launch_bounds__(256) void sgemm_tn_v2(
    const float* __restrict__ A, const float* __restrict__ Bm, float* __restrict__ C,
    int M, int N, int Kd, int lda,
    long aB, long bB, long cB,
    const float* __restrict__ kS, int kSb,
    int split)
{
    __shared__ float As[16][132];
    __shared__ float Bs[16][132];

    const int zb = blockIdx.z;
    const int b = zb / split, s = zb % split;
    const int kchunk = Kd / split;
    const int kbeg = s * kchunk, kend = kbeg + kchunk;

    const float* Ab = A + (long)b * aB;
    const float* Bb = Bm + (long)b * bB;
    float* Cb = C + (long)zb * cB;

    const int m0 = blockIdx.y * 128, n0 = blockIdx.x * 128;
    const int tid = threadIdx.x, tx = tid & 15, ty = tid >> 4;
    const int lk = tid >> 4, lm = (tid & 15) * 8;

    ull acc[4][8] = {};

    for (int k0 = kbeg; k0 < kend; k0 += 16) {
        const float* ap = &Ab[(long)(k0 + lk) * lda + m0 + lm];
        float4 a0 = *(const float4*)ap;
        float4 a1 = *(const float4*)(ap + 4);
        if (kS) {
            float sc = kS[b * kSb + k0 + lk];
            a0.x*=sc; a0.y*=sc; a0.z*=sc; a0.w*=sc;
            a1.x*=sc; a1.y*=sc; a1.z*=sc; a1.w*=sc;
        }
        const float* bp = &Bb[(long)(k0 + lk) * N + n0 + lm];
        float4 b0 = *(const float4*)bp;
        float4 b1 = *(const float4*)(bp + 4);

        __syncthreads();
        *(float4*)&As[lk][lm]     = a0;
        *(float4*)&As[lk][lm + 4] = a1;
        *(float4*)&Bs[lk][lm]     = b0;
        *(float4*)&Bs[lk][lm + 4] = b1;
        __syncthreads();

        INNER_16(As, Bs, acc, tx, ty)
    }

    #pragma unroll
    for (int p = 0; p < 4; p++) {
        int mbase = m0 + ((p < 2) ? 0 : 64) + ty*4 + (p & 1) * 2;
        #pragma unroll
        for (int h = 0; h < 2; h++) {
            long m = mbase + h;
            float4 c0, c1;
            if (h == 0) {
                c0 = make_float4(lof(acc[p][0]), lof(acc[p][1]), lof(acc[p][2]), lof(acc[p][3]));
                c1 = make_float4(lof(acc[p][4]), lof(acc[p][5]), lof(acc[p][6]), lof(acc[p][7]));
            } else {
                c0 = make_float4(hif(acc[p][0]), hif(acc[p][1]), hif(acc[p][2]), hif(acc[p][3]));
                c1 = make_float4(hif(acc[p][4]), hif(acc[p][5]), hif(acc[p][6]), hif(acc[p][7]));
            }
            *(float4*)&Cb[m * N + n0 + tx*4]      = c0;
            *(float4*)&Cb[m * N + n0 + 64 + tx*4] = c1;
        }
    }
}

__global__ void k_reduce_split(const float* __restrict__ part, float* __restrict__ out,
                               int mn, int batches, int split)
{
    long i = (long)blockIdx.x * 256 + threadIdx.x;
    if (i >= (long)batches * mn) return;
    int b = (int)(i / mn), r = (int)(i % mn);
    float sum = 0.f;
    for (int s = 0; s < split; s++)
        sum += part[((long)(b * split + s)) * mn + r];
    out[i] = sum;
}

// -------------------- small reduction / pointwise kernels -------------------
__global__ void k_xpart(const float* __restrict__ x, float* __restrict__ P)
{
    const int b = blockIdx.x, p = blockIdx.y, c = threadIdx.x;
    const float* base = x + ((long)b * VV + p * 128) * CIN + c;
    float s = 0.f;
    for (int v = 0; v < 128; v++) s += base[(long)v * CIN];
    P[(b * 32 + p) * CIN + c] = s;
}

__global__ void k_a(const float* __restrict__ P, const float* __restrict__ wa,
                    const float* __restrict__ ba, float* __restrict__ a)
{
    __shared__ float xm[CIN];
    const int b = blockIdx.x, f = threadIdx.x;
    for (int c = f; c < CIN; c += 128) {
        float s = 0.f;
        for (int p = 0; p < 32; p++) s += P[(b * 32 + p) * CIN + c];
        xm[c] = s * (1.0f / VV);
    }
    __syncthreads();
    float s = ba[f];
    for (int c = 0; c < CIN; c++) s += xm[c] * wa[c * FF + f];
    a[b * FF + f] = s;
}

__global__ void k_degD(const float* __restrict__ H, float* __restrict__ D)
{
    const int row  = blockIdx.x * 8 + (threadIdx.x >> 5);
    const int lane = threadIdx.x & 31;
    if (row >= BB * VV) return;
    const float* r = H + (long)row * EE;
    float s = 0.f;
    for (int c = lane; c < EE; c += 32) s += r[c];
    for (int o = 16; o; o >>= 1) s += __shfl_xor_sync(0xFFFFFFFFu, s, o);
    if (lane == 0) D[row] = rsqrtf(s);
}

__global__ void k_bpart(const float* __restrict__ H, float* __restrict__ P)
{
    const int b = blockIdx.x, p = blockIdx.y, e = threadIdx.x;
    const float* base = H + ((long)b * VV + p * 256) * EE + e;
    float s = 0.f;
    for (int v = 0; v < 256; v++) s += base[(long)v * EE];
    P[(b * 16 + p) * EE + e] = s;
}

__global__ void k_finishBe(const float* __restrict__ P, float* __restrict__ Be)
{
    const int b = blockIdx.x, e = threadIdx.x;
    float s = 0.f;
    for (int p = 0; p < 16; p++) s += P[(b * 16 + p) * EE + e];
    Be[b * EE + e] = 1.0f / s;
}

// ---------------------------------------------------------------------------
extern "C" void kernel_launch(void* const* d_in, const int* in_sizes, int n_in,
                              void* d_out, int out_size)
{
    const float* x   = (const float*)d_in[0];
    const float* wph = (const float*)d_in[1];
    const float* bph = (const float*)d_in[2];
    const float* wa  = (const float*)d_in[3];
    const float* ba  = (const float*)d_in[4];
    const float* wm  = (const float*)d_in[5];
    const float* bm  = (const float*)d_in[6];
    const float* w2  = (const float*)d_in[7];
    const float* b2  = (const float*)d_in[8];
    float* out = (float*)d_out;

    float *phi, *Mb, *tb, *Hb, *Db, *Beb, *tmpb, *Rb, *ab, *xp, *bp, *p1, *p2;
    __half *xhi, *xlo, *wh;
    cudaGetSymbolAddress((void**)&phi,  g_phi);
    cudaGetSymbolAddress((void**)&Mb,   g_M);
    cudaGetSymbolAddress((void**)&tb,   g_t);
    cudaGetSymbolAddress((void**)&Hb,   g_H);
    cudaGetSymbolAddress((void**)&Db,   g_D);
    cudaGetSymbolAddress((void**)&Beb,  g_Be);
    cudaGetSymbolAddress((void**)&tmpb, g_tmp);
    cudaGetSymbolAddress((void**)&Rb,   g_R);
    cudaGetSymbolAddress((void**)&ab,   g_a);
    cudaGetSymbolAddress((void**)&xp,   g_xpart);
    cudaGetSymbolAddress((void**)&bp,   g_bpart);
    cudaGetSymbolAddress((void**)&p1,   g_part1);
    cudaGetSymbolAddress((void**)&p2,   g_part2);
    cudaGetSymbolAddress((void**)&xhi,  g_xhi);
    cudaGetSymbolAddress((void**)&xlo,  g_xlo);
    cudaGetSymbolAddress((void**)&wh,   g_wh);

    // 0) fp16 splits for the tensor-core conv
    {
        long nx = (long)BB*VV*CIN;
        k_split_x<<<(unsigned)((nx + 255)/256), 256>>>(x, xhi, xlo);
        long nw = 49L*EE*CIN;
        k_split_wt<<<(unsigned)((nw + 255)/256), 256>>>(wm, wh);
    }

    // 1) pooled mean + a vector
    k_xpart<<<dim3(BB, 32), 256>>>(x, xp);
    k_a<<<BB, 128>>>(xp, wa, ba, ab);

    // 2) phi = x @ w_phi + b_phi
    sgemm_nn_v2<<<dim3(FF/128, (BB*VV)/128, 1), 256>>>(
        x, wph, phi, BB*VV, FF, CIN, 0, 0, 0,
        nullptr, 0, nullptr, 0, bph, 0, nullptr, 0);

    // 3) M = conv7x7(x) + b_m   — HMMA fp16 2-product implicit GEMM
    {
        const int smem_bytes = 2 * STAGE_B;   // 110592
        cudaFuncSetAttribute(conv7_mma, cudaFuncAttributeMaxDynamicSharedMemorySize, smem_bytes);
        conv7_mma<<<dim3(EE/128, VV/128, BB), 256, smem_bytes>>>(xhi, xlo, wh, bm, Mb);
    }

    // 4) t = phi^T @ M  (split-K, FFMA2)
    sgemm_tn_v2<<<dim3(EE/128, FF/128, BB*SPLITK), 256>>>(
        phi, Mb, p1, FF, EE, VV, FF,
        (long)VV*FF, (long)VV*EE, (long)FF*EE, nullptr, 0, SPLITK);
    k_reduce_split<<<(BB*FF*EE + 255)/256, 256>>>(p1, tb, FF*EE, BB, SPLITK);

    // 5) H = | phi @ (diag(a) t) |
    sgemm_nn_v2<<<dim3(EE/128, VV/128, BB), 256>>>(
        phi, tb, Hb, VV, EE, FF,
        (long)VV*FF, (long)FF*EE, (long)VV*EE,
        nullptr, 0, ab, FF, nullptr, 1, nullptr, 0);

    // 6) degrees
    k_degD<<<(BB*VV)/8, 256>>>(Hb, Db);
    k_bpart<<<dim3(BB, 16), 256>>>(Hb, bp);
    k_finishBe<<<BB, 256>>>(bp, Beb);

    // 7) tmp = (D^-1/2 H)^T @ x  (split-K, FFMA2; D^-1/2 as k-scale)
    sgemm_tn_v2<<<dim3(CIN/128, EE/128, BB*SPLITK), 256>>>(
        Hb, x, p2, EE, CIN, VV, EE,
        (long)VV*EE, (long)VV*CIN, (long)EE*CIN, Db, VV, SPLITK);
    k_reduce_split<<<(BB*EE*CIN + 255)/256, 256>>>(p2, tmpb, EE*CIN, BB, SPLITK);

    // 8) R = x - (D^-1/2 H) @ (diag(1/Be) tmp)
    sgemm_nn_v2<<<dim3(CIN/128, VV/128, BB), 256>>>(
        Hb, tmpb, Rb, VV, CIN, EE,
        (long)VV*EE, (long)EE*CIN, (long)VV*CIN,
        Db, VV, Beb, EE, nullptr, 2, x, (long)VV*CIN);

    // 9) out = R @ weight_2 + bias_2
    sgemm_nn_v2<<<dim3(COUT/128, (BB*VV)/128, 1), 256>>>(
        Rb, w2, out, BB*VV, COUT, CIN, 0, 0, 0,
        nullptr, 0, nullptr, 0, b2, 0, nullptr, 0);
}

// round 7
// speedup vs baseline: 3.8518x; 1.4294x over previous
#include <cuda_runtime.h>
#include <cuda_fp16.h>
#include <math.h>
#include <stdint.h>

// Problem dims (fixed by the dataset)
#define BB   8
#define HHH  64
#define WWW  64
#define VV   4096      // HHH*WWW
#define CIN  256
#define FF   128
#define EE   256
#define COUT 256
#define SPLITK 16

// ---------------- scratch (static device globals; no allocation allowed) ----
__device__ float g_phi [BB*VV*FF];
__device__ float g_M   [BB*VV*EE];
__device__ float g_t   [BB*FF*EE];
__device__ float g_H   [BB*VV*EE];
__device__ float g_D   [BB*VV];
__device__ float g_Be  [BB*EE];
__device__ float g_tmp [BB*EE*CIN];
__device__ float g_R   [BB*VV*CIN];
__device__ float g_a   [BB*FF];
__device__ float g_xpart[BB*32*CIN];
__device__ float g_bpart[BB*16*EE];
__device__ float g_part1[SPLITK*BB*FF*EE];
__device__ float g_part2[SPLITK*BB*EE*CIN];
__device__ __half g_xh[BB*VV*CIN];
__device__ __half g_wh[49*EE*CIN];   // transposed: [tap][e][c], fp16

// ======================= PTX helpers (mma.sync / cp.async) ==================
__device__ __forceinline__ uint32_t smem_u32(const void* p) {
    uint32_t a;
    asm("{ .reg .u64 t; cvta.to.shared.u64 t, %1; cvt.u32.u64 %0, t; }" : "=r"(a) : "l"(p));
    return a;
}
#define CP_ASYNC16(dst, src, sz) \
    asm volatile("cp.async.cg.shared.global [%0], [%1], 16, %2;" \
                 :: "r"(dst), "l"(src), "r"(sz) : "memory")
#define CP_COMMIT() asm volatile("cp.async.commit_group;" ::: "memory")
#define CP_WAIT(n)  asm volatile("cp.async.wait_group %0;" :: "n"(n) : "memory")
#define LDSM4(r, addr) \
    asm volatile("ldmatrix.sync.aligned.m8n8.x4.shared.b16 {%0,%1,%2,%3}, [%4];" \
                 : "=r"((r)[0]), "=r"((r)[1]), "=r"((r)[2]), "=r"((r)[3]) : "r"(addr))
#define MMA16816H(d, a, b0, b1) \
    asm volatile("mma.sync.aligned.m16n8k16.row.col.f32.f16.f16.f32 " \
                 "{%0,%1,%2,%3}, {%4,%5,%6,%7}, {%8,%9}, {%0,%1,%2,%3};" \
                 : "+f"((d)[0]), "+f"((d)[1]), "+f"((d)[2]), "+f"((d)[3]) \
                 : "r"((a)[0]), "r"((a)[1]), "r"((a)[2]), "r"((a)[3]), \
                   "r"(b0), "r"(b1))

// ======================= fp16 preprocessing =================================
__global__ void k_cvt_x(const float* __restrict__ x, __half* __restrict__ xh)
{
    long i = (long)blockIdx.x * 256 + threadIdx.x;
    if (i >= (long)BB*VV*CIN) return;
    xh[i] = __float2half(x[i]);
}

__global__ void k_cvt_wt(const float* __restrict__ wm, __half* __restrict__ wh)
{
    long i = (long)blockIdx.x * 256 + threadIdx.x;   // (tap, e, c)
    if (i >= 49L*EE*CIN) return;
    int tap = (int)(i / (EE*CIN));
    int r   = (int)(i % (EE*CIN));
    int e = r / CIN, c = r % CIN;
    wh[i] = __float2half(wm[((long)tap*CIN + c)*EE + e]);
}

// ======================= HMMA 7x7 conv ======================================
// Implicit GEMM: block tile 128(v) x 128(e), K = 49 taps x 256 ch, 64-ch chunks.
// Single fp16 product: M = fp16(x) * fp16(w), fp32 accum. Quantization error
// ~3.5e-4 rms in M, attenuated ~300x downstream (measured R5/R6).
#define ROWB   144                   // bytes per padded row (72 fp16)
#define TILE_B (128*ROWB)            // 18432 B, one 128x64 fp16 tile
#define OFF_A  0
#define OFF_B  (TILE_B)
#define STAGE_B (2*TILE_B)           // 36864 B per stage
#define NCHUNK  196                  // 49 taps * 4 ch-chunks

__global__ __launch_bounds__(256, 2) void conv7_mma(
    const __half* __restrict__ xh, const __half* __restrict__ wh,
    const float* __restrict__ bias, float* __restrict__ out)
{
    extern __shared__ __align__(128) char smem[];
    const uint32_t sbase = smem_u32(smem);
    const int tid = threadIdx.x;
    const int wid = tid >> 5, lane = tid & 31;
    const int e0 = blockIdx.x * 128, v0 = blockIdx.y * 128, b = blockIdx.z;
    const int warpm = wid >> 1, warpn = wid & 1;

    // producer coords: each thread owns (row, 32-ch half) of each 128x64 tile
    const int rowA = tid >> 1, half = (tid & 1) * 32;
    const int vh = (v0 + rowA) >> 6, vw = (v0 + rowA) & 63;
    const uint32_t dstRow = rowA * ROWB + half * 2;   // byte offset in tile

    auto issue = [&](int it) {
        const int tap = it >> 2, kc = (it & 3) * 64;
        const int dy = tap / 7 - 3, dx = tap % 7 - 3;
        const int hh = vh + dy, ww = vw + dx;
        const bool okA = ((unsigned)hh < 64u) && ((unsigned)ww < 64u);
        const uint32_t szA = okA ? 16u : 0u;
        const long aoff = okA ? ((long)b*VV + (hh<<6) + ww)*CIN + kc + half
                              : 0;                       // clamped when zfill
        const long boff = ((long)tap*EE + e0 + rowA)*CIN + kc + half;
        const uint32_t stg = sbase + (it & 1) * STAGE_B;
        #pragma unroll
        for (int j = 0; j < 4; j++) {
            CP_ASYNC16(stg + OFF_A + dstRow + j*16, xh + aoff + j*8, szA);
            CP_ASYNC16(stg + OFF_B + dstRow + j*16, wh + boff + j*8, 16u);
        }
        CP_COMMIT();
    };

    float acc[2][8][4];
    #pragma unroll
    for (int mt = 0; mt < 2; mt++)
        #pragma unroll
        for (int nt = 0; nt < 8; nt++)
            #pragma unroll
            for (int q = 0; q < 4; q++) acc[mt][nt][q] = 0.f;

    // per-lane ldmatrix byte offsets (within a tile)
    const uint32_t aLdOff = (warpm*32 + (lane & 15)) * ROWB + (lane >> 4) * 16;
    const uint32_t bLdOff = (warpn*64 + (lane & 7) + ((lane >> 4) & 1) * 8) * ROWB
                          + (((lane >> 3) & 1) * 8) * 2;

    issue(0);

    for (int it = 0; it < NCHUNK; it++) {
        if (it + 1 < NCHUNK) { issue(it + 1); CP_WAIT(1); }
        else                 { CP_WAIT(0); }
        __syncthreads();

        const uint32_t stg = sbase + (it & 1) * STAGE_B;
        #pragma unroll
        for (int k16 = 0; k16 < 4; k16++) {
            const uint32_t kByte = k16 * 32;   // 16 fp16
            uint32_t ah[2][4];
            #pragma unroll
            for (int mt = 0; mt < 2; mt++) {
                LDSM4(ah[mt], stg + OFF_A + aLdOff + mt * 16 * ROWB + kByte);
            }
            #pragma unroll
            for (int np = 0; np < 4; np++) {
                uint32_t bb[4];
                LDSM4(bb, stg + OFF_B + bLdOff + np * 16 * ROWB + kByte);
                #pragma unroll
                for (int mt = 0; mt < 2; mt++) {
                    MMA16816H(acc[mt][2*np],   ah[mt], bb[0], bb[1]);
                    MMA16816H(acc[mt][2*np+1], ah[mt], bb[2], bb[3]);
                }
            }
        }
        __syncthreads();
    }

    // epilogue: +bias, store fp32
    const int r = lane >> 2, c2 = (lane & 3) * 2;
    #pragma unroll
    for (int mt = 0; mt < 2; mt++) {
        #pragma unroll
        for (int nt = 0; nt < 8; nt++) {
            const int v = v0 + warpm*32 + mt*16 + r;
            const int e = e0 + warpn*64 + nt*8 + c2;
            const float bx = bias[e], by = bias[e+1];
            float* p0 = out + ((long)b*VV + v)*EE + e;
            float* p1 = p0 + 8L*EE;
            *(float2*)p0 = make_float2(acc[mt][nt][0] + bx, acc[mt][nt][1] + by);
            *(float2*)p1 = make_float2(acc[mt][nt][2] + bx, acc[mt][nt][3] + by);
        }
    }
}

// ------------------------- FFMA2 helpers ------------------------------------
typedef unsigned long long ull;

__device__ __forceinline__ void ffma2(ull &d, ull a, ull b) {
    asm("fma.rn.f32x2 %0, %1, %2, %0;" : "+l"(d) : "l"(a), "l"(b));
}
__device__ __forceinline__ ull bcast2(float v) {
    ull r;
    asm("mov.b64 %0, {%1, %1};" : "=l"(r) : "f"(v));
    return r;
}
__device__ __forceinline__ float lof(ull v){ return __uint_as_float((unsigned)v); }
__device__ __forceinline__ float hif(ull v){ return __uint_as_float((unsigned)(v>>32)); }

#define INNER_16(As, Bs, acc, tx, ty)                                          \
    _Pragma("unroll")                                                          \
    for (int kk = 0; kk < 16; kk++) {                                          \
        ulonglong2 A0 = *(const ulonglong2*)&As[kk][ty*4];                     \
        ulonglong2 A1 = *(const ulonglong2*)&As[kk][64 + ty*4];                \
        float4 bv0 = *(const float4*)&Bs[kk][tx*4];                            \
        float4 bv1 = *(const float4*)&Bs[kk][64 + tx*4];                       \
        ull bb0 = bcast2(bv0.x), bb1 = bcast2(bv0.y);                          \
        ull bb2 = bcast2(bv0.z), bb3 = bcast2(bv0.w);                          \
        ull bb4 = bcast2(bv1.x), bb5 = bcast2(bv1.y);                          \
        ull bb6 = bcast2(bv1.z), bb7 = bcast2(bv1.w);                          \
        ffma2(acc[0][0], A0.x, bb0); ffma2(acc[0][1], A0.x, bb1);              \
        ffma2(acc[0][2], A0.x, bb2); ffma2(acc[0][3], A0.x, bb3);              \
        ffma2(acc[0][4], A0.x, bb4); ffma2(acc[0][5], A0.x, bb5);              \
        ffma2(acc[0][6], A0.x, bb6); ffma2(acc[0][7], A0.x, bb7);              \
        ffma2(acc[1][0], A0.y, bb0); ffma2(acc[1][1], A0.y, bb1);              \
        ffma2(acc[1][2], A0.y, bb2); ffma2(acc[1][3], A0.y, bb3);              \
        ffma2(acc[1][4], A0.y, bb4); ffma2(acc[1][5], A0.y, bb5);              \
        ffma2(acc[1][6], A0.y, bb6); ffma2(acc[1][7], A0.y, bb7);              \
        ffma2(acc[2][0], A1.x, bb0); ffma2(acc[2][1], A1.x, bb1);              \
        ffma2(acc[2][2], A1.x, bb2); ffma2(acc[2][3], A1.x, bb3);              \
        ffma2(acc[2][4], A1.x, bb4); ffma2(acc[2][5], A1.x, bb5);              \
        ffma2(acc[2][6], A1.x, bb6); ffma2(acc[2][7], A1.x, bb7);              \
        ffma2(acc[3][0], A1.y, bb0); ffma2(acc[3][1], A1.y, bb1);              \
        ffma2(acc[3][2], A1.y, bb2); ffma2(acc[3][3], A1.y, bb3);              \
        ffma2(acc[3][4], A1.y, bb4); ffma2(acc[3][5], A1.y, bb5);              \
        ffma2(acc[3][6], A1.y, bb6); ffma2(acc[3][7], A1.y, bb7);              \
    }

// ---------------------------------------------------------------------------
// 128x128x16 FFMA2 SGEMM (modes: 0 bias, 1 abs, 2 resid-minus)
// ---------------------------------------------------------------------------
__global__ __launch_bounds__(256) void sgemm_nn_v2(
    const float* __restrict__ A, const float* __restrict__ Bm, float* __restrict__ C,
    int M, int N, int K,
    long aB, long bB, long cB,
    const float* __restrict__ aRS, int aRSb,
    const float* __restrict__ bKS, int bKSb,
    const float* __restrict__ bias,
    int mode, const float* __restrict__ resid, long rB)
{
    __shared__ float As[16][132];
    __shared__ float Bs[16][132];

    const int b  = blockIdx.z;
    const float* Ab = A + (long)b * aB;
    const float* Bb = Bm + (long)b * bB;
    float* Cb = C + (long)b * cB;

    const int m0 = blockIdx.y * 128, n0 = blockIdx.x * 128;
    const int tid = threadIdx.x;
    const int tx = tid & 15, ty = tid >> 4;
    const int lr  = tid >> 1, lkh = (tid & 1) * 8;
    const int bk  = tid >> 4, bn  = (tid & 15) * 4;

    ull acc[4][8] = {};
    const int nk = K / 16;

    float4 ra0, ra1, rb0, rb1;
    {
        const float* ap = &Ab[(long)(m0 + lr) * K + lkh];
        ra0 = *(const float4*)ap; ra1 = *(const float4*)(ap + 4);
        if (aRS) {
            float s = aRS[b * aRSb + m0 + lr];
            ra0.x*=s; ra0.y*=s; ra0.z*=s; ra0.w*=s;
            ra1.x*=s; ra1.y*=s; ra1.z*=s; ra1.w*=s;
        }
        const float* bp = &Bb[(long)bk * N + n0];
        rb0 = *(const float4*)(bp + bn); rb1 = *(const float4*)(bp + 64 + bn);
        if (bKS) {
            float s = bKS[b * bKSb + bk];
            rb0.x*=s; rb0.y*=s; rb0.z*=s; rb0.w*=s;
            rb1.x*=s; rb1.y*=s; rb1.z*=s; rb1.w*=s;
        }
    }

    for (int c = 0; c < nk; c++) {
        __syncthreads();
        As[lkh+0][lr] = ra0.x; As[lkh+1][lr] = ra0.y;
        As[lkh+2][lr] = ra0.z; As[lkh+3][lr] = ra0.w;
        As[lkh+4][lr] = ra1.x; As[lkh+5][lr] = ra1.y;
        As[lkh+6][lr] = ra1.z; As[lkh+7][lr] = ra1.w;
        *(float4*)&Bs[bk][bn]      = rb0;
        *(float4*)&Bs[bk][64 + bn] = rb1;
        __syncthreads();

        if (c + 1 < nk) {
            int k0 = (c + 1) * 16;
            const float* ap = &Ab[(long)(m0 + lr) * K + k0 + lkh];
            ra0 = *(const float4*)ap; ra1 = *(const float4*)(ap + 4);
            if (aRS) {
                float s = aRS[b * aRSb + m0 + lr];
                ra0.x*=s; ra0.y*=s; ra0.z*=s; ra0.w*=s;
                ra1.x*=s; ra1.y*=s; ra1.z*=s; ra1.w*=s;
            }
            const float* bp = &Bb[(long)(k0 + bk) * N + n0];
            rb0 = *(const float4*)(bp + bn); rb1 = *(const float4*)(bp + 64 + bn);
            if (bKS) {
                float s = bKS[b * bKSb + k0 + bk];
                rb0.x*=s; rb0.y*=s; rb0.z*=s; rb0.w*=s;
                rb1.x*=s; rb1.y*=s; rb1.z*=s; rb1.w*=s;
            }
        }

        INNER_16(As, Bs, acc, tx, ty)
    }

    float4 biasA = make_float4(0.f,0.f,0.f,0.f), biasB = biasA;
    if (bias) {
        biasA = *(const float4*)&bias[n0 + tx*4];
        biasB = *(const float4*)&bias[n0 + 64 + tx*4];
    }

    #pragma unroll
    for (int p = 0; p < 4; p++) {
        int mbase = m0 + ((p < 2) ? 0 : 64) + ty*4 + (p & 1) * 2;
        #pragma unroll
        for (int h = 0; h < 2; h++) {
            long m = mbase + h;
            float4 c0, c1;
            if (h == 0) {
                c0 = make_float4(lof(acc[p][0]), lof(acc[p][1]), lof(acc[p][2]), lof(acc[p][3]));
                c1 = make_float4(lof(acc[p][4]), lof(acc[p][5]), lof(acc[p][6]), lof(acc[p][7]));
            } else {
                c0 = make_float4(hif(acc[p][0]), hif(acc[p][1]), hif(acc[p][2]), hif(acc[p][3]));
                c1 = make_float4(hif(acc[p][4]), hif(acc[p][5]), hif(acc[p][6]), hif(acc[p][7]));
            }
            c0.x += biasA.x; c0.y += biasA.y; c0.z += biasA.z; c0.w += biasA.w;
            c1.x += biasB.x; c1.y += biasB.y; c1.z += biasB.z; c1.w += biasB.w;
            long off0 = m * N + n0 + tx*4;
            long off1 = m * N + n0 + 64 + tx*4;
            if (mode == 1) {
                c0.x=fabsf(c0.x); c0.y=fabsf(c0.y); c0.z=fabsf(c0.z); c0.w=fabsf(c0.w);
                c1.x=fabsf(c1.x); c1.y=fabsf(c1.y); c1.z=fabsf(c1.z); c1.w=fabsf(c1.w);
            } else if (mode == 2) {
                float4 r0 = *(const float4*)&resid[(long)b * rB + off0];
                float4 r1 = *(const float4*)&resid[(long)b * rB + off1];
                c0.x = r0.x - c0.x; c0.y = r0.y - c0.y; c0.z = r0.z - c0.z; c0.w = r0.w - c0.w;
                c1.x = r1.x - c1.x; c1.y = r1.y - c1.y; c1.z = r1.z - c1.z; c1.w = r1.w - c1.w;
            }
            *(float4*)&Cb[off0] = c0;
            *(float4*)&Cb[off1] = c1;
        }
    }
}

// ---------------------------------------------------------------------------
// 128x128x16 FFMA2 transposed-A GEMM with split-K.
// ---------------------------------------------------------------------------
__global__ __launch_bounds__(256) void sgemm_tn_v2(
    const float* __restrict__ A, const float* __restrict__ Bm, float* __restrict__ C,
    int M, int N, int Kd, int lda,
    long aB, long bB, long cB,
    const float* __restrict__ kS, int kSb,
    int split)
{
    __shared__ float As[16][132];
    __shared__ float Bs[16][132];

    const int zb = blockIdx.z;
    const int b = zb / split, s = zb % split;
    const int kchunk = Kd / split;
    const int kbeg = s * kchunk, kend = kbeg + kchunk;

    const float* Ab = A + (long)b * aB;
    const float* Bb = Bm + (long)b * bB;
    float* Cb = C + (long)zb * cB;

    const int m0 = blockIdx.y * 128, n0 = blockIdx.x * 128;
    const int tid = threadIdx.x, tx = tid & 15, ty = tid >> 4;
    const int lk = tid >> 4, lm = (tid & 15) * 8;

    ull acc[4][8] = {};

    for (int k0 = kbeg; k0 < kend; k0 += 16) {
        const float* ap = &Ab[(long)(k0 + lk) * lda + m0 + lm];
        float4 a0 = *(const float4*)ap;
        float4 a1 = *(const float4*)(ap + 4);
        if (kS) {
            float sc = kS[b * kSb + k0 + lk];
            a0.x*=sc; a0.y*=sc; a0.z*=sc; a0.w*=sc;
            a1.x*=sc; a1.y*=sc; a1.z*=sc; a1.w*=sc;
        }
        const float* bp = &Bb[(long)(k0 + lk) * N + n0 + lm];
        float4 b0 = *(const float4*)bp;
        float4 b1 = *(const float4*)(bp + 4);

        __syncthreads();
        *(float4*)&As[lk][lm]     = a0;
        *(float4*)&As[lk][lm + 4] = a1;
        *(float4*)&Bs[lk][lm]     = b0;
        *(float4*)&Bs[lk][lm + 4] = b1;
        __syncthreads();

        INNER_16(As, Bs, acc, tx, ty)
    }

    #pragma unroll
    for (int p = 0; p < 4; p++) {
        int mbase = m0 + ((p < 2) ? 0 : 64) + ty*4 + (p & 1) * 2;
        #pragma unroll
        for (int h = 0; h < 2; h++) {
            long m = mbase + h;
            float4 c0, c1;
            if (h == 0) {
                c0 = make_float4(lof(acc[p][0]), lof(acc[p][1]), lof(acc[p][2]), lof(acc[p][3]));
                c1 = make_float4(lof(acc[p][4]), lof(acc[p][5]), lof(acc[p][6]), lof(acc[p][7]));
            } else {
                c0 = make_float4(hif(acc[p][0]), hif(acc[p][1]), hif(acc[p][2]), hif(acc[p][3]));
                c1 = make_float4(hif(acc[p][4]), hif(acc[p][5]), hif(acc[p][6]), hif(acc[p][7]));
            }
            *(float4*)&Cb[m * N + n0 + tx*4]      = c0;
            *(float4*)&Cb[m * N + n0 + 64 + tx*4] = c1;
        }
    }
}

__global__ void k_reduce_split(const float* __restrict__ part, float* __restrict__ out,
                               int mn, int batches, int split)
{
    long i = (long)blockIdx.x * 256 + threadIdx.x;
    if (i >= (long)batches * mn) return;
    int b = (int)(i / mn), r = (int)(i % mn);
    float sum = 0.f;
    for (int s = 0; s < split; s++)
        sum += part[((long)(b * split + s)) * mn + r];
    out[i] = sum;
}

// -------------------- small reduction / pointwise kernels -------------------
__global__ void k_xpart(const float* __restrict__ x, float* __restrict__ P)
{
    const int b = blockIdx.x, p = blockIdx.y, c = threadIdx.x;
    const float* base = x + ((long)b * VV + p * 128) * CIN + c;
    float s = 0.f;
    for (int v = 0; v < 128; v++) s += base[(long)v * CIN];
    P[(b * 32 + p) * CIN + c] = s;
}

__global__ void k_a(const float* __restrict__ P, const float* __restrict__ wa,
                    const float* __restrict__ ba, float* __restrict__ a)
{
    __shared__ float xm[CIN];
    const int b = blockIdx.x, f = threadIdx.x;
    for (int c = f; c < CIN; c += 128) {
        float s = 0.f;
        for (int p = 0; p < 32; p++) s += P[(b * 32 + p) * CIN + c];
        xm[c] = s * (1.0f / VV);
    }
    __syncthreads();
    float s = ba[f];
    for (int c = 0; c < CIN; c++) s += xm[c] * wa[c * FF + f];
    a[b * FF + f] = s;
}

__global__ void k_degD(const float* __restrict__ H, float* __restrict__ D)
{
    const int row  = blockIdx.x * 8 + (threadIdx.x >> 5);
    const int lane = threadIdx.x & 31;
    if (row >= BB * VV) return;
    const float* r = H + (long)row * EE;
    float s = 0.f;
    for (int c = lane; c < EE; c += 32) s += r[c];
    for (int o = 16; o; o >>= 1) s += __shfl_xor_sync(0xFFFFFFFFu, s, o);
    if (lane == 0) D[row] = rsqrtf(s);
}

__global__ void k_bpart(const float* __restrict__ H, float* __restrict__ P)
{
    const int b = blockIdx.x, p = blockIdx.y, e = threadIdx.x;
    const float* base = H + ((long)b * VV + p * 256) * EE + e;
    float s = 0.f;
    for (int v = 0; v < 256; v++) s += base[(long)v * EE];
    P[(b * 16 + p) * EE + e] = s;
}

__global__ void k_finishBe(const float* __restrict__ P, float* __restrict__ Be)
{
    const int b = blockIdx.x, e = threadIdx.x;
    float s = 0.f;
    for (int p = 0; p < 16; p++) s += P[(b * 16 + p) * EE + e];
    Be[b * EE + e] = 1.0f / s;
}

// ---------------------------------------------------------------------------
extern "C" void kernel_launch(void* const* d_in, const int* in_sizes, int n_in,
                              void* d_out, int out_size)
{
    const float* x   = (const float*)d_in[0];
    const float* wph = (const float*)d_in[1];
    const float* bph = (const float*)d_in[2];
    const float* wa  = (const float*)d_in[3];
    const float* ba  = (const float*)d_in[4];
    const float* wm  = (const float*)d_in[5];
    const float* bm  = (const float*)d_in[6];
    const float* w2  = (const float*)d_in[7];
    const float* b2  = (const float*)d_in[8];
    float* out = (float*)d_out;

    float *phi, *Mb, *tb, *Hb, *Db, *Beb, *tmpb, *Rb, *ab, *xp, *bp, *p1, *p2;
    __half *xh, *wh;
    cudaGetSymbolAddress((void**)&phi,  g_phi);
    cudaGetSymbolAddress((void**)&Mb,   g_M);
    cudaGetSymbolAddress((void**)&tb,   g_t);
    cudaGetSymbolAddress((void**)&Hb,   g_H);
    cudaGetSymbolAddress((void**)&Db,   g_D);
    cudaGetSymbolAddress((void**)&Beb,  g_Be);
    cudaGetSymbolAddress((void**)&tmpb, g_tmp);
    cudaGetSymbolAddress((void**)&Rb,   g_R);
    cudaGetSymbolAddress((void**)&ab,   g_a);
    cudaGetSymbolAddress((void**)&xp,   g_xpart);
    cudaGetSymbolAddress((void**)&bp,   g_bpart);
    cudaGetSymbolAddress((void**)&p1,   g_part1);
    cudaGetSymbolAddress((void**)&p2,   g_part2);
    cudaGetSymbolAddress((void**)&xh,   g_xh);
    cudaGetSymbolAddress((void**)&wh,   g_wh);

    // 0) fp16 conversions for the tensor-core conv
    {
        long nx = (long)BB*VV*CIN;
        k_cvt_x<<<(unsigned)((nx + 255)/256), 256>>>(x, xh);
        long nw = 49L*EE*CIN;
        k_cvt_wt<<<(unsigned)((nw + 255)/256), 256>>>(wm, wh);
    }

    // 1) pooled mean + a vector
    k_xpart<<<dim3(BB, 32), 256>>>(x, xp);
    k_a<<<BB, 128>>>(xp, wa, ba, ab);

    // 2) phi = x @ w_phi + b_phi
    sgemm_nn_v2<<<dim3(FF/128, (BB*VV)/128, 1), 256>>>(
        x, wph, phi, BB*VV, FF, CIN, 0, 0, 0,
        nullptr, 0, nullptr, 0, bph, 0, nullptr, 0);

    // 3) M = conv7x7(x) + b_m   — HMMA fp16 single-product implicit GEMM
    {
        const int smem_bytes = 2 * STAGE_B;   // 73728
        cudaFuncSetAttribute(conv7_mma, cudaFuncAttributeMaxDynamicSharedMemorySize, smem_bytes);
        conv7_mma<<<dim3(EE/128, VV/128, BB), 256, smem_bytes>>>(xh, wh, bm, Mb);
    }

    // 4) t = phi^T @ M  (split-K, FFMA2)
    sgemm_tn_v2<<<dim3(EE/128, FF/128, BB*SPLITK), 256>>>(
        phi, Mb, p1, FF, EE, VV, FF,
        (long)VV*FF, (long)VV*EE, (long)FF*EE, nullptr, 0, SPLITK);
    k_reduce_split<<<(BB*FF*EE + 255)/256, 256>>>(p1, tb, FF*EE, BB, SPLITK);

    // 5) H = | phi @ (diag(a) t) |
    sgemm_nn_v2<<<dim3(EE/128, VV/128, BB), 256>>>(
        phi, tb, Hb, VV, EE, FF,
        (long)VV*FF, (long)FF*EE, (long)VV*EE,
        nullptr, 0, ab, FF, nullptr, 1, nullptr, 0);

    // 6) degrees
    k_degD<<<(BB*VV)/8, 256>>>(Hb, Db);
    k_bpart<<<dim3(BB, 16), 256>>>(Hb, bp);
    k_finishBe<<<BB, 256>>>(bp, Beb);

    // 7) tmp = (D^-1/2 H)^T @ x  (split-K, FFMA2; D^-1/2 as k-scale)
    sgemm_tn_v2<<<dim3(CIN/128, EE/128, BB*SPLITK), 256>>>(
        Hb, x, p2, EE, CIN, VV, EE,
        (long)VV*EE, (long)VV*CIN, (long)EE*CIN, Db, VV, SPLITK);
    k_reduce_split<<<(BB*EE*CIN + 255)/256, 256>>>(p2, tmpb, EE*CIN, BB, SPLITK);

    // 8) R = x - (D^-1/2 H) @ (diag(1/Be) tmp)
    sgemm_nn_v2<<<dim3(CIN/128, VV/128, BB), 256>>>(
        Hb, tmpb, Rb, VV, CIN, EE,
        (long)VV*EE, (long)EE*CIN, (long)VV*CIN,
        Db, VV, Beb, EE, nullptr, 2, x, (long)VV*CIN);

    // 9) out = R @ weight_2 + bias_2
    sgemm_nn_v2<<<dim3(COUT/128, (BB*VV)/128, 1), 256>>>(
        Rb, w2, out, BB*VV, COUT, CIN, 0, 0, 0,
        nullptr, 0, nullptr, 0, b2, 0, nullptr, 0);
}

// round 8
// speedup vs baseline: 3.8797x; 1.0073x over previous
#include <cuda_runtime.h>
#include <cuda_fp16.h>
#include <math.h>
#include <stdint.h>

// Problem dims (fixed by the dataset)
#define BB   8
#define HHH  64
#define WWW  64
#define VV   4096      // HHH*WWW
#define CIN  256
#define FF   128
#define EE   256
#define COUT 256
#define SPLITK_T 16    // t GEMM split
#define SPLITK_P 8     // tmp GEMM split

// ---------------- scratch (static device globals; no allocation allowed) ----
__device__ __half g_phi16[BB*VV*FF];     // 8 MB
__device__ __half g_M16 [BB*VV*EE];      // 16 MB
__device__ __half g_H16 [BB*VV*EE];      // 16 MB
__device__ float g_t   [BB*FF*EE];
__device__ float g_D   [BB*VV];
__device__ float g_Be  [BB*EE];
__device__ float g_tmp [BB*EE*CIN];
__device__ float g_R   [BB*VV*CIN];      // fp32: direct output path
__device__ float g_a   [BB*FF];
__device__ float g_xpart[BB*32*CIN];
__device__ float g_xmean[BB*CIN];
__device__ float g_bpart[BB*16*EE];
__device__ float g_part1[SPLITK_T*BB*FF*EE];
__device__ float g_part2[SPLITK_P*BB*EE*CIN];
__device__ __half g_xh[BB*VV*CIN];
__device__ __half g_wh[49*EE*CIN];       // transposed: [tap][e][c], fp16

// ======================= PTX helpers ========================================
__device__ __forceinline__ uint32_t smem_u32(const void* p) {
    uint32_t a;
    asm("{ .reg .u64 t; cvta.to.shared.u64 t, %1; cvt.u32.u64 %0, t; }" : "=r"(a) : "l"(p));
    return a;
}
#define CP_ASYNC16(dst, src, sz) \
    asm volatile("cp.async.cg.shared.global [%0], [%1], 16, %2;" \
                 :: "r"(dst), "l"(src), "r"(sz) : "memory")
#define CP_COMMIT() asm volatile("cp.async.commit_group;" ::: "memory")
#define CP_WAIT(n)  asm volatile("cp.async.wait_group %0;" :: "n"(n) : "memory")
#define LDSM4(r, addr) \
    asm volatile("ldmatrix.sync.aligned.m8n8.x4.shared.b16 {%0,%1,%2,%3}, [%4];" \
                 : "=r"((r)[0]), "=r"((r)[1]), "=r"((r)[2]), "=r"((r)[3]) : "r"(addr))
#define MMA16816H(d, a, b0, b1) \
    asm volatile("mma.sync.aligned.m16n8k16.row.col.f32.f16.f16.f32 " \
                 "{%0,%1,%2,%3}, {%4,%5,%6,%7}, {%8,%9}, {%0,%1,%2,%3};" \
                 : "+f"((d)[0]), "+f"((d)[1]), "+f"((d)[2]), "+f"((d)[3]) \
                 : "r"((a)[0]), "r"((a)[1]), "r"((a)[2]), "r"((a)[3]), \
                   "r"(b0), "r"(b1))

// 8 halfs (uint4) -> two float4
__device__ __forceinline__ void h8_f8(uint4 v, float4 &lo, float4 &hi) {
    const __half2* h = (const __half2*)&v;
    float2 f0 = __half22float2(h[0]), f1 = __half22float2(h[1]);
    float2 f2 = __half22float2(h[2]), f3 = __half22float2(h[3]);
    lo = make_float4(f0.x, f0.y, f1.x, f1.y);
    hi = make_float4(f2.x, f2.y, f3.x, f3.y);
}

// ======================= fp16 preprocessing =================================
__global__ void k_cvt_x(const float* __restrict__ x, __half* __restrict__ xh)
{
    long i = (long)blockIdx.x * 256 + threadIdx.x;
    if (i >= (long)BB*VV*CIN) return;
    xh[i] = __float2half(x[i]);
}

__global__ void k_cvt_wt(const float* __restrict__ wm, __half* __restrict__ wh)
{
    long i = (long)blockIdx.x * 256 + threadIdx.x;   // (tap, e, c)
    if (i >= 49L*EE*CIN) return;
    int tap = (int)(i / (EE*CIN));
    int r   = (int)(i % (EE*CIN));
    int e = r / CIN, c = r % CIN;
    wh[i] = __float2half(wm[((long)tap*CIN + c)*EE + e]);
}

// ======================= HMMA 7x7 conv (fp16 in, fp16 out) ==================
#define ROWB   144
#define TILE_B (128*ROWB)
#define OFF_A  0
#define OFF_B  (TILE_B)
#define STAGE_B (2*TILE_B)
#define NCHUNK  196

__global__ __launch_bounds__(256, 2) void conv7_mma(
    const __half* __restrict__ xh, const __half* __restrict__ wh,
    const float* __restrict__ bias, __half* __restrict__ out)
{
    extern __shared__ __align__(128) char smem[];
    const uint32_t sbase = smem_u32(smem);
    const int tid = threadIdx.x;
    const int wid = tid >> 5, lane = tid & 31;
    const int e0 = blockIdx.x * 128, v0 = blockIdx.y * 128, b = blockIdx.z;
    const int warpm = wid >> 1, warpn = wid & 1;

    const int rowA = tid >> 1, half = (tid & 1) * 32;
    const int vh = (v0 + rowA) >> 6, vw = (v0 + rowA) & 63;
    const uint32_t dstRow = rowA * ROWB + half * 2;

    auto issue = [&](int it) {
        const int tap = it >> 2, kc = (it & 3) * 64;
        const int dy = tap / 7 - 3, dx = tap % 7 - 3;
        const int hh = vh + dy, ww = vw + dx;
        const bool okA = ((unsigned)hh < 64u) && ((unsigned)ww < 64u);
        const uint32_t szA = okA ? 16u : 0u;
        const long aoff = okA ? ((long)b*VV + (hh<<6) + ww)*CIN + kc + half : 0;
        const long boff = ((long)tap*EE + e0 + rowA)*CIN + kc + half;
        const uint32_t stg = sbase + (it & 1) * STAGE_B;
        #pragma unroll
        for (int j = 0; j < 4; j++) {
            CP_ASYNC16(stg + OFF_A + dstRow + j*16, xh + aoff + j*8, szA);
            CP_ASYNC16(stg + OFF_B + dstRow + j*16, wh + boff + j*8, 16u);
        }
        CP_COMMIT();
    };

    float acc[2][8][4];
    #pragma unroll
    for (int mt = 0; mt < 2; mt++)
        #pragma unroll
        for (int nt = 0; nt < 8; nt++)
            #pragma unroll
            for (int q = 0; q < 4; q++) acc[mt][nt][q] = 0.f;

    const uint32_t aLdOff = (warpm*32 + (lane & 15)) * ROWB + (lane >> 4) * 16;
    const uint32_t bLdOff = (warpn*64 + (lane & 7) + ((lane >> 4) & 1) * 8) * ROWB
                          + (((lane >> 3) & 1) * 8) * 2;

    issue(0);

    for (int it = 0; it < NCHUNK; it++) {
        if (it + 1 < NCHUNK) { issue(it + 1); CP_WAIT(1); }
        else                 { CP_WAIT(0); }
        __syncthreads();

        const uint32_t stg = sbase + (it & 1) * STAGE_B;
        #pragma unroll
        for (int k16 = 0; k16 < 4; k16++) {
            const uint32_t kByte = k16 * 32;
            uint32_t ah[2][4];
            #pragma unroll
            for (int mt = 0; mt < 2; mt++) {
                LDSM4(ah[mt], stg + OFF_A + aLdOff + mt * 16 * ROWB + kByte);
            }
            #pragma unroll
            for (int np = 0; np < 4; np++) {
                uint32_t bb[4];
                LDSM4(bb, stg + OFF_B + bLdOff + np * 16 * ROWB + kByte);
                #pragma unroll
                for (int mt = 0; mt < 2; mt++) {
                    MMA16816H(acc[mt][2*np],   ah[mt], bb[0], bb[1]);
                    MMA16816H(acc[mt][2*np+1], ah[mt], bb[2], bb[3]);
                }
            }
        }
        __syncthreads();
    }

    // epilogue: +bias, store fp16
    const int r = lane >> 2, c2 = (lane & 3) * 2;
    #pragma unroll
    for (int mt = 0; mt < 2; mt++) {
        #pragma unroll
        for (int nt = 0; nt < 8; nt++) {
            const int v = v0 + warpm*32 + mt*16 + r;
            const int e = e0 + warpn*64 + nt*8 + c2;
            const float bx = bias[e], by = bias[e+1];
            __half* p0 = out + ((long)b*VV + v)*EE + e;
            __half* p1 = p0 + 8L*EE;
            *(__half2*)p0 = __floats2half2_rn(acc[mt][nt][0] + bx, acc[mt][nt][1] + by);
            *(__half2*)p1 = __floats2half2_rn(acc[mt][nt][2] + bx, acc[mt][nt][3] + by);
        }
    }
}

// ------------------------- FFMA2 helpers ------------------------------------
typedef unsigned long long ull;

__device__ __forceinline__ void ffma2(ull &d, ull a, ull b) {
    asm("fma.rn.f32x2 %0, %1, %2, %0;" : "+l"(d) : "l"(a), "l"(b));
}
__device__ __forceinline__ ull bcast2(float v) {
    ull r;
    asm("mov.b64 %0, {%1, %1};" : "=l"(r) : "f"(v));
    return r;
}
__device__ __forceinline__ float lof(ull v){ return __uint_as_float((unsigned)v); }
__device__ __forceinline__ float hif(ull v){ return __uint_as_float((unsigned)(v>>32)); }

#define INNER_16(As, Bs, acc, tx, ty)                                          \
    _Pragma("unroll")                                                          \
    for (int kk = 0; kk < 16; kk++) {                                          \
        ulonglong2 A0 = *(const ulonglong2*)&As[kk][ty*4];                     \
        ulonglong2 A1 = *(const ulonglong2*)&As[kk][64 + ty*4];                \
        float4 bv0 = *(const float4*)&Bs[kk][tx*4];                            \
        float4 bv1 = *(const float4*)&Bs[kk][64 + tx*4];                       \
        ull bb0 = bcast2(bv0.x), bb1 = bcast2(bv0.y);                          \
        ull bb2 = bcast2(bv0.z), bb3 = bcast2(bv0.w);                          \
        ull bb4 = bcast2(bv1.x), bb5 = bcast2(bv1.y);                          \
        ull bb6 = bcast2(bv1.z), bb7 = bcast2(bv1.w);                          \
        ffma2(acc[0][0], A0.x, bb0); ffma2(acc[0][1], A0.x, bb1);              \
        ffma2(acc[0][2], A0.x, bb2); ffma2(acc[0][3], A0.x, bb3);              \
        ffma2(acc[0][4], A0.x, bb4); ffma2(acc[0][5], A0.x, bb5);              \
        ffma2(acc[0][6], A0.x, bb6); ffma2(acc[0][7], A0.x, bb7);              \
        ffma2(acc[1][0], A0.y, bb0); ffma2(acc[1][1], A0.y, bb1);              \
        ffma2(acc[1][2], A0.y, bb2); ffma2(acc[1][3], A0.y, bb3);              \
        ffma2(acc[1][4], A0.y, bb4); ffma2(acc[1][5], A0.y, bb5);              \
        ffma2(acc[1][6], A0.y, bb6); ffma2(acc[1][7], A0.y, bb7);              \
        ffma2(acc[2][0], A1.x, bb0); ffma2(acc[2][1], A1.x, bb1);              \
        ffma2(acc[2][2], A1.x, bb2); ffma2(acc[2][3], A1.x, bb3);              \
        ffma2(acc[2][4], A1.x, bb4); ffma2(acc[2][5], A1.x, bb5);              \
        ffma2(acc[2][6], A1.x, bb6); ffma2(acc[2][7], A1.x, bb7);              \
        ffma2(acc[3][0], A1.y, bb0); ffma2(acc[3][1], A1.y, bb1);              \
        ffma2(acc[3][2], A1.y, bb2); ffma2(acc[3][3], A1.y, bb3);              \
        ffma2(acc[3][4], A1.y, bb4); ffma2(acc[3][5], A1.y, bb5);              \
        ffma2(acc[3][6], A1.y, bb6); ffma2(acc[3][7], A1.y, bb7);              \
    }

// ---------------------------------------------------------------------------
// 128x128x16 FFMA2 NN GEMM. AHALF: A fp16; CHALF: C stored fp16.
// modes: 0 bias, 1 abs, 2 resid-minus
// ---------------------------------------------------------------------------
template<bool AHALF, bool CHALF>
__global__ __launch_bounds__(256) void sgemm_nn_v3(
    const void* __restrict__ Av, const float* __restrict__ Bm, void* __restrict__ Cv,
    int M, int N, int K,
    long aB, long bB, long cB,
    const float* __restrict__ aRS, int aRSb,
    const float* __restrict__ bKS, int bKSb,
    const float* __restrict__ bias,
    int mode, const float* __restrict__ resid, long rB)
{
    __shared__ float As[16][132];
    __shared__ float Bs[16][132];

    const int b  = blockIdx.z;
    const float* Bb = Bm + (long)b * bB;

    const int m0 = blockIdx.y * 128, n0 = blockIdx.x * 128;
    const int tid = threadIdx.x;
    const int tx = tid & 15, ty = tid >> 4;
    const int lr  = tid >> 1, lkh = (tid & 1) * 8;
    const int bk  = tid >> 4, bn  = (tid & 15) * 4;

    ull acc[4][8] = {};
    const int nk = K / 16;

    float4 ra0, ra1, rb0, rb1;

    auto loadA = [&](int k0) {
        if (AHALF) {
            const __half* ap = (const __half*)Av + (long)b*aB + (long)(m0 + lr) * K + k0 + lkh;
            h8_f8(*(const uint4*)ap, ra0, ra1);
        } else {
            const float* ap = (const float*)Av + (long)b*aB + (long)(m0 + lr) * K + k0 + lkh;
            ra0 = *(const float4*)ap; ra1 = *(const float4*)(ap + 4);
        }
        if (aRS) {
            float s = aRS[b * aRSb + m0 + lr];
            ra0.x*=s; ra0.y*=s; ra0.z*=s; ra0.w*=s;
            ra1.x*=s; ra1.y*=s; ra1.z*=s; ra1.w*=s;
        }
    };
    auto loadB = [&](int k0) {
        const float* bp = &Bb[(long)(k0 + bk) * N + n0];
        rb0 = *(const float4*)(bp + bn); rb1 = *(const float4*)(bp + 64 + bn);
        if (bKS) {
            float s = bKS[b * bKSb + k0 + bk];
            rb0.x*=s; rb0.y*=s; rb0.z*=s; rb0.w*=s;
            rb1.x*=s; rb1.y*=s; rb1.z*=s; rb1.w*=s;
        }
    };

    loadA(0); loadB(0);

    for (int c = 0; c < nk; c++) {
        __syncthreads();
        As[lkh+0][lr] = ra0.x; As[lkh+1][lr] = ra0.y;
        As[lkh+2][lr] = ra0.z; As[lkh+3][lr] = ra0.w;
        As[lkh+4][lr] = ra1.x; As[lkh+5][lr] = ra1.y;
        As[lkh+6][lr] = ra1.z; As[lkh+7][lr] = ra1.w;
        *(float4*)&Bs[bk][bn]      = rb0;
        *(float4*)&Bs[bk][64 + bn] = rb1;
        __syncthreads();

        if (c + 1 < nk) { loadA((c+1)*16); loadB((c+1)*16); }

        INNER_16(As, Bs, acc, tx, ty)
    }

    float4 biasA = make_float4(0.f,0.f,0.f,0.f), biasB = biasA;
    if (bias) {
        biasA = *(const float4*)&bias[n0 + tx*4];
        biasB = *(const float4*)&bias[n0 + 64 + tx*4];
    }

    #pragma unroll
    for (int p = 0; p < 4; p++) {
        int mbase = m0 + ((p < 2) ? 0 : 64) + ty*4 + (p & 1) * 2;
        #pragma unroll
        for (int h = 0; h < 2; h++) {
            long m = mbase + h;
            float4 c0, c1;
            if (h == 0) {
                c0 = make_float4(lof(acc[p][0]), lof(acc[p][1]), lof(acc[p][2]), lof(acc[p][3]));
                c1 = make_float4(lof(acc[p][4]), lof(acc[p][5]), lof(acc[p][6]), lof(acc[p][7]));
            } else {
                c0 = make_float4(hif(acc[p][0]), hif(acc[p][1]), hif(acc[p][2]), hif(acc[p][3]));
                c1 = make_float4(hif(acc[p][4]), hif(acc[p][5]), hif(acc[p][6]), hif(acc[p][7]));
            }
            c0.x += biasA.x; c0.y += biasA.y; c0.z += biasA.z; c0.w += biasA.w;
            c1.x += biasB.x; c1.y += biasB.y; c1.z += biasB.z; c1.w += biasB.w;
            long off0 = m * N + n0 + tx*4;
            long off1 = m * N + n0 + 64 + tx*4;
            if (mode == 1) {
                c0.x=fabsf(c0.x); c0.y=fabsf(c0.y); c0.z=fabsf(c0.z); c0.w=fabsf(c0.w);
                c1.x=fabsf(c1.x); c1.y=fabsf(c1.y); c1.z=fabsf(c1.z); c1.w=fabsf(c1.w);
            } else if (mode == 2) {
                float4 r0 = *(const float4*)&resid[(long)b * rB + off0];
                float4 r1 = *(const float4*)&resid[(long)b * rB + off1];
                c0.x = r0.x - c0.x; c0.y = r0.y - c0.y; c0.z = r0.z - c0.z; c0.w = r0.w - c0.w;
                c1.x = r1.x - c1.x; c1.y = r1.y - c1.y; c1.z = r1.z - c1.z; c1.w = r1.w - c1.w;
            }
            if (CHALF) {
                __half* cp = (__half*)Cv + (long)b * cB;
                *(__half2*)&cp[off0]     = __floats2half2_rn(c0.x, c0.y);
                *(__half2*)&cp[off0 + 2] = __floats2half2_rn(c0.z, c0.w);
                *(__half2*)&cp[off1]     = __floats2half2_rn(c1.x, c1.y);
                *(__half2*)&cp[off1 + 2] = __floats2half2_rn(c1.z, c1.w);
            } else {
                float* cp = (float*)Cv + (long)b * cB;
                *(float4*)&cp[off0] = c0;
                *(float4*)&cp[off1] = c1;
            }
        }
    }
}

// ---------------------------------------------------------------------------
// 128x128x16 FFMA2 TN GEMM with split-K. A always fp16 [Kd, lda]; BHALF: B fp16.
// ---------------------------------------------------------------------------
template<bool BHALF>
__global__ __launch_bounds__(256) void sgemm_tn_v3(
    const __half* __restrict__ A, const void* __restrict__ Bv, float* __restrict__ C,
    int M, int N, int Kd, int lda,
    long aB, long bB, long cB,
    const float* __restrict__ kS, int kSb,
    int split)
{
    __shared__ float As[16][132];
    __shared__ float Bs[16][132];

    const int zb = blockIdx.z;
    const int b = zb / split, s = zb % split;
    const int kchunk = Kd / split;
    const int kbeg = s * kchunk, kend = kbeg + kchunk;

    const __half* Ab = A + (long)b * aB;
    float* Cb = C + (long)zb * cB;

    const int m0 = blockIdx.y * 128, n0 = blockIdx.x * 128;
    const int tid = threadIdx.x, tx = tid & 15, ty = tid >> 4;
    const int lk = tid >> 4, lm = (tid & 15) * 8;

    ull acc[4][8] = {};

    for (int k0 = kbeg; k0 < kend; k0 += 16) {
        float4 a0, a1, b0, b1;
        h8_f8(*(const uint4*)&Ab[(long)(k0 + lk) * lda + m0 + lm], a0, a1);
        if (kS) {
            float sc = kS[b * kSb + k0 + lk];
            a0.x*=sc; a0.y*=sc; a0.z*=sc; a0.w*=sc;
            a1.x*=sc; a1.y*=sc; a1.z*=sc; a1.w*=sc;
        }
        if (BHALF) {
            const __half* bp = (const __half*)Bv + (long)b*bB + (long)(k0 + lk) * N + n0 + lm;
            h8_f8(*(const uint4*)bp, b0, b1);
        } else {
            const float* bp = (const float*)Bv + (long)b*bB + (long)(k0 + lk) * N + n0 + lm;
            b0 = *(const float4*)bp; b1 = *(const float4*)(bp + 4);
        }

        __syncthreads();
        *(float4*)&As[lk][lm]     = a0;
        *(float4*)&As[lk][lm + 4] = a1;
        *(float4*)&Bs[lk][lm]     = b0;
        *(float4*)&Bs[lk][lm + 4] = b1;
        __syncthreads();

        INNER_16(As, Bs, acc, tx, ty)
    }

    #pragma unroll
    for (int p = 0; p < 4; p++) {
        int mbase = m0 + ((p < 2) ? 0 : 64) + ty*4 + (p & 1) * 2;
        #pragma unroll
        for (int h = 0; h < 2; h++) {
            long m = mbase + h;
            float4 c0, c1;
            if (h == 0) {
                c0 = make_float4(lof(acc[p][0]), lof(acc[p][1]), lof(acc[p][2]), lof(acc[p][3]));
                c1 = make_float4(lof(acc[p][4]), lof(acc[p][5]), lof(acc[p][6]), lof(acc[p][7]));
            } else {
                c0 = make_float4(hif(acc[p][0]), hif(acc[p][1]), hif(acc[p][2]), hif(acc[p][3]));
                c1 = make_float4(hif(acc[p][4]), hif(acc[p][5]), hif(acc[p][6]), hif(acc[p][7]));
            }
            *(float4*)&Cb[m * N + n0 + tx*4]      = c0;
            *(float4*)&Cb[m * N + n0 + 64 + tx*4] = c1;
        }
    }
}

__global__ void k_reduce_split(const float* __restrict__ part, float* __restrict__ out,
                               int mn, int batches, int split)
{
    long i = (long)blockIdx.x * 256 + threadIdx.x;
    if (i >= (long)batches * mn) return;
    int b = (int)(i / mn), r = (int)(i % mn);
    float sum = 0.f;
    for (int s = 0; s < split; s++)
        sum += part[((long)(b * split + s)) * mn + r];
    out[i] = sum;
}

// -------------------- small reduction / pointwise kernels -------------------
__global__ void k_xpart(const float* __restrict__ x, float* __restrict__ P)
{
    const int b = blockIdx.x, p = blockIdx.y, c = threadIdx.x;
    const float* base = x + ((long)b * VV + p * 128) * CIN + c;
    float s = 0.f;
    for (int v = 0; v < 128; v++) s += base[(long)v * CIN];
    P[(b * 32 + p) * CIN + c] = s;
}

__global__ void k_xmean(const float* __restrict__ P, float* __restrict__ xm)
{
    const int b = blockIdx.x, c = threadIdx.x;   // 256 threads
    float s = 0.f;
    for (int p = 0; p < 32; p++) s += P[(b * 32 + p) * CIN + c];
    xm[b * CIN + c] = s * (1.0f / VV);
}

__global__ void k_a(const float* __restrict__ xmg, const float* __restrict__ wa,
                    const float* __restrict__ ba, float* __restrict__ a)
{
    __shared__ float xm[CIN];
    const int b = blockIdx.x, f = threadIdx.x;   // 128 threads
    xm[f] = xmg[b * CIN + f];
    xm[f + 128] = xmg[b * CIN + f + 128];
    __syncthreads();
    float s = ba[f];
    #pragma unroll 8
    for (int c = 0; c < CIN; c++) s += xm[c] * wa[c * FF + f];
    a[b * FF + f] = s;
}

__global__ void k_degD(const __half* __restrict__ H, float* __restrict__ D)
{
    const int row  = blockIdx.x * 8 + (threadIdx.x >> 5);
    const int lane = threadIdx.x & 31;
    if (row >= BB * VV) return;
    const __half2* r = (const __half2*)(H + (long)row * EE);
    float s = 0.f;
    for (int c = lane; c < EE/2; c += 32) {
        float2 f = __half22float2(r[c]);
        s += f.x + f.y;
    }
    for (int o = 16; o; o >>= 1) s += __shfl_xor_sync(0xFFFFFFFFu, s, o);
    if (lane == 0) D[row] = rsqrtf(s);
}

__global__ void k_bpart(const __half* __restrict__ H, float* __restrict__ P)
{
    const int b = blockIdx.x, p = blockIdx.y, e = threadIdx.x;
    const __half* base = H + ((long)b * VV + p * 256) * EE + e;
    float s = 0.f;
    for (int v = 0; v < 256; v++) s += __half2float(base[(long)v * EE]);
    P[(b * 16 + p) * EE + e] = s;
}

__global__ void k_finishBe(const float* __restrict__ P, float* __restrict__ Be)
{
    const int b = blockIdx.x, e = threadIdx.x;
    float s = 0.f;
    for (int p = 0; p < 16; p++) s += P[(b * 16 + p) * EE + e];
    Be[b * EE + e] = 1.0f / s;
}

// ---------------------------------------------------------------------------
extern "C" void kernel_launch(void* const* d_in, const int* in_sizes, int n_in,
                              void* d_out, int out_size)
{
    const float* x   = (const float*)d_in[0];
    const float* wph = (const float*)d_in[1];
    const float* bph = (const float*)d_in[2];
    const float* wa  = (const float*)d_in[3];
    const float* ba  = (const float*)d_in[4];
    const float* wm  = (const float*)d_in[5];
    const float* bm  = (const float*)d_in[6];
    const float* w2  = (const float*)d_in[7];
    const float* b2  = (const float*)d_in[8];
    float* out = (float*)d_out;

    float *tb, *Db, *Beb, *tmpb, *Rb, *ab, *xp, *xmg, *bp, *p1, *p2;
    __half *xh, *wh, *phi16, *M16, *H16;
    cudaGetSymbolAddress((void**)&phi16, g_phi16);
    cudaGetSymbolAddress((void**)&M16,  g_M16);
    cudaGetSymbolAddress((void**)&H16,  g_H16);
    cudaGetSymbolAddress((void**)&tb,   g_t);
    cudaGetSymbolAddress((void**)&Db,   g_D);
    cudaGetSymbolAddress((void**)&Beb,  g_Be);
    cudaGetSymbolAddress((void**)&tmpb, g_tmp);
    cudaGetSymbolAddress((void**)&Rb,   g_R);
    cudaGetSymbolAddress((void**)&ab,   g_a);
    cudaGetSymbolAddress((void**)&xp,   g_xpart);
    cudaGetSymbolAddress((void**)&xmg,  g_xmean);
    cudaGetSymbolAddress((void**)&bp,   g_bpart);
    cudaGetSymbolAddress((void**)&p1,   g_part1);
    cudaGetSymbolAddress((void**)&p2,   g_part2);
    cudaGetSymbolAddress((void**)&xh,   g_xh);
    cudaGetSymbolAddress((void**)&wh,   g_wh);

    // 0) fp16 conversions
    {
        long nx = (long)BB*VV*CIN;
        k_cvt_x<<<(unsigned)((nx + 255)/256), 256>>>(x, xh);
        long nw = 49L*EE*CIN;
        k_cvt_wt<<<(unsigned)((nw + 255)/256), 256>>>(wm, wh);
    }

    // 1) pooled mean + a vector
    k_xpart<<<dim3(BB, 32), 256>>>(x, xp);
    k_xmean<<<BB, 256>>>(xp, xmg);
    k_a<<<BB, 128>>>(xmg, wa, ba, ab);

    // 2) phi = x @ w_phi + b_phi   (A=xh fp16, C=phi16 fp16)
    sgemm_nn_v3<true, true><<<dim3(FF/128, (BB*VV)/128, 1), 256>>>(
        xh, wph, phi16, BB*VV, FF, CIN, 0, 0, 0,
        nullptr, 0, nullptr, 0, bph, 0, nullptr, 0);

    // 3) M = conv7x7(x) + b_m  (fp16 out)
    {
        const int smem_bytes = 2 * STAGE_B;   // 73728
        cudaFuncSetAttribute(conv7_mma, cudaFuncAttributeMaxDynamicSharedMemorySize, smem_bytes);
        conv7_mma<<<dim3(EE/128, VV/128, BB), 256, smem_bytes>>>(xh, wh, bm, M16);
    }

    // 4) t = phi^T @ M  (split-K, A/B fp16)
    sgemm_tn_v3<true><<<dim3(EE/128, FF/128, BB*SPLITK_T), 256>>>(
        phi16, M16, p1, FF, EE, VV, FF,
        (long)VV*FF, (long)VV*EE, (long)FF*EE, nullptr, 0, SPLITK_T);
    k_reduce_split<<<(BB*FF*EE + 255)/256, 256>>>(p1, tb, FF*EE, BB, SPLITK_T);

    // 5) H = | phi @ (diag(a) t) |   (A=phi16, C=H16)
    sgemm_nn_v3<true, true><<<dim3(EE/128, VV/128, BB), 256>>>(
        phi16, tb, H16, VV, EE, FF,
        (long)VV*FF, (long)FF*EE, (long)VV*EE,
        nullptr, 0, ab, FF, nullptr, 1, nullptr, 0);

    // 6) degrees (read H16)
    k_degD<<<(BB*VV)/8, 256>>>(H16, Db);
    k_bpart<<<dim3(BB, 16), 256>>>(H16, bp);
    k_finishBe<<<BB, 256>>>(bp, Beb);

    // 7) tmp = (D^-1/2 H)^T @ x  (split-K, A=H16, B=x fp32)
    sgemm_tn_v3<false><<<dim3(CIN/128, EE/128, BB*SPLITK_P), 256>>>(
        H16, x, p2, EE, CIN, VV, EE,
        (long)VV*EE, (long)VV*CIN, (long)EE*CIN, Db, VV, SPLITK_P);
    k_reduce_split<<<(BB*EE*CIN + 255)/256, 256>>>(p2, tmpb, EE*CIN, BB, SPLITK_P);

    // 8) R = x - (D^-1/2 H) @ (diag(1/Be) tmp)   (A=H16, C=R fp32)
    sgemm_nn_v3<true, false><<<dim3(CIN/128, VV/128, BB), 256>>>(
        H16, tmpb, Rb, VV, CIN, EE,
        (long)VV*EE, (long)EE*CIN, (long)VV*CIN,
        Db, VV, Beb, EE, nullptr, 2, x, (long)VV*CIN);

    // 9) out = R @ weight_2 + bias_2   (all fp32)
    sgemm_nn_v3<false, false><<<dim3(COUT/128, (BB*VV)/128, 1), 256>>>(
        Rb, w2, out, BB*VV, COUT, CIN, 0, 0, 0,
        nullptr, 0, nullptr, 0, b2, 0, nullptr, 0);
}

// round 9
// speedup vs baseline: 4.6185x; 1.1904x over previous
#include <cuda_runtime.h>
#include <cuda_fp16.h>
#include <math.h>
#include <stdint.h>

// Problem dims (fixed by the dataset)
#define BB   8
#define HHH  64
#define WWW  64
#define VV   4096      // HHH*WWW
#define CIN  256
#define FF   128
#define EE   256
#define COUT 256
#define SPLITK_T 16    // t GEMM split
#define SPLITK_P 8     // tmp GEMM split

// ---------------- scratch (static device globals; no allocation allowed) ----
__device__ __half g_phi16[BB*VV*FF];
__device__ __half g_M16 [BB*VV*EE];
__device__ __half g_H16 [BB*VV*EE];
__device__ __half g_R16 [BB*VV*CIN];
__device__ float g_t   [BB*FF*EE];
__device__ float g_D   [BB*VV];
__device__ float g_Be  [BB*EE];
__device__ float g_tmp [BB*EE*CIN];
__device__ float g_a   [BB*FF];
__device__ float g_xpart[BB*32*CIN];
__device__ float g_xmean[BB*CIN];
__device__ float g_bpart[BB*16*EE];
__device__ float g_part1[SPLITK_T*BB*FF*EE];
__device__ float g_part2[SPLITK_P*BB*EE*CIN];
__device__ __half g_xh  [BB*VV*CIN];
__device__ __half g_wh  [49*EE*CIN];   // [tap][e][c]
__device__ __half g_wpht[FF*CIN];      // [f][c]
__device__ __half g_at  [BB*EE*FF];    // [b][e][f] = a_f * t_fe
__device__ __half g_w2t [COUT*CIN];    // [o][c]
__device__ __half g_btmp[BB*CIN*EE];   // [b][c][e] = Binv_e * tmp_ec

// ======================= PTX helpers ========================================
__device__ __forceinline__ uint32_t smem_u32(const void* p) {
    uint32_t a;
    asm("{ .reg .u64 t; cvta.to.shared.u64 t, %1; cvt.u32.u64 %0, t; }" : "=r"(a) : "l"(p));
    return a;
}
#define CP_ASYNC16(dst, src, sz) \
    asm volatile("cp.async.cg.shared.global [%0], [%1], 16, %2;" \
                 :: "r"(dst), "l"(src), "r"(sz) : "memory")
#define CP_COMMIT() asm volatile("cp.async.commit_group;" ::: "memory")
#define CP_WAIT(n)  asm volatile("cp.async.wait_group %0;" :: "n"(n) : "memory")
#define LDSM4(r, addr) \
    asm volatile("ldmatrix.sync.aligned.m8n8.x4.shared.b16 {%0,%1,%2,%3}, [%4];" \
                 : "=r"((r)[0]), "=r"((r)[1]), "=r"((r)[2]), "=r"((r)[3]) : "r"(addr))
#define MMA16816H(d, a, b0, b1) \
    asm volatile("mma.sync.aligned.m16n8k16.row.col.f32.f16.f16.f32 " \
                 "{%0,%1,%2,%3}, {%4,%5,%6,%7}, {%8,%9}, {%0,%1,%2,%3};" \
                 : "+f"((d)[0]), "+f"((d)[1]), "+f"((d)[2]), "+f"((d)[3]) \
                 : "r"((a)[0]), "r"((a)[1]), "r"((a)[2]), "r"((a)[3]), \
                   "r"(b0), "r"(b1))

__device__ __forceinline__ void h8_f8(uint4 v, float4 &lo, float4 &hi) {
    const __half2* h = (const __half2*)&v;
    float2 f0 = __half22float2(h[0]), f1 = __half22float2(h[1]);
    float2 f2 = __half22float2(h[2]), f3 = __half22float2(h[3]);
    lo = make_float4(f0.x, f0.y, f1.x, f1.y);
    hi = make_float4(f2.x, f2.y, f3.x, f3.y);
}

// ======================= conversion kernels =================================
__global__ void k_cvt_x(const float* __restrict__ x, __half* __restrict__ xh)
{
    long i = (long)blockIdx.x * 256 + threadIdx.x;
    if (i >= (long)BB*VV*CIN) return;
    xh[i] = __float2half(x[i]);
}

__global__ void k_cvt_wt(const float* __restrict__ wm, __half* __restrict__ wh)
{
    long i = (long)blockIdx.x * 256 + threadIdx.x;
    if (i >= 49L*EE*CIN) return;
    int tap = (int)(i / (EE*CIN));
    int r   = (int)(i % (EE*CIN));
    int e = r / CIN, c = r % CIN;
    wh[i] = __float2half(wm[((long)tap*CIN + c)*EE + e]);
}

__global__ void k_cvt_wpht(const float* __restrict__ wph, __half* __restrict__ wt)
{
    int i = blockIdx.x * 256 + threadIdx.x;   // f*CIN + c
    if (i >= FF*CIN) return;
    int f = i / CIN, c = i % CIN;
    wt[i] = __float2half(wph[c*FF + f]);
}

__global__ void k_cvt_w2t(const float* __restrict__ w2, __half* __restrict__ wt)
{
    int i = blockIdx.x * 256 + threadIdx.x;   // o*CIN + c
    if (i >= COUT*CIN) return;
    int o = i / CIN, c = i % CIN;
    wt[i] = __float2half(w2[c*COUT + o]);
}

// at[b][e][f] = a[b][f] * t[b][f][e]
__global__ void k_cvt_at(const float* __restrict__ t, const float* __restrict__ a,
                         __half* __restrict__ at)
{
    int i = blockIdx.x * 256 + threadIdx.x;   // b*EE*FF + e*FF + f
    if (i >= BB*EE*FF) return;
    int b = i / (EE*FF), r = i % (EE*FF);
    int e = r / FF, f = r % FF;
    at[i] = __float2half(a[b*FF + f] * t[((long)b*FF + f)*EE + e]);
}

// btmp[b][c][e] = Be[b][e] * tmp[b][e][c]
__global__ void k_cvt_btmp(const float* __restrict__ tmp, const float* __restrict__ Be,
                           __half* __restrict__ bt)
{
    int i = blockIdx.x * 256 + threadIdx.x;   // b*CIN*EE + c*EE + e
    if (i >= BB*CIN*EE) return;
    int b = i / (CIN*EE), r = i % (CIN*EE);
    int c = r / EE, e = r % EE;
    bt[i] = __float2half(Be[b*EE + e] * tmp[((long)b*EE + e)*CIN + c]);
}

// ======================= HMMA tile constants ================================
#define ROWB   144
#define TILE_B (128*ROWB)
#define OFF_A  0
#define OFF_B  (TILE_B)
#define STAGE_B (2*TILE_B)
#define NCHUNK  196

// ======================= HMMA 7x7 conv (fp16 in, fp16 out) ==================
__global__ __launch_bounds__(256, 2) void conv7_mma(
    const __half* __restrict__ xh, const __half* __restrict__ wh,
    const float* __restrict__ bias, __half* __restrict__ out)
{
    extern __shared__ __align__(128) char smem[];
    const uint32_t sbase = smem_u32(smem);
    const int tid = threadIdx.x;
    const int wid = tid >> 5, lane = tid & 31;
    const int e0 = blockIdx.x * 128, v0 = blockIdx.y * 128, b = blockIdx.z;
    const int warpm = wid >> 1, warpn = wid & 1;

    const int rowA = tid >> 1, half = (tid & 1) * 32;
    const int vh = (v0 + rowA) >> 6, vw = (v0 + rowA) & 63;
    const uint32_t dstRow = rowA * ROWB + half * 2;

    auto issue = [&](int it) {
        const int tap = it >> 2, kc = (it & 3) * 64;
        const int dy = tap / 7 - 3, dx = tap % 7 - 3;
        const int hh = vh + dy, ww = vw + dx;
        const bool okA = ((unsigned)hh < 64u) && ((unsigned)ww < 64u);
        const uint32_t szA = okA ? 16u : 0u;
        const long aoff = okA ? ((long)b*VV + (hh<<6) + ww)*CIN + kc + half : 0;
        const long boff = ((long)tap*EE + e0 + rowA)*CIN + kc + half;
        const uint32_t stg = sbase + (it & 1) * STAGE_B;
        #pragma unroll
        for (int j = 0; j < 4; j++) {
            CP_ASYNC16(stg + OFF_A + dstRow + j*16, xh + aoff + j*8, szA);
            CP_ASYNC16(stg + OFF_B + dstRow + j*16, wh + boff + j*8, 16u);
        }
        CP_COMMIT();
    };

    float acc[2][8][4];
    #pragma unroll
    for (int mt = 0; mt < 2; mt++)
        #pragma unroll
        for (int nt = 0; nt < 8; nt++)
            #pragma unroll
            for (int q = 0; q < 4; q++) acc[mt][nt][q] = 0.f;

    const uint32_t aLdOff = (warpm*32 + (lane & 15)) * ROWB + (lane >> 4) * 16;
    const uint32_t bLdOff = (warpn*64 + (lane & 7) + ((lane >> 4) & 1) * 8) * ROWB
                          + (((lane >> 3) & 1) * 8) * 2;

    issue(0);

    for (int it = 0; it < NCHUNK; it++) {
        if (it + 1 < NCHUNK) { issue(it + 1); CP_WAIT(1); }
        else                 { CP_WAIT(0); }
        __syncthreads();

        const uint32_t stg = sbase + (it & 1) * STAGE_B;
        #pragma unroll
        for (int k16 = 0; k16 < 4; k16++) {
            const uint32_t kByte = k16 * 32;
            uint32_t ah[2][4];
            #pragma unroll
            for (int mt = 0; mt < 2; mt++) {
                LDSM4(ah[mt], stg + OFF_A + aLdOff + mt * 16 * ROWB + kByte);
            }
            #pragma unroll
            for (int np = 0; np < 4; np++) {
                uint32_t bb[4];
                LDSM4(bb, stg + OFF_B + bLdOff + np * 16 * ROWB + kByte);
                #pragma unroll
                for (int mt = 0; mt < 2; mt++) {
                    MMA16816H(acc[mt][2*np],   ah[mt], bb[0], bb[1]);
                    MMA16816H(acc[mt][2*np+1], ah[mt], bb[2], bb[3]);
                }
            }
        }
        __syncthreads();
    }

    const int r = lane >> 2, c2 = (lane & 3) * 2;
    #pragma unroll
    for (int mt = 0; mt < 2; mt++) {
        #pragma unroll
        for (int nt = 0; nt < 8; nt++) {
            const int v = v0 + warpm*32 + mt*16 + r;
            const int e = e0 + warpn*64 + nt*8 + c2;
            const float bx = bias[e], by = bias[e+1];
            __half* p0 = out + ((long)b*VV + v)*EE + e;
            __half* p1 = p0 + 8L*EE;
            *(__half2*)p0 = __floats2half2_rn(acc[mt][nt][0] + bx, acc[mt][nt][1] + by);
            *(__half2*)p1 = __floats2half2_rn(acc[mt][nt][2] + bx, acc[mt][nt][3] + by);
        }
    }
}

// ======================= HMMA generic NN GEMM ===============================
// C[m][n] = A[m][k] * Bt[n][k]^T, fp16 operands, fp32 accum, K = nk*64.
// MODE 0: +bias -> fp16 C     (phi)
// MODE 1: |acc| -> fp16 C     (H)
// MODE 2: resid - rowScale[m]*acc -> fp16 C   (R)
// MODE 3: +bias -> fp32 C     (out)
template<int MODE>
__global__ __launch_bounds__(256, 2) void hgemm_nn(
    const __half* __restrict__ A, const __half* __restrict__ Bt, void* __restrict__ Cv,
    const float* __restrict__ bias, const float* __restrict__ rowScale,
    const float* __restrict__ resid,
    int K, int N, int nk,
    long aB, long bB, long cB, long rB, long sB)
{
    extern __shared__ __align__(128) char smem[];
    const uint32_t sbase = smem_u32(smem);
    const int tid = threadIdx.x;
    const int wid = tid >> 5, lane = tid & 31;
    const int n0 = blockIdx.x * 128, m0 = blockIdx.y * 128, b = blockIdx.z;
    const int warpm = wid >> 1, warpn = wid & 1;

    const __half* Ab = A + (long)b * aB;
    const __half* Bb = Bt + (long)b * bB;

    const int rowA = tid >> 1, half = (tid & 1) * 32;
    const uint32_t dstRow = rowA * ROWB + half * 2;

    auto issue = [&](int it) {
        const int kc = it * 64;
        const long aoff = (long)(m0 + rowA) * K + kc + half;
        const long boff = (long)(n0 + rowA) * K + kc + half;
        const uint32_t stg = sbase + (it & 1) * STAGE_B;
        #pragma unroll
        for (int j = 0; j < 4; j++) {
            CP_ASYNC16(stg + OFF_A + dstRow + j*16, Ab + aoff + j*8, 16u);
            CP_ASYNC16(stg + OFF_B + dstRow + j*16, Bb + boff + j*8, 16u);
        }
        CP_COMMIT();
    };

    float acc[2][8][4];
    #pragma unroll
    for (int mt = 0; mt < 2; mt++)
        #pragma unroll
        for (int nt = 0; nt < 8; nt++)
            #pragma unroll
            for (int q = 0; q < 4; q++) acc[mt][nt][q] = 0.f;

    const uint32_t aLdOff = (warpm*32 + (lane & 15)) * ROWB + (lane >> 4) * 16;
    const uint32_t bLdOff = (warpn*64 + (lane & 7) + ((lane >> 4) & 1) * 8) * ROWB
                          + (((lane >> 3) & 1) * 8) * 2;

    issue(0);

    for (int it = 0; it < nk; it++) {
        if (it + 1 < nk) { issue(it + 1); CP_WAIT(1); }
        else             { CP_WAIT(0); }
        __syncthreads();

        const uint32_t stg = sbase + (it & 1) * STAGE_B;
        #pragma unroll
        for (int k16 = 0; k16 < 4; k16++) {
            const uint32_t kByte = k16 * 32;
            uint32_t ah[2][4];
            #pragma unroll
            for (int mt = 0; mt < 2; mt++) {
                LDSM4(ah[mt], stg + OFF_A + aLdOff + mt * 16 * ROWB + kByte);
            }
            #pragma unroll
            for (int np = 0; np < 4; np++) {
                uint32_t bb[4];
                LDSM4(bb, stg + OFF_B + bLdOff + np * 16 * ROWB + kByte);
                #pragma unroll
                for (int mt = 0; mt < 2; mt++) {
                    MMA16816H(acc[mt][2*np],   ah[mt], bb[0], bb[1]);
                    MMA16816H(acc[mt][2*np+1], ah[mt], bb[2], bb[3]);
                }
            }
        }
        __syncthreads();
    }

    const int r = lane >> 2, c2 = (lane & 3) * 2;
    #pragma unroll
    for (int mt = 0; mt < 2; mt++) {
        #pragma unroll
        for (int nt = 0; nt < 8; nt++) {
            const int m = m0 + warpm*32 + mt*16 + r;      // rows m and m+8
            const int n = n0 + warpn*64 + nt*8 + c2;
            float c00 = acc[mt][nt][0], c01 = acc[mt][nt][1];
            float c10 = acc[mt][nt][2], c11 = acc[mt][nt][3];
            if (MODE == 0 || MODE == 3) {
                const float bx = bias[n], by = bias[n+1];
                c00 += bx; c01 += by; c10 += bx; c11 += by;
            } else if (MODE == 1) {
                c00 = fabsf(c00); c01 = fabsf(c01);
                c10 = fabsf(c10); c11 = fabsf(c11);
            } else if (MODE == 2) {
                const float d0 = rowScale[b*sB + m];
                const float d1 = rowScale[b*sB + m + 8];
                const float* rp0 = resid + b*rB + (long)m * N + n;
                const float* rp1 = rp0 + 8L*N;
                float2 r0 = *(const float2*)rp0;
                float2 r1 = *(const float2*)rp1;
                c00 = r0.x - d0*c00; c01 = r0.y - d0*c01;
                c10 = r1.x - d1*c10; c11 = r1.y - d1*c11;
            }
            if (MODE == 3) {
                float* cp = (float*)Cv + (long)b*cB + (long)m * N + n;
                *(float2*)cp          = make_float2(c00, c01);
                *(float2*)(cp + 8L*N) = make_float2(c10, c11);
            } else {
                __half* cp = (__half*)Cv + (long)b*cB + (long)m * N + n;
                *(__half2*)cp          = __floats2half2_rn(c00, c01);
                *(__half2*)(cp + 8L*N) = __floats2half2_rn(c10, c11);
            }
        }
    }
}

// ------------------------- FFMA2 helpers ------------------------------------
typedef unsigned long long ull;

__device__ __forceinline__ void ffma2(ull &d, ull a, ull b) {
    asm("fma.rn.f32x2 %0, %1, %2, %0;" : "+l"(d) : "l"(a), "l"(b));
}
__device__ __forceinline__ ull bcast2(float v) {
    ull r;
    asm("mov.b64 %0, {%1, %1};" : "=l"(r) : "f"(v));
    return r;
}
__device__ __forceinline__ float lof(ull v){ return __uint_as_float((unsigned)v); }
__device__ __forceinline__ float hif(ull v){ return __uint_as_float((unsigned)(v>>32)); }

#define INNER_16(As, Bs, acc, tx, ty)                                          \
    _Pragma("unroll")                                                          \
    for (int kk = 0; kk < 16; kk++) {                                          \
        ulonglong2 A0 = *(const ulonglong2*)&As[kk][ty*4];                     \
        ulonglong2 A1 = *(const ulonglong2*)&As[kk][64 + ty*4];                \
        float4 bv0 = *(const float4*)&Bs[kk][tx*4];                            \
        float4 bv1 = *(const float4*)&Bs[kk][64 + tx*4];                       \
        ull bb0 = bcast2(bv0.x), bb1 = bcast2(bv0.y);                          \
        ull bb2 = bcast2(bv0.z), bb3 = bcast2(bv0.w);                          \
        ull bb4 = bcast2(bv1.x), bb5 = bcast2(bv1.y);                          \
        ull bb6 = bcast2(bv1.z), bb7 = bcast2(bv1.w);                          \
        ffma2(acc[0][0], A0.x, bb0); ffma2(acc[0][1], A0.x, bb1);              \
        ffma2(acc[0][2], A0.x, bb2); ffma2(acc[0][3], A0.x, bb3);              \
        ffma2(acc[0][4], A0.x, bb4); ffma2(acc[0][5], A0.x, bb5);              \
        ffma2(acc[0][6], A0.x, bb6); ffma2(acc[0][7], A0.x, bb7);              \
        ffma2(acc[1][0], A0.y, bb0); ffma2(acc[1][1], A0.y, bb1);              \
        ffma2(acc[1][2], A0.y, bb2); ffma2(acc[1][3], A0.y, bb3);              \
        ffma2(acc[1][4], A0.y, bb4); ffma2(acc[1][5], A0.y, bb5);              \
        ffma2(acc[1][6], A0.y, bb6); ffma2(acc[1][7], A0.y, bb7);              \
        ffma2(acc[2][0], A1.x, bb0); ffma2(acc[2][1], A1.x, bb1);              \
        ffma2(acc[2][2], A1.x, bb2); ffma2(acc[2][3], A1.x, bb3);              \
        ffma2(acc[2][4], A1.x, bb4); ffma2(acc[2][5], A1.x, bb5);              \
        ffma2(acc[2][6], A1.x, bb6); ffma2(acc[2][7], A1.x, bb7);              \
        ffma2(acc[3][0], A1.y, bb0); ffma2(acc[3][1], A1.y, bb1);              \
        ffma2(acc[3][2], A1.y, bb2); ffma2(acc[3][3], A1.y, bb3);              \
        ffma2(acc[3][4], A1.y, bb4); ffma2(acc[3][5], A1.y, bb5);              \
        ffma2(acc[3][6], A1.y, bb6); ffma2(acc[3][7], A1.y, bb7);              \
    }

// ---------------------------------------------------------------------------
// 128x128x16 FFMA2 TN GEMM with split-K. A fp16 [Kd, lda]; BHALF: B fp16.
// ---------------------------------------------------------------------------
template<bool BHALF>
__global__ __launch_bounds__(256) void sgemm_tn_v3(
    const __half* __restrict__ A, const void* __restrict__ Bv, float* __restrict__ C,
    int M, int N, int Kd, int lda,
    long aB, long bB, long cB,
    const float* __restrict__ kS, int kSb,
    int split)
{
    __shared__ float As[16][132];
    __shared__ float Bs[16][132];

    const int zb = blockIdx.z;
    const int b = zb / split, s = zb % split;
    const int kchunk = Kd / split;
    const int kbeg = s * kchunk, kend = kbeg + kchunk;

    const __half* Ab = A + (long)b * aB;
    float* Cb = C + (long)zb * cB;

    const int m0 = blockIdx.y * 128, n0 = blockIdx.x * 128;
    const int tid = threadIdx.x, tx = tid & 15, ty = tid >> 4;
    const int lk = tid >> 4, lm = (tid & 15) * 8;

    ull acc[4][8] = {};

    for (int k0 = kbeg; k0 < kend; k0 += 16) {
        float4 a0, a1, b0, b1;
        h8_f8(*(const uint4*)&Ab[(long)(k0 + lk) * lda + m0 + lm], a0, a1);
        if (kS) {
            float sc = kS[b * kSb + k0 + lk];
            a0.x*=sc; a0.y*=sc; a0.z*=sc; a0.w*=sc;
            a1.x*=sc; a1.y*=sc; a1.z*=sc; a1.w*=sc;
        }
        if (BHALF) {
            const __half* bp = (const __half*)Bv + (long)b*bB + (long)(k0 + lk) * N + n0 + lm;
            h8_f8(*(const uint4*)bp, b0, b1);
        } else {
            const float* bp = (const float*)Bv + (long)b*bB + (long)(k0 + lk) * N + n0 + lm;
            b0 = *(const float4*)bp; b1 = *(const float4*)(bp + 4);
        }

        __syncthreads();
        *(float4*)&As[lk][lm]     = a0;
        *(float4*)&As[lk][lm + 4] = a1;
        *(float4*)&Bs[lk][lm]     = b0;
        *(float4*)&Bs[lk][lm + 4] = b1;
        __syncthreads();

        INNER_16(As, Bs, acc, tx, ty)
    }

    #pragma unroll
    for (int p = 0; p < 4; p++) {
        int mbase = m0 + ((p < 2) ? 0 : 64) + ty*4 + (p & 1) * 2;
        #pragma unroll
        for (int h = 0; h < 2; h++) {
            long m = mbase + h;
            float4 c0, c1;
            if (h == 0) {
                c0 = make_float4(lof(acc[p][0]), lof(acc[p][1]), lof(acc[p][2]), lof(acc[p][3]));
                c1 = make_float4(lof(acc[p][4]), lof(acc[p][5]), lof(acc[p][6]), lof(acc[p][7]));
            } else {
                c0 = make_float4(hif(acc[p][0]), hif(acc[p][1]), hif(acc[p][2]), hif(acc[p][3]));
                c1 = make_float4(hif(acc[p][4]), hif(acc[p][5]), hif(acc[p][6]), hif(acc[p][7]));
            }
            *(float4*)&Cb[m * N + n0 + tx*4]      = c0;
            *(float4*)&Cb[m * N + n0 + 64 + tx*4] = c1;
        }
    }
}

__global__ void k_reduce_split(const float* __restrict__ part, float* __restrict__ out,
                               int mn, int batches, int split)
{
    long i = (long)blockIdx.x * 256 + threadIdx.x;
    if (i >= (long)batches * mn) return;
    int b = (int)(i / mn), r = (int)(i % mn);
    float sum = 0.f;
    for (int s = 0; s < split; s++)
        sum += part[((long)(b * split + s)) * mn + r];
    out[i] = sum;
}

// -------------------- small reduction / pointwise kernels -------------------
__global__ void k_xpart(const float* __restrict__ x, float* __restrict__ P)
{
    const int b = blockIdx.x, p = blockIdx.y, c = threadIdx.x;
    const float* base = x + ((long)b * VV + p * 128) * CIN + c;
    float s = 0.f;
    for (int v = 0; v < 128; v++) s += base[(long)v * CIN];
    P[(b * 32 + p) * CIN + c] = s;
}

__global__ void k_xmean(const float* __restrict__ P, float* __restrict__ xm)
{
    const int b = blockIdx.x, c = threadIdx.x;
    float s = 0.f;
    for (int p = 0; p < 32; p++) s += P[(b * 32 + p) * CIN + c];
    xm[b * CIN + c] = s * (1.0f / VV);
}

__global__ void k_a(const float* __restrict__ xmg, const float* __restrict__ wa,
                    const float* __restrict__ ba, float* __restrict__ a)
{
    __shared__ float xm[CIN];
    const int b = blockIdx.x, f = threadIdx.x;
    xm[f] = xmg[b * CIN + f];
    xm[f + 128] = xmg[b * CIN + f + 128];
    __syncthreads();
    float s = ba[f];
    #pragma unroll 8
    for (int c = 0; c < CIN; c++) s += xm[c] * wa[c * FF + f];
    a[b * FF + f] = s;
}

__global__ void k_degD(const __half* __restrict__ H, float* __restrict__ D)
{
    const int row  = blockIdx.x * 8 + (threadIdx.x >> 5);
    const int lane = threadIdx.x & 31;
    if (row >= BB * VV) return;
    const __half2* r = (const __half2*)(H + (long)row * EE);
    float s = 0.f;
    for (int c = lane; c < EE/2; c += 32) {
        float2 f = __half22float2(r[c]);
        s += f.x + f.y;
    }
    for (int o = 16; o; o >>= 1) s += __shfl_xor_sync(0xFFFFFFFFu, s, o);
    if (lane == 0) D[row] = rsqrtf(s);
}

__global__ void k_bpart(const __half* __restrict__ H, float* __restrict__ P)
{
    const int b = blockIdx.x, p = blockIdx.y, e = threadIdx.x;
    const __half* base = H + ((long)b * VV + p * 256) * EE + e;
    float s = 0.f;
    for (int v = 0; v < 256; v++) s += __half2float(base[(long)v * EE]);
    P[(b * 16 + p) * EE + e] = s;
}

__global__ void k_finishBe(const float* __restrict__ P, float* __restrict__ Be)
{
    const int b = blockIdx.x, e = threadIdx.x;
    float s = 0.f;
    for (int p = 0; p < 16; p++) s += P[(b * 16 + p) * EE + e];
    Be[b * EE + e] = 1.0f / s;
}

// ---------------------------------------------------------------------------
extern "C" void kernel_launch(void* const* d_in, const int* in_sizes, int n_in,
                              void* d_out, int out_size)
{
    const float* x   = (const float*)d_in[0];
    const float* wph = (const float*)d_in[1];
    const float* bph = (const float*)d_in[2];
    const float* wa  = (const float*)d_in[3];
    const float* ba  = (const float*)d_in[4];
    const float* wm  = (const float*)d_in[5];
    const float* bm  = (const float*)d_in[6];
    const float* w2  = (const float*)d_in[7];
    const float* b2  = (const float*)d_in[8];
    float* out = (float*)d_out;

    float *tb, *Db, *Beb, *tmpb, *ab, *xp, *xmg, *bp, *p1, *p2;
    __half *xh, *wh, *phi16, *M16, *H16, *R16, *wpht, *at16, *w2t, *btmp;
    cudaGetSymbolAddress((void**)&phi16, g_phi16);
    cudaGetSymbolAddress((void**)&M16,  g_M16);
    cudaGetSymbolAddress((void**)&H16,  g_H16);
    cudaGetSymbolAddress((void**)&R16,  g_R16);
    cudaGetSymbolAddress((void**)&tb,   g_t);
    cudaGetSymbolAddress((void**)&Db,   g_D);
    cudaGetSymbolAddress((void**)&Beb,  g_Be);
    cudaGetSymbolAddress((void**)&tmpb, g_tmp);
    cudaGetSymbolAddress((void**)&ab,   g_a);
    cudaGetSymbolAddress((void**)&xp,   g_xpart);
    cudaGetSymbolAddress((void**)&xmg,  g_xmean);
    cudaGetSymbolAddress((void**)&bp,   g_bpart);
    cudaGetSymbolAddress((void**)&p1,   g_part1);
    cudaGetSymbolAddress((void**)&p2,   g_part2);
    cudaGetSymbolAddress((void**)&xh,   g_xh);
    cudaGetSymbolAddress((void**)&wh,   g_wh);
    cudaGetSymbolAddress((void**)&wpht, g_wpht);
    cudaGetSymbolAddress((void**)&at16, g_at);
    cudaGetSymbolAddress((void**)&w2t,  g_w2t);
    cudaGetSymbolAddress((void**)&btmp, g_btmp);

    const int smem_bytes = 2 * STAGE_B;   // 73728
    cudaFuncSetAttribute(conv7_mma,   cudaFuncAttributeMaxDynamicSharedMemorySize, smem_bytes);
    cudaFuncSetAttribute(hgemm_nn<0>, cudaFuncAttributeMaxDynamicSharedMemorySize, smem_bytes);
    cudaFuncSetAttribute(hgemm_nn<1>, cudaFuncAttributeMaxDynamicSharedMemorySize, smem_bytes);
    cudaFuncSetAttribute(hgemm_nn<2>, cudaFuncAttributeMaxDynamicSharedMemorySize, smem_bytes);
    cudaFuncSetAttribute(hgemm_nn<3>, cudaFuncAttributeMaxDynamicSharedMemorySize, smem_bytes);

    // 0) fp16 conversions
    {
        long nx = (long)BB*VV*CIN;
        k_cvt_x<<<(unsigned)((nx + 255)/256), 256>>>(x, xh);
        long nw = 49L*EE*CIN;
        k_cvt_wt<<<(unsigned)((nw + 255)/256), 256>>>(wm, wh);
        k_cvt_wpht<<<(FF*CIN + 255)/256, 256>>>(wph, wpht);
        k_cvt_w2t<<<(COUT*CIN + 255)/256, 256>>>(w2, w2t);
    }

    // 1) pooled mean + a vector
    k_xpart<<<dim3(BB, 32), 256>>>(x, xp);
    k_xmean<<<BB, 256>>>(xp, xmg);
    k_a<<<BB, 128>>>(xmg, wa, ba, ab);

    // 2) phi = x @ w_phi + b_phi   (HMMA, fp16 out)
    hgemm_nn<0><<<dim3(1, 256, 1), 256, smem_bytes>>>(
        xh, wpht, phi16, bph, nullptr, nullptr,
        CIN, FF, 4, 0, 0, 0, 0, 0);

    // 3) M = conv7x7(x) + b_m  (fp16 out)
    conv7_mma<<<dim3(EE/128, VV/128, BB), 256, smem_bytes>>>(xh, wh, bm, M16);

    // 4) t = phi^T @ M  (split-K, FFMA2)
    sgemm_tn_v3<true><<<dim3(EE/128, FF/128, BB*SPLITK_T), 256>>>(
        phi16, M16, p1, FF, EE, VV, FF,
        (long)VV*FF, (long)VV*EE, (long)FF*EE, nullptr, 0, SPLITK_T);
    k_reduce_split<<<(BB*FF*EE + 255)/256, 256>>>(p1, tb, FF*EE, BB, SPLITK_T);

    // 4b) fold a into t, transpose -> at16 [e][f]
    k_cvt_at<<<(BB*EE*FF + 255)/256, 256>>>(tb, ab, at16);

    // 5) H = | phi @ (diag(a) t) |   (HMMA, fp16 out)
    hgemm_nn<1><<<dim3(2, 32, BB), 256, smem_bytes>>>(
        phi16, at16, H16, nullptr, nullptr, nullptr,
        FF, EE, 2, (long)VV*FF, (long)EE*FF, (long)VV*EE, 0, 0);

    // 6) degrees
    k_degD<<<(BB*VV)/8, 256>>>(H16, Db);
    k_bpart<<<dim3(BB, 16), 256>>>(H16, bp);
    k_finishBe<<<BB, 256>>>(bp, Beb);

    // 7) tmp = (D^-1/2 H)^T @ x  (split-K, FFMA2; D^-1/2 as k-scale)
    sgemm_tn_v3<false><<<dim3(CIN/128, EE/128, BB*SPLITK_P), 256>>>(
        H16, x, p2, EE, CIN, VV, EE,
        (long)VV*EE, (long)VV*CIN, (long)EE*CIN, Db, VV, SPLITK_P);
    k_reduce_split<<<(BB*EE*CIN + 255)/256, 256>>>(p2, tmpb, EE*CIN, BB, SPLITK_P);

    // 7b) fold Binv into tmp, transpose -> btmp [c][e]
    k_cvt_btmp<<<(BB*CIN*EE + 255)/256, 256>>>(tmpb, Beb, btmp);

    // 8) R = x - D^-1/2 * (H @ btmp^T)   (HMMA, fp16 out; D in epilogue)
    hgemm_nn<2><<<dim3(2, 32, BB), 256, smem_bytes>>>(
        H16, btmp, R16, nullptr, Db, x,
        EE, CIN, 4, (long)VV*EE, (long)CIN*EE, (long)VV*CIN, (long)VV*CIN, VV);

    // 9) out = R @ weight_2 + bias_2   (HMMA, fp32 out)
    hgemm_nn<3><<<dim3(2, 256, 1), 256, smem_bytes>>>(
        R16, w2t, out, b2, nullptr, nullptr,
        CIN, COUT, 4, 0, 0, 0, 0, 0);
}

// round 10
// speedup vs baseline: 6.3892x; 1.3834x over previous
#include <cuda_runtime.h>
#include <cuda_fp16.h>
#include <math.h>
#include <stdint.h>

// Problem dims (fixed by the dataset)
#define BB   8
#define HHH  64
#define WWW  64
#define VV   4096      // HHH*WWW
#define CIN  256
#define FF   128
#define EE   256
#define COUT 256
#define SPLITK_P 8     // tmp GEMM split
#define SPLITS2  14    // stage-2 (t) split: 196 chunks / 14
#define LD2  12544     // 49*256, K of stage-2

// ---------------- scratch (static device globals; no allocation allowed) ----
__device__ __half g_phi16[BB*VV*FF];       // [b][v][f]
__device__ __half g_phiT [BB*FF*VV];       // [b][f][v]
__device__ __half g_H16  [BB*VV*EE];
__device__ float  g_Rf   [BB*VV*CIN];      // fp32 R (direct output path)
__device__ float  g_D    [BB*VV];
__device__ float  g_Be   [BB*EE];
__device__ float  g_tmp  [BB*EE*CIN];
__device__ float  g_a    [BB*FF];
__device__ float  g_P    [BB*FF];          // phi column sums
__device__ float  g_xpart[BB*32*CIN];
__device__ float  g_xmean[BB*CIN];
__device__ float  g_bpart[BB*16*EE];
__device__ float  g_part1[SPLITS2*BB*FF*EE];    // 14.7 MB stage-2 partials
__device__ float  g_part2[SPLITK_P*BB*EE*CIN];  // tmp partials
__device__ __half g_xh  [BB*VV*CIN];       // [b][v][c]
__device__ __half g_xT  [BB*CIN*VV];       // [b][c][v]
__device__ __half g_xT7 [7*BB*CIN*VV];     // [dx+3][b][c][v], col-shift masked
__device__ __half g_G   [BB*FF*LD2];       // [b][f][tap*256+c]  (25.7 MB)
__device__ __half g_wte [EE*LD2];          // [e][tap*256+c]
__device__ __half g_wpht[FF*CIN];          // [f][c]
__device__ __half g_at  [BB*EE*FF];        // [b][e][f] = a_f * t_fe
__device__ __half g_btmpH[BB*CIN*EE];      // hi of Binv*tmp, [b][c][e]
__device__ __half g_btmpL[BB*CIN*EE];      // lo

// ======================= PTX helpers ========================================
__device__ __forceinline__ uint32_t smem_u32(const void* p) {
    uint32_t a;
    asm("{ .reg .u64 t; cvta.to.shared.u64 t, %1; cvt.u32.u64 %0, t; }" : "=r"(a) : "l"(p));
    return a;
}
#define CP_ASYNC16(dst, src, sz) \
    asm volatile("cp.async.cg.shared.global [%0], [%1], 16, %2;" \
                 :: "r"(dst), "l"(src), "r"(sz) : "memory")
#define CP_COMMIT() asm volatile("cp.async.commit_group;" ::: "memory")
#define CP_WAIT(n)  asm volatile("cp.async.wait_group %0;" :: "n"(n) : "memory")
#define LDSM4(r, addr) \
    asm volatile("ldmatrix.sync.aligned.m8n8.x4.shared.b16 {%0,%1,%2,%3}, [%4];" \
                 : "=r"((r)[0]), "=r"((r)[1]), "=r"((r)[2]), "=r"((r)[3]) : "r"(addr))
#define MMA16816H(d, a, b0, b1) \
    asm volatile("mma.sync.aligned.m16n8k16.row.col.f32.f16.f16.f32 " \
                 "{%0,%1,%2,%3}, {%4,%5,%6,%7}, {%8,%9}, {%0,%1,%2,%3};" \
                 : "+f"((d)[0]), "+f"((d)[1]), "+f"((d)[2]), "+f"((d)[3]) \
                 : "r"((a)[0]), "r"((a)[1]), "r"((a)[2]), "r"((a)[3]), \
                   "r"(b0), "r"(b1))

// ======================= HMMA tile constants ================================
#define ROWB   144
#define TILE_B (128*ROWB)
#define OFF_A  0
#define OFF_B  (TILE_B)
#define STAGE_B (2*TILE_B)     // 36864
#define OFF_BL (2*TILE_B)
#define STAGE3_B (3*TILE_B)    // 55296 (R-GEMM: A + Bhi + Blo)

// ======================= conversion / transpose kernels =====================
__global__ void k_cvt_x(const float* __restrict__ x, __half* __restrict__ xh)
{
    long i = (long)blockIdx.x * 256 + threadIdx.x;
    if (i >= (long)BB*VV*CIN) return;
    xh[i] = __float2half(x[i]);
}

// x [b][v][c] fp32 -> xT [b][c][v] fp16, 32x32 tiles
__global__ void k_tr_x(const float* __restrict__ x, __half* __restrict__ xT)
{
    __shared__ __half t[32][33];
    const int v0 = blockIdx.x * 32, c0 = blockIdx.y * 32, b = blockIdx.z;
    const int tx = threadIdx.x, ty = threadIdx.y;   // 32 x 8
    #pragma unroll
    for (int j = 0; j < 4; j++) {
        int r = ty + j*8;
        t[r][tx] = __float2half(x[((long)b*VV + v0 + r)*CIN + c0 + tx]);
    }
    __syncthreads();
    #pragma unroll
    for (int j = 0; j < 4; j++) {
        int r = ty + j*8;
        xT[((long)b*CIN + c0 + r)*VV + v0 + tx] = t[tx][r];
    }
}

// phi16 [b][v][f] -> phiT [b][f][v]
__global__ void k_tr_phi(const __half* __restrict__ phi, __half* __restrict__ phiT)
{
    __shared__ __half t[32][33];
    const int v0 = blockIdx.x * 32, f0 = blockIdx.y * 32, b = blockIdx.z;
    const int tx = threadIdx.x, ty = threadIdx.y;
    #pragma unroll
    for (int j = 0; j < 4; j++) {
        int r = ty + j*8;
        t[r][tx] = phi[((long)b*VV + v0 + r)*FF + f0 + tx];
    }
    __syncthreads();
    #pragma unroll
    for (int j = 0; j < 4; j++) {
        int r = ty + j*8;
        phiT[((long)b*FF + f0 + r)*VV + v0 + tx] = t[tx][r];
    }
}

// xT7[dxslot][b][c][u] = (uw+dx in [0,64)) ? xT[b][c][u+dx] : 0
__global__ void k_shift7(const __half* __restrict__ xT, __half* __restrict__ xT7)
{
    const int dxslot = blockIdx.y;
    const int dx = dxslot - 3;
    long base = (long)blockIdx.x * 2048 + threadIdx.x * 8;   // 8 u per thread
    if (base >= (long)BB*CIN*VV) return;
    const int uw0 = (int)(base & 63);
    __half v[8];
    #pragma unroll
    for (int j = 0; j < 8; j++) {
        int uw = uw0 + j;
        v[j] = ((unsigned)(uw + dx) < 64u) ? xT[base + j + dx] : __half(0.f);
    }
    *(uint4*)(xT7 + (long)dxslot*BB*CIN*VV + base) = *(uint4*)v;
}

// wte[e][tap*256+c] = wm[tap][c][e]
__global__ void k_cvt_wte(const float* __restrict__ wm, __half* __restrict__ wte)
{
    long i = (long)blockIdx.x * 256 + threadIdx.x;
    if (i >= (long)EE*LD2) return;
    int e = (int)(i / LD2);
    int k = (int)(i % LD2);
    int tap = k >> 8, c = k & 255;
    wte[i] = __float2half(wm[((long)tap*CIN + c)*EE + e]);
}

__global__ void k_cvt_wpht(const float* __restrict__ wph, __half* __restrict__ wt)
{
    int i = blockIdx.x * 256 + threadIdx.x;
    if (i >= FF*CIN) return;
    int f = i / CIN, c = i % CIN;
    wt[i] = __float2half(wph[c*FF + f]);
}

// P[b][f] = sum_v phiT[b][f][v]
__global__ void k_rowsum_phi(const __half* __restrict__ phiT, float* __restrict__ P)
{
    const int row  = blockIdx.x * 8 + (threadIdx.x >> 5);   // b*FF+f
    const int lane = threadIdx.x & 31;
    if (row >= BB*FF) return;
    const __half2* r = (const __half2*)(phiT + (long)row * VV);
    float s = 0.f;
    for (int c = lane; c < VV/2; c += 32) {
        float2 f = __half22float2(r[c]);
        s += f.x + f.y;
    }
    for (int o = 16; o; o >>= 1) s += __shfl_xor_sync(0xFFFFFFFFu, s, o);
    if (lane == 0) P[row] = s;
}

// at16[b][e][f] = half( a[b][f] * ( sum_s part[(b*14+s)][f][e] + P[b][f]*bm[e] ) )
__global__ void k_at_reduce(const float* __restrict__ part, const float* __restrict__ P,
                            const float* __restrict__ bm, const float* __restrict__ a,
                            __half* __restrict__ at)
{
    int i = blockIdx.x * 256 + threadIdx.x;     // b*EE*FF + e*FF + f
    if (i >= BB*EE*FF) return;
    int b = i / (EE*FF), r = i % (EE*FF);
    int e = r / FF, f = r % FF;
    float s = P[b*FF + f] * bm[e];
    #pragma unroll
    for (int sp = 0; sp < SPLITS2; sp++)
        s += part[((long)(b*SPLITS2 + sp))*FF*EE + f*EE + e];
    at[i] = __float2half(a[b*FF + f] * s);
}

// btmp hi/lo: val = Be[b][e]*tmp[b][e][c] stored [b][c][e]
__global__ void k_cvt_btmp2(const float* __restrict__ tmp, const float* __restrict__ Be,
                            __half* __restrict__ bh, __half* __restrict__ bl)
{
    int i = blockIdx.x * 256 + threadIdx.x;     // b*CIN*EE + c*EE + e
    if (i >= BB*CIN*EE) return;
    int b = i / (CIN*EE), r = i % (CIN*EE);
    int c = r / EE, e = r % EE;
    float v = Be[b*EE + e] * tmp[((long)b*EE + e)*CIN + c];
    __half h = __float2half(v);
    bh[i] = h;
    bl[i] = __float2half(v - __half2float(h));
}

// ======================= HMMA generic NN GEMM (modes 0,1) ===================
// C = A[m][K] * Bt[n][K]^T, fp16, fp32 accum. MODE 0: +bias fp16 C (phi)
// MODE 1: |acc| fp16 C (H)
template<int MODE>
__global__ __launch_bounds__(256, 2) void hgemm_nn(
    const __half* __restrict__ A, const __half* __restrict__ Bt, __half* __restrict__ C,
    const float* __restrict__ bias,
    int K, int N, int nk, long aB, long bB, long cB)
{
    extern __shared__ __align__(128) char smem[];
    const uint32_t sbase = smem_u32(smem);
    const int tid = threadIdx.x;
    const int wid = tid >> 5, lane = tid & 31;
    const int n0 = blockIdx.x * 128, m0 = blockIdx.y * 128, b = blockIdx.z;
    const int warpm = wid >> 1, warpn = wid & 1;

    const __half* Ab = A + (long)b * aB;
    const __half* Bb = Bt + (long)b * bB;

    const int rowA = tid >> 1, half = (tid & 1) * 32;
    const uint32_t dstRow = rowA * ROWB + half * 2;

    auto issue = [&](int it) {
        const int kc = it * 64;
        const long aoff = (long)(m0 + rowA) * K + kc + half;
        const long boff = (long)(n0 + rowA) * K + kc + half;
        const uint32_t stg = sbase + (it & 1) * STAGE_B;
        #pragma unroll
        for (int j = 0; j < 4; j++) {
            CP_ASYNC16(stg + OFF_A + dstRow + j*16, Ab + aoff + j*8, 16u);
            CP_ASYNC16(stg + OFF_B + dstRow + j*16, Bb + boff + j*8, 16u);
        }
        CP_COMMIT();
    };

    float acc[2][8][4];
    #pragma unroll
    for (int mt = 0; mt < 2; mt++)
        #pragma unroll
        for (int nt = 0; nt < 8; nt++)
            #pragma unroll
            for (int q = 0; q < 4; q++) acc[mt][nt][q] = 0.f;

    const uint32_t aLdOff = (warpm*32 + (lane & 15)) * ROWB + (lane >> 4) * 16;
    const uint32_t bLdOff = (warpn*64 + (lane & 7) + ((lane >> 4) & 1) * 8) * ROWB
                          + (((lane >> 3) & 1) * 8) * 2;

    issue(0);

    for (int it = 0; it < nk; it++) {
        if (it + 1 < nk) { issue(it + 1); CP_WAIT(1); }
        else             { CP_WAIT(0); }
        __syncthreads();

        const uint32_t stg = sbase + (it & 1) * STAGE_B;
        #pragma unroll
        for (int k16 = 0; k16 < 4; k16++) {
            const uint32_t kByte = k16 * 32;
            uint32_t ah[2][4];
            #pragma unroll
            for (int mt = 0; mt < 2; mt++)
                LDSM4(ah[mt], stg + OFF_A + aLdOff + mt * 16 * ROWB + kByte);
            #pragma unroll
            for (int np = 0; np < 4; np++) {
                uint32_t bb[4];
                LDSM4(bb, stg + OFF_B + bLdOff + np * 16 * ROWB + kByte);
                #pragma unroll
                for (int mt = 0; mt < 2; mt++) {
                    MMA16816H(acc[mt][2*np],   ah[mt], bb[0], bb[1]);
                    MMA16816H(acc[mt][2*np+1], ah[mt], bb[2], bb[3]);
                }
            }
        }
        __syncthreads();
    }

    const int r = lane >> 2, c2 = (lane & 3) * 2;
    #pragma unroll
    for (int mt = 0; mt < 2; mt++) {
        #pragma unroll
        for (int nt = 0; nt < 8; nt++) {
            const int m = m0 + warpm*32 + mt*16 + r;
            const int n = n0 + warpn*64 + nt*8 + c2;
            float c00 = acc[mt][nt][0], c01 = acc[mt][nt][1];
            float c10 = acc[mt][nt][2], c11 = acc[mt][nt][3];
            if (MODE == 0) {
                const float bx = bias[n], by = bias[n+1];
                c00 += bx; c01 += by; c10 += bx; c11 += by;
            } else {
                c00 = fabsf(c00); c01 = fabsf(c01);
                c10 = fabsf(c10); c11 = fabsf(c11);
            }
            __half* cp = C + (long)b*cB + (long)m * N + n;
            *(__half2*)cp          = __floats2half2_rn(c00, c01);
            *(__half2*)(cp + 8L*N) = __floats2half2_rn(c10, c11);
        }
    }
}

// ======================= G-GEMM: shifted correlations =======================
// G[b][f][tap*256+c] = sum_v phiT[b][f][v] * xT7[dx][b][c][v + dy*64]
// grid: (CIN/128, 49, BB). m-tile = all 128 f. K = 4096, 64 chunks (1 vh each).
__global__ __launch_bounds__(256, 2) void gconv_mma(
    const __half* __restrict__ phiT, const __half* __restrict__ xT7,
    __half* __restrict__ G)
{
    extern __shared__ __align__(128) char smem[];
    const uint32_t sbase = smem_u32(smem);
    const int tid = threadIdx.x;
    const int wid = tid >> 5, lane = tid & 31;
    const int n0 = blockIdx.x * 128, tap = blockIdx.y, b = blockIdx.z;
    const int dy = tap / 7 - 3, dx = tap % 7 - 3;
    const int warpm = wid >> 1, warpn = wid & 1;

    const __half* Ab = phiT + (long)b * FF * VV;
    const __half* Bb = xT7 + ((long)(dx + 3) * BB + b) * CIN * VV;

    const int rowA = tid >> 1, half = (tid & 1) * 32;
    const uint32_t dstRow = rowA * ROWB + half * 2;

    auto issue = [&](int it) {
        const long aoff = (long)rowA * VV + it * 64 + half;
        const int vh2 = it + dy;
        const bool ok = ((unsigned)vh2 < 64u);
        const uint32_t szB = ok ? 16u : 0u;
        const long boff = (long)(n0 + rowA) * VV + (ok ? vh2 : 0) * 64 + half;
        const uint32_t stg = sbase + (it & 1) * STAGE_B;
        #pragma unroll
        for (int j = 0; j < 4; j++) {
            CP_ASYNC16(stg + OFF_A + dstRow + j*16, Ab + aoff + j*8, 16u);
            CP_ASYNC16(stg + OFF_B + dstRow + j*16, Bb + boff + j*8, szB);
        }
        CP_COMMIT();
    };

    float acc[2][8][4];
    #pragma unroll
    for (int mt = 0; mt < 2; mt++)
        #pragma unroll
        for (int nt = 0; nt < 8; nt++)
            #pragma unroll
            for (int q = 0; q < 4; q++) acc[mt][nt][q] = 0.f;

    const uint32_t aLdOff = (warpm*32 + (lane & 15)) * ROWB + (lane >> 4) * 16;
    const uint32_t bLdOff = (warpn*64 + (lane & 7) + ((lane >> 4) & 1) * 8) * ROWB
                          + (((lane >> 3) & 1) * 8) * 2;

    issue(0);

    for (int it = 0; it < 64; it++) {
        if (it + 1 < 64) { issue(it + 1); CP_WAIT(1); }
        else             { CP_WAIT(0); }
        __syncthreads();

        const uint32_t stg = sbase + (it & 1) * STAGE_B;
        #pragma unroll
        for (int k16 = 0; k16 < 4; k16++) {
            const uint32_t kByte = k16 * 32;
            uint32_t ah[2][4];
            #pragma unroll
            for (int mt = 0; mt < 2; mt++)
                LDSM4(ah[mt], stg + OFF_A + aLdOff + mt * 16 * ROWB + kByte);
            #pragma unroll
            for (int np = 0; np < 4; np++) {
                uint32_t bb[4];
                LDSM4(bb, stg + OFF_B + bLdOff + np * 16 * ROWB + kByte);
                #pragma unroll
                for (int mt = 0; mt < 2; mt++) {
                    MMA16816H(acc[mt][2*np],   ah[mt], bb[0], bb[1]);
                    MMA16816H(acc[mt][2*np+1], ah[mt], bb[2], bb[3]);
                }
            }
        }
        __syncthreads();
    }

    const int r = lane >> 2, c2 = (lane & 3) * 2;
    __half* Gb = G + (long)b * FF * LD2 + tap * 256;
    #pragma unroll
    for (int mt = 0; mt < 2; mt++) {
        #pragma unroll
        for (int nt = 0; nt < 8; nt++) {
            const int m = warpm*32 + mt*16 + r;
            const int n = n0 + warpn*64 + nt*8 + c2;
            __half* cp = Gb + (long)m * LD2 + n;
            *(__half2*)cp            = __floats2half2_rn(acc[mt][nt][0], acc[mt][nt][1]);
            *(__half2*)(cp + 8L*LD2) = __floats2half2_rn(acc[mt][nt][2], acc[mt][nt][3]);
        }
    }
}

// ======================= stage-2: t partials (split-K) ======================
// part[b*14+s][f][e] = sum_{k in slice} G[b][f][k] * wte[e][k]
__global__ __launch_bounds__(256, 2) void hgemm_s2(
    const __half* __restrict__ G, const __half* __restrict__ wte,
    float* __restrict__ part)
{
    extern __shared__ __align__(128) char smem[];
    const uint32_t sbase = smem_u32(smem);
    const int tid = threadIdx.x;
    const int wid = tid >> 5, lane = tid & 31;
    const int n0 = blockIdx.x * 128, zb = blockIdx.z;
    const int b = zb / SPLITS2, s = zb % SPLITS2;
    const int kbeg = s * 14;                         // chunks of 64, 14 per split
    const int warpm = wid >> 1, warpn = wid & 1;

    const __half* Ab = G + (long)b * FF * LD2;

    const int rowA = tid >> 1, half = (tid & 1) * 32;
    const uint32_t dstRow = rowA * ROWB + half * 2;

    auto issue = [&](int it) {
        const int kc = (kbeg + it) * 64;
        const long aoff = (long)rowA * LD2 + kc + half;
        const long boff = (long)(n0 + rowA) * LD2 + kc + half;
        const uint32_t stg = sbase + (it & 1) * STAGE_B;
        #pragma unroll
        for (int j = 0; j < 4; j++) {
            CP_ASYNC16(stg + OFF_A + dstRow + j*16, Ab + aoff + j*8, 16u);
            CP_ASYNC16(stg + OFF_B + dstRow + j*16, wte + boff + j*8, 16u);
        }
        CP_COMMIT();
    };

    float acc[2][8][4];
    #pragma unroll
    for (int mt = 0; mt < 2; mt++)
        #pragma unroll
        for (int nt = 0; nt < 8; nt++)
            #pragma unroll
            for (int q = 0; q < 4; q++) acc[mt][nt][q] = 0.f;

    const uint32_t aLdOff = (warpm*32 + (lane & 15)) * ROWB + (lane >> 4) * 16;
    const uint32_t bLdOff = (warpn*64 + (lane & 7) + ((lane >> 4) & 1) * 8) * ROWB
                          + (((lane >> 3) & 1) * 8) * 2;

    issue(0);

    for (int it = 0; it < 14; it++) {
        if (it + 1 < 14) { issue(it + 1); CP_WAIT(1); }
        else             { CP_WAIT(0); }
        __syncthreads();

        const uint32_t stg = sbase + (it & 1) * STAGE_B;
        #pragma unroll
        for (int k16 = 0; k16 < 4; k16++) {
            const uint32_t kByte = k16 * 32;
            uint32_t ah[2][4];
            #pragma unroll
            for (int mt = 0; mt < 2; mt++)
                LDSM4(ah[mt], stg + OFF_A + aLdOff + mt * 16 * ROWB + kByte);
            #pragma unroll
            for (int np = 0; np < 4; np++) {
                uint32_t bb[4];
                LDSM4(bb, stg + OFF_B + bLdOff + np * 16 * ROWB + kByte);
                #pragma unroll
                for (int mt = 0; mt < 2; mt++) {
                    MMA16816H(acc[mt][2*np],   ah[mt], bb[0], bb[1]);
                    MMA16816H(acc[mt][2*np+1], ah[mt], bb[2], bb[3]);
                }
            }
        }
        __syncthreads();
    }

    const int r = lane >> 2, c2 = (lane & 3) * 2;
    float* Cb = part + (long)zb * FF * EE;
    #pragma unroll
    for (int mt = 0; mt < 2; mt++) {
        #pragma unroll
        for (int nt = 0; nt < 8; nt++) {
            const int m = warpm*32 + mt*16 + r;
            const int n = n0 + warpn*64 + nt*8 + c2;
            float* cp = Cb + (long)m * EE + n;
            *(float2*)cp           = make_float2(acc[mt][nt][0], acc[mt][nt][1]);
            *(float2*)(cp + 8L*EE) = make_float2(acc[mt][nt][2], acc[mt][nt][3]);
        }
    }
}

// ======================= R-GEMM: 2-product (btmp hi/lo) =====================
// R[b][v][c] = x - D[v] * sum_e H[v][e]*(btmpH+btmpL)[c][e], fp32 out.
__global__ __launch_bounds__(256, 2) void hgemm_rgemm(
    const __half* __restrict__ H, const __half* __restrict__ BH,
    const __half* __restrict__ BL, const float* __restrict__ D,
    const float* __restrict__ x, float* __restrict__ R)
{
    extern __shared__ __align__(128) char smem[];
    const uint32_t sbase = smem_u32(smem);
    const int tid = threadIdx.x;
    const int wid = tid >> 5, lane = tid & 31;
    const int n0 = blockIdx.x * 128, m0 = blockIdx.y * 128, b = blockIdx.z;
    const int warpm = wid >> 1, warpn = wid & 1;

    const __half* Ab = H + (long)b * VV * EE;
    const __half* BHb = BH + (long)b * CIN * EE;
    const __half* BLb = BL + (long)b * CIN * EE;

    const int rowA = tid >> 1, half = (tid & 1) * 32;
    const uint32_t dstRow = rowA * ROWB + half * 2;

    auto issue = [&](int it) {
        const int kc = it * 64;
        const long aoff = (long)(m0 + rowA) * EE + kc + half;
        const long boff = (long)(n0 + rowA) * EE + kc + half;
        const uint32_t stg = sbase + (it & 1) * STAGE3_B;
        #pragma unroll
        for (int j = 0; j < 4; j++) {
            CP_ASYNC16(stg + OFF_A  + dstRow + j*16, Ab  + aoff + j*8, 16u);
            CP_ASYNC16(stg + OFF_B  + dstRow + j*16, BHb + boff + j*8, 16u);
            CP_ASYNC16(stg + OFF_BL + dstRow + j*16, BLb + boff + j*8, 16u);
        }
        CP_COMMIT();
    };

    float acc[2][8][4];
    #pragma unroll
    for (int mt = 0; mt < 2; mt++)
        #pragma unroll
        for (int nt = 0; nt < 8; nt++)
            #pragma unroll
            for (int q = 0; q < 4; q++) acc[mt][nt][q] = 0.f;

    const uint32_t aLdOff = (warpm*32 + (lane & 15)) * ROWB + (lane >> 4) * 16;
    const uint32_t bLdOff = (warpn*64 + (lane & 7) + ((lane >> 4) & 1) * 8) * ROWB
                          + (((lane >> 3) & 1) * 8) * 2;

    issue(0);

    for (int it = 0; it < 4; it++) {          // K = EE = 256
        if (it + 1 < 4) { issue(it + 1); CP_WAIT(1); }
        else            { CP_WAIT(0); }
        __syncthreads();

        const uint32_t stg = sbase + (it & 1) * STAGE3_B;
        #pragma unroll
        for (int k16 = 0; k16 < 4; k16++) {
            const uint32_t kByte = k16 * 32;
            uint32_t ah[2][4];
            #pragma unroll
            for (int mt = 0; mt < 2; mt++)
                LDSM4(ah[mt], stg + OFF_A + aLdOff + mt * 16 * ROWB + kByte);
            #pragma unroll
            for (int np = 0; np < 4; np++) {
                uint32_t bh[4], bl[4];
                LDSM4(bh, stg + OFF_B  + bLdOff + np * 16 * ROWB + kByte);
                LDSM4(bl, stg + OFF_BL + bLdOff + np * 16 * ROWB + kByte);
                #pragma unroll
                for (int mt = 0; mt < 2; mt++) {
                    MMA16816H(acc[mt][2*np],   ah[mt], bh[0], bh[1]);
                    MMA16816H(acc[mt][2*np+1], ah[mt], bh[2], bh[3]);
                    MMA16816H(acc[mt][2*np],   ah[mt], bl[0], bl[1]);
                    MMA16816H(acc[mt][2*np+1], ah[mt], bl[2], bl[3]);
                }
            }
        }
        __syncthreads();
    }

    const int r = lane >> 2, c2 = (lane & 3) * 2;
    #pragma unroll
    for (int mt = 0; mt < 2; mt++) {
        #pragma unroll
        for (int nt = 0; nt < 8; nt++) {
            const int m = m0 + warpm*32 + mt*16 + r;
            const int n = n0 + warpn*64 + nt*8 + c2;
            const float d0 = D[b*VV + m], d1 = D[b*VV + m + 8];
            const float* xp0 = x + (long)b*VV*CIN + (long)m * CIN + n;
            float2 x0 = *(const float2*)xp0;
            float2 x1 = *(const float2*)(xp0 + 8L*CIN);
            float* cp = R + (long)b*VV*CIN + (long)m * CIN + n;
            *(float2*)cp            = make_float2(x0.x - d0*acc[mt][nt][0], x0.y - d0*acc[mt][nt][1]);
            *(float2*)(cp + 8L*CIN) = make_float2(x1.x - d1*acc[mt][nt][2], x1.y - d1*acc[mt][nt][3]);
        }
    }
}

// ------------------------- FFMA2 helpers ------------------------------------
typedef unsigned long long ull;

__device__ __forceinline__ void ffma2(ull &d, ull a, ull b) {
    asm("fma.rn.f32x2 %0, %1, %2, %0;" : "+l"(d) : "l"(a), "l"(b));
}
__device__ __forceinline__ ull bcast2(float v) {
    ull r;
    asm("mov.b64 %0, {%1, %1};" : "=l"(r) : "f"(v));
    return r;
}
__device__ __forceinline__ float lof(ull v){ return __uint_as_float((unsigned)v); }
__device__ __forceinline__ float hif(ull v){ return __uint_as_float((unsigned)(v>>32)); }
__device__ __forceinline__ void h8_f8(uint4 v, float4 &lo, float4 &hi) {
    const __half2* h = (const __half2*)&v;
    float2 f0 = __half22float2(h[0]), f1 = __half22float2(h[1]);
    float2 f2 = __half22float2(h[2]), f3 = __half22float2(h[3]);
    lo = make_float4(f0.x, f0.y, f1.x, f1.y);
    hi = make_float4(f2.x, f2.y, f3.x, f3.y);
}

#define INNER_16(As, Bs, acc, tx, ty)                                          \
    _Pragma("unroll")                                                          \
    for (int kk = 0; kk < 16; kk++) {                                          \
        ulonglong2 A0 = *(const ulonglong2*)&As[kk][ty*4];                     \
        ulonglong2 A1 = *(const ulonglong2*)&As[kk][64 + ty*4];                \
        float4 bv0 = *(const float4*)&Bs[kk][tx*4];                            \
        float4 bv1 = *(const float4*)&Bs[kk][64 + tx*4];                       \
        ull bb0 = bcast2(bv0.x), bb1 = bcast2(bv0.y);                          \
        ull bb2 = bcast2(bv0.z), bb3 = bcast2(bv0.w);                          \
        ull bb4 = bcast2(bv1.x), bb5 = bcast2(bv1.y);                          \
        ull bb6 = bcast2(bv1.z), bb7 = bcast2(bv1.w);                          \
        ffma2(acc[0][0], A0.x, bb0); ffma2(acc[0][1], A0.x, bb1);              \
        ffma2(acc[0][2], A0.x, bb2); ffma2(acc[0][3], A0.x, bb3);              \
        ffma2(acc[0][4], A0.x, bb4); ffma2(acc[0][5], A0.x, bb5);              \
        ffma2(acc[0][6], A0.x, bb6); ffma2(acc[0][7], A0.x, bb7);              \
        ffma2(acc[1][0], A0.y, bb0); ffma2(acc[1][1], A0.y, bb1);              \
        ffma2(acc[1][2], A0.y, bb2); ffma2(acc[1][3], A0.y, bb3);              \
        ffma2(acc[1][4], A0.y, bb4); ffma2(acc[1][5], A0.y, bb5);              \
        ffma2(acc[1][6], A0.y, bb6); ffma2(acc[1][7], A0.y, bb7);              \
        ffma2(acc[2][0], A1.x, bb0); ffma2(acc[2][1], A1.x, bb1);              \
        ffma2(acc[2][2], A1.x, bb2); ffma2(acc[2][3], A1.x, bb3);              \
        ffma2(acc[2][4], A1.x, bb4); ffma2(acc[2][5], A1.x, bb5);              \
        ffma2(acc[2][6], A1.x, bb6); ffma2(acc[2][7], A1.x, bb7);              \
        ffma2(acc[3][0], A1.y, bb0); ffma2(acc[3][1], A1.y, bb1);              \
        ffma2(acc[3][2], A1.y, bb2); ffma2(acc[3][3], A1.y, bb3);              \
        ffma2(acc[3][4], A1.y, bb4); ffma2(acc[3][5], A1.y, bb5);              \
        ffma2(acc[3][6], A1.y, bb6); ffma2(acc[3][7], A1.y, bb7);              \
    }

// ---------------------------------------------------------------------------
// 128x128x16 FFMA2 TN GEMM with split-K. A fp16 [Kd, lda]; B fp32.
// (tmp = (D^-1/2 H)^T @ x)
// ---------------------------------------------------------------------------
__global__ __launch_bounds__(256) void sgemm_tn_f(
    const __half* __restrict__ A, const float* __restrict__ Bv, float* __restrict__ C,
    int N, int Kd, int lda,
    long aB, long bB, long cB,
    const float* __restrict__ kS, int kSb, int split)
{
    __shared__ float As[16][132];
    __shared__ float Bs[16][132];

    const int zb = blockIdx.z;
    const int b = zb / split, s = zb % split;
    const int kchunk = Kd / split;
    const int kbeg = s * kchunk, kend = kbeg + kchunk;

    const __half* Ab = A + (long)b * aB;
    float* Cb = C + (long)zb * cB;

    const int m0 = blockIdx.y * 128, n0 = blockIdx.x * 128;
    const int tid = threadIdx.x, tx = tid & 15, ty = tid >> 4;
    const int lk = tid >> 4, lm = (tid & 15) * 8;

    ull acc[4][8] = {};

    for (int k0 = kbeg; k0 < kend; k0 += 16) {
        float4 a0, a1;
        h8_f8(*(const uint4*)&Ab[(long)(k0 + lk) * lda + m0 + lm], a0, a1);
        float sc = kS[b * kSb + k0 + lk];
        a0.x*=sc; a0.y*=sc; a0.z*=sc; a0.w*=sc;
        a1.x*=sc; a1.y*=sc; a1.z*=sc; a1.w*=sc;
        const float* bp = Bv + (long)b*bB + (long)(k0 + lk) * N + n0 + lm;
        float4 b0 = *(const float4*)bp;
        float4 b1 = *(const float4*)(bp + 4);

        __syncthreads();
        *(float4*)&As[lk][lm]     = a0;
        *(float4*)&As[lk][lm + 4] = a1;
        *(float4*)&Bs[lk][lm]     = b0;
        *(float4*)&Bs[lk][lm + 4] = b1;
        __syncthreads();

        INNER_16(As, Bs, acc, tx, ty)
    }

    #pragma unroll
    for (int p = 0; p < 4; p++) {
        int mbase = m0 + ((p < 2) ? 0 : 64) + ty*4 + (p & 1) * 2;
        #pragma unroll
        for (int h = 0; h < 2; h++) {
            long m = mbase + h;
            float4 c0, c1;
            if (h == 0) {
                c0 = make_float4(lof(acc[p][0]), lof(acc[p][1]), lof(acc[p][2]), lof(acc[p][3]));
                c1 = make_float4(lof(acc[p][4]), lof(acc[p][5]), lof(acc[p][6]), lof(acc[p][7]));
            } else {
                c0 = make_float4(hif(acc[p][0]), hif(acc[p][1]), hif(acc[p][2]), hif(acc[p][3]));
                c1 = make_float4(hif(acc[p][4]), hif(acc[p][5]), hif(acc[p][6]), hif(acc[p][7]));
            }
            *(float4*)&Cb[m * N + n0 + tx*4]      = c0;
            *(float4*)&Cb[m * N + n0 + 64 + tx*4] = c1;
        }
    }
}

// ---------------------------------------------------------------------------
// 128x128x16 FFMA2 NN GEMM fp32 (out = R @ w2 + b2)
// ---------------------------------------------------------------------------
__global__ __launch_bounds__(256) void sgemm_out(
    const float* __restrict__ A, const float* __restrict__ Bm, float* __restrict__ C,
    const float* __restrict__ bias, int K, int N)
{
    __shared__ float As[16][132];
    __shared__ float Bs[16][132];

    const int m0 = blockIdx.y * 128, n0 = blockIdx.x * 128;
    const int tid = threadIdx.x;
    const int tx = tid & 15, ty = tid >> 4;
    const int lr  = tid >> 1, lkh = (tid & 1) * 8;
    const int bk  = tid >> 4, bn  = (tid & 15) * 4;

    ull acc[4][8] = {};
    const int nk = K / 16;

    float4 ra0, ra1, rb0, rb1;
    {
        const float* ap = &A[(long)(m0 + lr) * K + lkh];
        ra0 = *(const float4*)ap; ra1 = *(const float4*)(ap + 4);
        const float* bp = &Bm[(long)bk * N + n0];
        rb0 = *(const float4*)(bp + bn); rb1 = *(const float4*)(bp + 64 + bn);
    }

    for (int c = 0; c < nk; c++) {
        __syncthreads();
        As[lkh+0][lr] = ra0.x; As[lkh+1][lr] = ra0.y;
        As[lkh+2][lr] = ra0.z; As[lkh+3][lr] = ra0.w;
        As[lkh+4][lr] = ra1.x; As[lkh+5][lr] = ra1.y;
        As[lkh+6][lr] = ra1.z; As[lkh+7][lr] = ra1.w;
        *(float4*)&Bs[bk][bn]      = rb0;
        *(float4*)&Bs[bk][64 + bn] = rb1;
        __syncthreads();

        if (c + 1 < nk) {
            int k0 = (c + 1) * 16;
            const float* ap = &A[(long)(m0 + lr) * K + k0 + lkh];
            ra0 = *(const float4*)ap; ra1 = *(const float4*)(ap + 4);
            const float* bp = &Bm[(long)(k0 + bk) * N + n0];
            rb0 = *(const float4*)(bp + bn); rb1 = *(const float4*)(bp + 64 + bn);
        }

        INNER_16(As, Bs, acc, tx, ty)
    }

    float4 biasA = *(const float4*)&bias[n0 + tx*4];
    float4 biasB = *(const float4*)&bias[n0 + 64 + tx*4];

    #pragma unroll
    for (int p = 0; p < 4; p++) {
        int mbase = m0 + ((p < 2) ? 0 : 64) + ty*4 + (p & 1) * 2;
        #pragma unroll
        for (int h = 0; h < 2; h++) {
            long m = mbase + h;
            float4 c0, c1;
            if (h == 0) {
                c0 = make_float4(lof(acc[p][0]), lof(acc[p][1]), lof(acc[p][2]), lof(acc[p][3]));
                c1 = make_float4(lof(acc[p][4]), lof(acc[p][5]), lof(acc[p][6]), lof(acc[p][7]));
            } else {
                c0 = make_float4(hif(acc[p][0]), hif(acc[p][1]), hif(acc[p][2]), hif(acc[p][3]));
                c1 = make_float4(hif(acc[p][4]), hif(acc[p][5]), hif(acc[p][6]), hif(acc[p][7]));
            }
            c0.x += biasA.x; c0.y += biasA.y; c0.z += biasA.z; c0.w += biasA.w;
            c1.x += biasB.x; c1.y += biasB.y; c1.z += biasB.z; c1.w += biasB.w;
            *(float4*)&C[m * N + n0 + tx*4]      = c0;
            *(float4*)&C[m * N + n0 + 64 + tx*4] = c1;
        }
    }
}

__global__ void k_reduce_split(const float* __restrict__ part, float* __restrict__ out,
                               int mn, int batches, int split)
{
    long i = (long)blockIdx.x * 256 + threadIdx.x;
    if (i >= (long)batches * mn) return;
    int b = (int)(i / mn), r = (int)(i % mn);
    float sum = 0.f;
    for (int s = 0; s < split; s++)
        sum += part[((long)(b * split + s)) * mn + r];
    out[i] = sum;
}

// -------------------- small reduction / pointwise kernels -------------------
__global__ void k_xpart(const float* __restrict__ x, float* __restrict__ P)
{
    const int b = blockIdx.x, p = blockIdx.y, c = threadIdx.x;
    const float* base = x + ((long)b * VV + p * 128) * CIN + c;
    float s = 0.f;
    for (int v = 0; v < 128; v++) s += base[(long)v * CIN];
    P[(b * 32 + p) * CIN + c] = s;
}

__global__ void k_xmean(const float* __restrict__ P, float* __restrict__ xm)
{
    const int b = blockIdx.x, c = threadIdx.x;
    float s = 0.f;
    for (int p = 0; p < 32; p++) s += P[(b * 32 + p) * CIN + c];
    xm[b * CIN + c] = s * (1.0f / VV);
}

__global__ void k_a(const float* __restrict__ xmg, const float* __restrict__ wa,
                    const float* __restrict__ ba, float* __restrict__ a)
{
    __shared__ float xm[CIN];
    const int b = blockIdx.x, f = threadIdx.x;
    xm[f] = xmg[b * CIN + f];
    xm[f + 128] = xmg[b * CIN + f + 128];
    __syncthreads();
    float s = ba[f];
    #pragma unroll 8
    for (int c = 0; c < CIN; c++) s += xm[c] * wa[c * FF + f];
    a[b * FF + f] = s;
}

__global__ void k_degD(const __half* __restrict__ H, float* __restrict__ D)
{
    const int row  = blockIdx.x * 8 + (threadIdx.x >> 5);
    const int lane = threadIdx.x & 31;
    if (row >= BB * VV) return;
    const __half2* r = (const __half2*)(H + (long)row * EE);
    float s = 0.f;
    for (int c = lane; c < EE/2; c += 32) {
        float2 f = __half22float2(r[c]);
        s += f.x + f.y;
    }
    for (int o = 16; o; o >>= 1) s += __shfl_xor_sync(0xFFFFFFFFu, s, o);
    if (lane == 0) D[row] = rsqrtf(s);
}

__global__ void k_bpart(const __half* __restrict__ H, float* __restrict__ P)
{
    const int b = blockIdx.x, p = blockIdx.y, e = threadIdx.x;
    const __half* base = H + ((long)b * VV + p * 256) * EE + e;
    float s = 0.f;
    for (int v = 0; v < 256; v++) s += __half2float(base[(long)v * EE]);
    P[(b * 16 + p) * EE + e] = s;
}

__global__ void k_finishBe(const float* __restrict__ P, float* __restrict__ Be)
{
    const int b = blockIdx.x, e = threadIdx.x;
    float s = 0.f;
    for (int p = 0; p < 16; p++) s += P[(b * 16 + p) * EE + e];
    Be[b * EE + e] = 1.0f / s;
}

// ---------------------------------------------------------------------------
extern "C" void kernel_launch(void* const* d_in, const int* in_sizes, int n_in,
                              void* d_out, int out_size)
{
    const float* x   = (const float*)d_in[0];
    const float* wph = (const float*)d_in[1];
    const float* bph = (const float*)d_in[2];
    const float* wa  = (const float*)d_in[3];
    const float* ba  = (const float*)d_in[4];
    const float* wm  = (const float*)d_in[5];
    const float* bm  = (const float*)d_in[6];
    const float* w2  = (const float*)d_in[7];
    const float* b2  = (const float*)d_in[8];
    float* out = (float*)d_out;

    float *Db, *Beb, *tmpb, *ab, *Pb, *xp, *xmg, *bp, *p1, *p2, *Rf;
    __half *xh, *xT, *xT7, *phi16, *phiT, *H16, *G, *wte, *wpht, *at16, *btH, *btL;
    cudaGetSymbolAddress((void**)&phi16, g_phi16);
    cudaGetSymbolAddress((void**)&phiT, g_phiT);
    cudaGetSymbolAddress((void**)&H16,  g_H16);
    cudaGetSymbolAddress((void**)&Rf,   g_Rf);
    cudaGetSymbolAddress((void**)&Db,   g_D);
    cudaGetSymbolAddress((void**)&Beb,  g_Be);
    cudaGetSymbolAddress((void**)&tmpb, g_tmp);
    cudaGetSymbolAddress((void**)&ab,   g_a);
    cudaGetSymbolAddress((void**)&Pb,   g_P);
    cudaGetSymbolAddress((void**)&xp,   g_xpart);
    cudaGetSymbolAddress((void**)&xmg,  g_xmean);
    cudaGetSymbolAddress((void**)&bp,   g_bpart);
    cudaGetSymbolAddress((void**)&p1,   g_part1);
    cudaGetSymbolAddress((void**)&p2,   g_part2);
    cudaGetSymbolAddress((void**)&xh,   g_xh);
    cudaGetSymbolAddress((void**)&xT,   g_xT);
    cudaGetSymbolAddress((void**)&xT7,  g_xT7);
    cudaGetSymbolAddress((void**)&G,    g_G);
    cudaGetSymbolAddress((void**)&wte,  g_wte);
    cudaGetSymbolAddress((void**)&wpht, g_wpht);
    cudaGetSymbolAddress((void**)&at16, g_at);
    cudaGetSymbolAddress((void**)&btH,  g_btmpH);
    cudaGetSymbolAddress((void**)&btL,  g_btmpL);

    cudaFuncSetAttribute(hgemm_nn<0>, cudaFuncAttributeMaxDynamicSharedMemorySize, STAGE_B*2);
    cudaFuncSetAttribute(hgemm_nn<1>, cudaFuncAttributeMaxDynamicSharedMemorySize, STAGE_B*2);
    cudaFuncSetAttribute(gconv_mma,   cudaFuncAttributeMaxDynamicSharedMemorySize, STAGE_B*2);
    cudaFuncSetAttribute(hgemm_s2,    cudaFuncAttributeMaxDynamicSharedMemorySize, STAGE_B*2);
    cudaFuncSetAttribute(hgemm_rgemm, cudaFuncAttributeMaxDynamicSharedMemorySize, STAGE3_B*2);

    // 0) conversions / transposes / shifted copies
    {
        long nx = (long)BB*VV*CIN;
        k_cvt_x<<<(unsigned)((nx + 255)/256), 256>>>(x, xh);
        k_tr_x<<<dim3(VV/32, CIN/32, BB), dim3(32, 8)>>>(x, xT);
        k_shift7<<<dim3((unsigned)((nx + 2047)/2048), 7), 256>>>(xT, xT7);
        k_cvt_wte<<<(unsigned)(((long)EE*LD2 + 255)/256), 256>>>(wm, wte);
        k_cvt_wpht<<<(FF*CIN + 255)/256, 256>>>(wph, wpht);
    }

    // 1) pooled mean + a vector
    k_xpart<<<dim3(BB, 32), 256>>>(x, xp);
    k_xmean<<<BB, 256>>>(xp, xmg);
    k_a<<<BB, 128>>>(xmg, wa, ba, ab);

    // 2) phi = x @ w_phi + b_phi  (HMMA), then transpose + column sums
    hgemm_nn<0><<<dim3(1, 256, 1), 256, STAGE_B*2>>>(
        xh, wpht, phi16, bph, CIN, FF, 4, 0, 0, 0);
    k_tr_phi<<<dim3(VV/32, FF/32, BB), dim3(32, 8)>>>(phi16, phiT);
    k_rowsum_phi<<<BB*FF/8, 256>>>(phiT, Pb);

    // 3) G = 49 shifted correlations phi^T (x) x    (replaces conv + M)
    gconv_mma<<<dim3(CIN/128, 49, BB), 256, STAGE_B*2>>>(phiT, xT7, G);

    // 4) t = G @ w (+ rank-1 bias), split-K, fold a, transpose -> at16
    hgemm_s2<<<dim3(EE/128, 1, BB*SPLITS2), 256, STAGE_B*2>>>(G, wte, p1);
    k_at_reduce<<<(BB*EE*FF + 255)/256, 256>>>(p1, Pb, bm, ab, at16);

    // 5) H = | phi @ (diag(a) t) |
    hgemm_nn<1><<<dim3(2, 32, BB), 256, STAGE_B*2>>>(
        phi16, at16, H16, nullptr, FF, EE, 2,
        (long)VV*FF, (long)EE*FF, (long)VV*EE);

    // 6) degrees
    k_degD<<<(BB*VV)/8, 256>>>(H16, Db);
    k_bpart<<<dim3(BB, 16), 256>>>(H16, bp);
    k_finishBe<<<BB, 256>>>(bp, Beb);

    // 7) tmp = (D^-1/2 H)^T @ x  (split-K FFMA2), then Binv fold hi/lo
    sgemm_tn_f<<<dim3(CIN/128, EE/128, BB*SPLITK_P), 256>>>(
        H16, x, p2, CIN, VV, EE,
        (long)VV*EE, (long)VV*CIN, (long)EE*CIN, Db, VV, SPLITK_P);
    k_reduce_split<<<(BB*EE*CIN + 255)/256, 256>>>(p2, tmpb, EE*CIN, BB, SPLITK_P);
    k_cvt_btmp2<<<(BB*CIN*EE + 255)/256, 256>>>(tmpb, Beb, btH, btL);

    // 8) R = x - D^-1/2 * (H @ (btmpH+btmpL)^T)   fp32 out, 2-product HMMA
    hgemm_rgemm<<<dim3(2, 32, BB), 256, STAGE3_B*2>>>(H16, btH, btL, Db, x, Rf);

    // 9) out = R @ weight_2 + bias_2   (exact FFMA2 fp32)
    sgemm_out<<<dim3(COUT/128, (BB*VV)/128, 1), 256>>>(Rf, w2, out, b2, CIN, COUT);
}

// round 12
// speedup vs baseline: 7.3844x; 1.1558x over previous
#include <cuda_runtime.h>
#include <cuda_fp16.h>
#include <math.h>
#include <stdint.h>

// Problem dims (fixed by the dataset)
#define BB   8
#define HHH  64
#define WWW  64
#define VV   4096      // HHH*WWW
#define CIN  256
#define FF   128
#define EE   256
#define COUT 256
#define SPLITK_P 8     // tmp GEMM split
#define SPLITS2  14    // stage-2 (t) split: 196 chunks / 14
#define LD2  12544     // 49*256, K of stage-2

// ---------------- scratch (static device globals; no allocation allowed) ----
__device__ __half g_phi16[BB*VV*FF];       // [b][v][f]
__device__ __half g_phiT [BB*FF*VV];       // [b][f][v]
__device__ __half g_H16  [BB*VV*EE];       // [b][v][e]
__device__ __half g_HDT  [BB*EE*VV];       // [b][e][v] = D[v]*H[v][e]
__device__ __half g_Rh   [BB*VV*CIN];      // R hi
__device__ __half g_Rl   [BB*VV*CIN];      // R lo
__device__ float  g_D    [BB*VV];
__device__ float  g_Be   [BB*EE];
__device__ float  g_a    [BB*FF];
__device__ float  g_P    [BB*FF];          // phi column sums
__device__ float  g_xpart[BB*32*CIN];
__device__ float  g_xmean[BB*CIN];
__device__ float  g_bpart[BB*16*EE];
__device__ float  g_part1[SPLITS2*BB*FF*EE];    // stage-2 partials
__device__ float  g_part2[SPLITK_P*BB*CIN*EE];  // tmp partials [zb][c][e]
__device__ __half g_xh  [BB*VV*CIN];       // [b][v][c]
__device__ __half g_xT  [BB*CIN*VV];       // [b][c][v]
__device__ __half g_xT7 [7*BB*CIN*VV];     // [dx+3][b][c][v], col-shift masked
__device__ __half g_G   [BB*FF*LD2];       // [b][f][tap*256+c]
__device__ __half g_wte [EE*LD2];          // [e][tap*256+c]
__device__ __half g_wpht[FF*CIN];          // [f][c]
__device__ __half g_at  [BB*EE*FF];        // [b][e][f] = a_f * t_fe
__device__ __half g_btmpH[BB*CIN*EE];      // hi of Binv*tmp, [b][c][e]
__device__ __half g_btmpL[BB*CIN*EE];      // lo
__device__ __half g_w2th[COUT*CIN];        // w2^T hi [o][c]
__device__ __half g_w2tl[COUT*CIN];        // w2^T lo

// ======================= PTX helpers ========================================
__device__ __forceinline__ uint32_t smem_u32(const void* p) {
    uint32_t a;
    asm("{ .reg .u64 t; cvta.to.shared.u64 t, %1; cvt.u32.u64 %0, t; }" : "=r"(a) : "l"(p));
    return a;
}
#define CP_ASYNC16(dst, src, sz) \
    asm volatile("cp.async.cg.shared.global [%0], [%1], 16, %2;" \
                 :: "r"(dst), "l"(src), "r"(sz) : "memory")
#define CP_COMMIT() asm volatile("cp.async.commit_group;" ::: "memory")
#define CP_WAIT(n)  asm volatile("cp.async.wait_group %0;" :: "n"(n) : "memory")
#define LDSM4(r, addr) \
    asm volatile("ldmatrix.sync.aligned.m8n8.x4.shared.b16 {%0,%1,%2,%3}, [%4];" \
                 : "=r"((r)[0]), "=r"((r)[1]), "=r"((r)[2]), "=r"((r)[3]) : "r"(addr))
#define MMA16816H(d, a, b0, b1) \
    asm volatile("mma.sync.aligned.m16n8k16.row.col.f32.f16.f16.f32 " \
                 "{%0,%1,%2,%3}, {%4,%5,%6,%7}, {%8,%9}, {%0,%1,%2,%3};" \
                 : "+f"((d)[0]), "+f"((d)[1]), "+f"((d)[2]), "+f"((d)[3]) \
                 : "r"((a)[0]), "r"((a)[1]), "r"((a)[2]), "r"((a)[3]), \
                   "r"(b0), "r"(b1))

// ======================= HMMA tile constants ================================
#define ROWB   144
#define TILE_B (128*ROWB)
#define OFF_A   0
#define OFF_B   (TILE_B)
#define STAGE_B (2*TILE_B)     // 36864 (A+B)
#define OFF_BL  (2*TILE_B)
#define STAGE3_B (3*TILE_B)    // 55296 (A + Bhi + Blo)
#define OFF_AL4 (TILE_B)
#define OFF_BH4 (2*TILE_B)
#define OFF_BL4 (3*TILE_B)
#define STAGE4_B (4*TILE_B)    // 73728 (Ah + Al + Bh + Bl)

// ======================= prep / conversion kernels ==========================
// one pass over x: xh[v][c] fp16 + xT[c][v] fp16 (32x32 tile transpose)
__global__ void k_prep_x(const float* __restrict__ x, __half* __restrict__ xh,
                         __half* __restrict__ xT)
{
    __shared__ __half t[32][33];
    const int v0 = blockIdx.x * 32, c0 = blockIdx.y * 32, b = blockIdx.z;
    const int tx = threadIdx.x, ty = threadIdx.y;   // 32 x 8
    #pragma unroll
    for (int j = 0; j < 4; j++) {
        int r = ty + j*8;
        __half h = __float2half(x[((long)b*VV + v0 + r)*CIN + c0 + tx]);
        xh[((long)b*VV + v0 + r)*CIN + c0 + tx] = h;
        t[r][tx] = h;
    }
    __syncthreads();
    #pragma unroll
    for (int j = 0; j < 4; j++) {
        int r = ty + j*8;
        xT[((long)b*CIN + c0 + r)*VV + v0 + tx] = t[tx][r];
    }
}

// phi16 [b][v][f] -> phiT [b][f][v]
__global__ void k_tr_phi(const __half* __restrict__ phi, __half* __restrict__ phiT)
{
    __shared__ __half t[32][33];
    const int v0 = blockIdx.x * 32, f0 = blockIdx.y * 32, b = blockIdx.z;
    const int tx = threadIdx.x, ty = threadIdx.y;
    #pragma unroll
    for (int j = 0; j < 4; j++) {
        int r = ty + j*8;
        t[r][tx] = phi[((long)b*VV + v0 + r)*FF + f0 + tx];
    }
    __syncthreads();
    #pragma unroll
    for (int j = 0; j < 4; j++) {
        int r = ty + j*8;
        phiT[((long)b*FF + f0 + r)*VV + v0 + tx] = t[tx][r];
    }
}

// HDT[b][e][v] = D[b][v] * H16[b][v][e]   (32x32 tile transpose + row scale)
__global__ void k_tr_hd(const __half* __restrict__ H, const float* __restrict__ D,
                        __half* __restrict__ HDT)
{
    __shared__ __half t[32][33];
    const int v0 = blockIdx.x * 32, e0 = blockIdx.y * 32, b = blockIdx.z;
    const int tx = threadIdx.x, ty = threadIdx.y;
    #pragma unroll
    for (int j = 0; j < 4; j++) {
        int r = ty + j*8;
        float d = D[b*VV + v0 + r];
        t[r][tx] = __float2half(d * __half2float(H[((long)b*VV + v0 + r)*EE + e0 + tx]));
    }
    __syncthreads();
    #pragma unroll
    for (int j = 0; j < 4; j++) {
        int r = ty + j*8;
        HDT[((long)b*EE + e0 + r)*VV + v0 + tx] = t[tx][r];
    }
}

// xT7[dxslot][b][c][u] = (uw+dx in [0,64)) ? xT[b][c][u+dx] : 0
__global__ void k_shift7(const __half* __restrict__ xT, __half* __restrict__ xT7)
{
    const int dxslot = blockIdx.y;
    const int dx = dxslot - 3;
    long base = (long)blockIdx.x * 2048 + threadIdx.x * 8;
    if (base >= (long)BB*CIN*VV) return;
    const int uw0 = (int)(base & 63);
    __half v[8];
    #pragma unroll
    for (int j = 0; j < 8; j++) {
        int uw = uw0 + j;
        v[j] = ((unsigned)(uw + dx) < 64u) ? xT[base + j + dx] : __half(0.f);
    }
    *(uint4*)(xT7 + (long)dxslot*BB*CIN*VV + base) = *(uint4*)v;
}

// wte[e][tap*256+c] = wm[tap][c][e] — 32x32 smem tile transpose (coalesced)
__global__ void k_cvt_wte(const float* __restrict__ wm, __half* __restrict__ wte)
{
    __shared__ __half t[32][33];
    const int k0 = blockIdx.x * 32, e0 = blockIdx.y * 32;   // k = tap*256+c
    const int tx = threadIdx.x, ty = threadIdx.y;
    #pragma unroll
    for (int j = 0; j < 4; j++) {
        int r = k0 + ty + j*8;                               // wm row (tap*CIN+c)
        t[ty + j*8][tx] = __float2half(wm[(long)r*EE + e0 + tx]);
    }
    __syncthreads();
    #pragma unroll
    for (int j = 0; j < 4; j++) {
        int r = ty + j*8;
        wte[(long)(e0 + r)*LD2 + k0 + tx] = t[tx][r];
    }
}

__global__ void k_cvt_wpht(const float* __restrict__ wph, __half* __restrict__ wt)
{
    int i = blockIdx.x * 256 + threadIdx.x;
    if (i >= FF*CIN) return;
    int f = i / CIN, c = i % CIN;
    wt[i] = __float2half(wph[c*FF + f]);
}

// w2t hi/lo [o][c]
__global__ void k_cvt_w2t2(const float* __restrict__ w2, __half* __restrict__ wh,
                           __half* __restrict__ wl)
{
    int i = blockIdx.x * 256 + threadIdx.x;
    if (i >= COUT*CIN) return;
    int o = i / CIN, c = i % CIN;
    float v = w2[c*COUT + o];
    __half h = __float2half(v);
    wh[i] = h;
    wl[i] = __float2half(v - __half2float(h));
}

// P[b][f] = sum_v phiT[b][f][v]
__global__ void k_rowsum_phi(const __half* __restrict__ phiT, float* __restrict__ P)
{
    const int row  = blockIdx.x * 8 + (threadIdx.x >> 5);
    const int lane = threadIdx.x & 31;
    if (row >= BB*FF) return;
    const __half2* r = (const __half2*)(phiT + (long)row * VV);
    float s = 0.f;
    for (int c = lane; c < VV/2; c += 32) {
        float2 f = __half22float2(r[c]);
        s += f.x + f.y;
    }
    for (int o = 16; o; o >>= 1) s += __shfl_xor_sync(0xFFFFFFFFu, s, o);
    if (lane == 0) P[row] = s;
}

// at16[b][e][f] = half( a[b][f] * ( sum_s part[(b*14+s)][f][e] + P[b][f]*bm[e] ) )
__global__ void k_at_reduce(const float* __restrict__ part, const float* __restrict__ P,
                            const float* __restrict__ bm, const float* __restrict__ a,
                            __half* __restrict__ at)
{
    int i = blockIdx.x * 256 + threadIdx.x;
    if (i >= BB*EE*FF) return;
    int b = i / (EE*FF), r = i % (EE*FF);
    int e = r / FF, f = r % FF;
    float s = P[b*FF + f] * bm[e];
    #pragma unroll
    for (int sp = 0; sp < SPLITS2; sp++)
        s += part[((long)(b*SPLITS2 + sp))*FF*EE + f*EE + e];
    at[i] = __float2half(a[b*FF + f] * s);
}

// btmp hi/lo from tmp partials: v = Be[b][e] * sum_s part2[(b*8+s)][c][e]
__global__ void k_btmp_reduce(const float* __restrict__ part, const float* __restrict__ Be,
                              __half* __restrict__ bh, __half* __restrict__ bl)
{
    int i = blockIdx.x * 256 + threadIdx.x;     // b*CIN*EE + c*EE + e
    if (i >= BB*CIN*EE) return;
    int b = i / (CIN*EE), r = i % (CIN*EE);
    int e = r % EE;
    float s = 0.f;
    #pragma unroll
    for (int sp = 0; sp < SPLITK_P; sp++)
        s += part[((long)(b*SPLITK_P + sp))*CIN*EE + r];
    float v = Be[b*EE + e] * s;
    __half h = __float2half(v);
    bh[i] = h;
    bl[i] = __float2half(v - __half2float(h));
}

// ======================= HMMA generic NN GEMM (modes 0,1) ===================
template<int MODE>
__global__ __launch_bounds__(256, 2) void hgemm_nn(
    const __half* __restrict__ A, const __half* __restrict__ Bt, __half* __restrict__ C,
    const float* __restrict__ bias,
    int K, int N, int nk, long aB, long bB, long cB)
{
    extern __shared__ __align__(128) char smem[];
    const uint32_t sbase = smem_u32(smem);
    const int tid = threadIdx.x;
    const int wid = tid >> 5, lane = tid & 31;
    const int n0 = blockIdx.x * 128, m0 = blockIdx.y * 128, b = blockIdx.z;
    const int warpm = wid >> 1, warpn = wid & 1;

    const __half* Ab = A + (long)b * aB;
    const __half* Bb = Bt + (long)b * bB;

    const int rowA = tid >> 1, half = (tid & 1) * 32;
    const uint32_t dstRow = rowA * ROWB + half * 2;

    auto issue = [&](int it) {
        const int kc = it * 64;
        const long aoff = (long)(m0 + rowA) * K + kc + half;
        const long boff = (long)(n0 + rowA) * K + kc + half;
        const uint32_t stg = sbase + (it & 1) * STAGE_B;
        #pragma unroll
        for (int j = 0; j < 4; j++) {
            CP_ASYNC16(stg + OFF_A + dstRow + j*16, Ab + aoff + j*8, 16u);
            CP_ASYNC16(stg + OFF_B + dstRow + j*16, Bb + boff + j*8, 16u);
        }
        CP_COMMIT();
    };

    float acc[2][8][4];
    #pragma unroll
    for (int mt = 0; mt < 2; mt++)
        #pragma unroll
        for (int nt = 0; nt < 8; nt++)
            #pragma unroll
            for (int q = 0; q < 4; q++) acc[mt][nt][q] = 0.f;

    const uint32_t aLdOff = (warpm*32 + (lane & 15)) * ROWB + (lane >> 4) * 16;
    const uint32_t bLdOff = (warpn*64 + (lane & 7) + ((lane >> 4) & 1) * 8) * ROWB
                          + (((lane >> 3) & 1) * 8) * 2;

    issue(0);

    for (int it = 0; it < nk; it++) {
        if (it + 1 < nk) { issue(it + 1); CP_WAIT(1); }
        else             { CP_WAIT(0); }
        __syncthreads();

        const uint32_t stg = sbase + (it & 1) * STAGE_B;
        #pragma unroll
        for (int k16 = 0; k16 < 4; k16++) {
            const uint32_t kByte = k16 * 32;
            uint32_t ah[2][4];
            #pragma unroll
            for (int mt = 0; mt < 2; mt++)
                LDSM4(ah[mt], stg + OFF_A + aLdOff + mt * 16 * ROWB + kByte);
            #pragma unroll
            for (int np = 0; np < 4; np++) {
                uint32_t bb[4];
                LDSM4(bb, stg + OFF_B + bLdOff + np * 16 * ROWB + kByte);
                #pragma unroll
                for (int mt = 0; mt < 2; mt++) {
                    MMA16816H(acc[mt][2*np],   ah[mt], bb[0], bb[1]);
                    MMA16816H(acc[mt][2*np+1], ah[mt], bb[2], bb[3]);
                }
            }
        }
        __syncthreads();
    }

    const int r = lane >> 2, c2 = (lane & 3) * 2;
    #pragma unroll
    for (int mt = 0; mt < 2; mt++) {
        #pragma unroll
        for (int nt = 0; nt < 8; nt++) {
            const int m = m0 + warpm*32 + mt*16 + r;
            const int n = n0 + warpn*64 + nt*8 + c2;
            float c00 = acc[mt][nt][0], c01 = acc[mt][nt][1];
            float c10 = acc[mt][nt][2], c11 = acc[mt][nt][3];
            if (MODE == 0) {
                const float bx = bias[n], by = bias[n+1];
                c00 += bx; c01 += by; c10 += bx; c11 += by;
            } else {
                c00 = fabsf(c00); c01 = fabsf(c01);
                c10 = fabsf(c10); c11 = fabsf(c11);
            }
            __half* cp = C + (long)b*cB + (long)m * N + n;
            *(__half2*)cp          = __floats2half2_rn(c00, c01);
            *(__half2*)(cp + 8L*N) = __floats2half2_rn(c10, c11);
        }
    }
}

// ======================= G-GEMM: shifted correlations =======================
__global__ __launch_bounds__(256, 2) void gconv_mma(
    const __half* __restrict__ phiT, const __half* __restrict__ xT7,
    __half* __restrict__ G)
{
    extern __shared__ __align__(128) char smem[];
    const uint32_t sbase = smem_u32(smem);
    const int tid = threadIdx.x;
    const int wid = tid >> 5, lane = tid & 31;
    const int n0 = blockIdx.x * 128, tap = blockIdx.y, b = blockIdx.z;
    const int dy = tap / 7 - 3, dx = tap % 7 - 3;
    const int warpm = wid >> 1, warpn = wid & 1;

    const __half* Ab = phiT + (long)b * FF * VV;
    const __half* Bb = xT7 + ((long)(dx + 3) * BB + b) * CIN * VV;

    const int rowA = tid >> 1, half = (tid & 1) * 32;
    const uint32_t dstRow = rowA * ROWB + half * 2;

    auto issue = [&](int it) {
        const long aoff = (long)rowA * VV + it * 64 + half;
        const int vh2 = it + dy;
        const bool ok = ((unsigned)vh2 < 64u);
        const uint32_t szB = ok ? 16u : 0u;
        const long boff = (long)(n0 + rowA) * VV + (ok ? vh2 : 0) * 64 + half;
        const uint32_t stg = sbase + (it & 1) * STAGE_B;
        #pragma unroll
        for (int j = 0; j < 4; j++) {
            CP_ASYNC16(stg + OFF_A + dstRow + j*16, Ab + aoff + j*8, 16u);
            CP_ASYNC16(stg + OFF_B + dstRow + j*16, Bb + boff + j*8, szB);
        }
        CP_COMMIT();
    };

    float acc[2][8][4];
    #pragma unroll
    for (int mt = 0; mt < 2; mt++)
        #pragma unroll
        for (int nt = 0; nt < 8; nt++)
            #pragma unroll
            for (int q = 0; q < 4; q++) acc[mt][nt][q] = 0.f;

    const uint32_t aLdOff = (warpm*32 + (lane & 15)) * ROWB + (lane >> 4) * 16;
    const uint32_t bLdOff = (warpn*64 + (lane & 7) + ((lane >> 4) & 1) * 8) * ROWB
                          + (((lane >> 3) & 1) * 8) * 2;

    issue(0);

    for (int it = 0; it < 64; it++) {
        if (it + 1 < 64) { issue(it + 1); CP_WAIT(1); }
        else             { CP_WAIT(0); }
        __syncthreads();

        const uint32_t stg = sbase + (it & 1) * STAGE_B;
        #pragma unroll
        for (int k16 = 0; k16 < 4; k16++) {
            const uint32_t kByte = k16 * 32;
            uint32_t ah[2][4];
            #pragma unroll
            for (int mt = 0; mt < 2; mt++)
                LDSM4(ah[mt], stg + OFF_A + aLdOff + mt * 16 * ROWB + kByte);
            #pragma unroll
            for (int np = 0; np < 4; np++) {
                uint32_t bb[4];
                LDSM4(bb, stg + OFF_B + bLdOff + np * 16 * ROWB + kByte);
                #pragma unroll
                for (int mt = 0; mt < 2; mt++) {
                    MMA16816H(acc[mt][2*np],   ah[mt], bb[0], bb[1]);
                    MMA16816H(acc[mt][2*np+1], ah[mt], bb[2], bb[3]);
                }
            }
        }
        __syncthreads();
    }

    const int r = lane >> 2, c2 = (lane & 3) * 2;
    __half* Gb = G + (long)b * FF * LD2 + tap * 256;
    #pragma unroll
    for (int mt = 0; mt < 2; mt++) {
        #pragma unroll
        for (int nt = 0; nt < 8; nt++) {
            const int m = warpm*32 + mt*16 + r;
            const int n = n0 + warpn*64 + nt*8 + c2;
            __half* cp = Gb + (long)m * LD2 + n;
            *(__half2*)cp            = __floats2half2_rn(acc[mt][nt][0], acc[mt][nt][1]);
            *(__half2*)(cp + 8L*LD2) = __floats2half2_rn(acc[mt][nt][2], acc[mt][nt][3]);
        }
    }
}

// ======================= stage-2: t partials (split-K) ======================
__global__ __launch_bounds__(256, 2) void hgemm_s2(
    const __half* __restrict__ G, const __half* __restrict__ wte,
    float* __restrict__ part)
{
    extern __shared__ __align__(128) char smem[];
    const uint32_t sbase = smem_u32(smem);
    const int tid = threadIdx.x;
    const int wid = tid >> 5, lane = tid & 31;
    const int n0 = blockIdx.x * 128, zb = blockIdx.z;
    const int b = zb / SPLITS2, s = zb % SPLITS2;
    const int kbeg = s * 14;
    const int warpm = wid >> 1, warpn = wid & 1;

    const __half* Ab = G + (long)b * FF * LD2;

    const int rowA = tid >> 1, half = (tid & 1) * 32;
    const uint32_t dstRow = rowA * ROWB + half * 2;

    auto issue = [&](int it) {
        const int kc = (kbeg + it) * 64;
        const long aoff = (long)rowA * LD2 + kc + half;
        const long boff = (long)(n0 + rowA) * LD2 + kc + half;
        const uint32_t stg = sbase + (it & 1) * STAGE_B;
        #pragma unroll
        for (int j = 0; j < 4; j++) {
            CP_ASYNC16(stg + OFF_A + dstRow + j*16, Ab + aoff + j*8, 16u);
            CP_ASYNC16(stg + OFF_B + dstRow + j*16, wte + boff + j*8, 16u);
        }
        CP_COMMIT();
    };

    float acc[2][8][4];
    #pragma unroll
    for (int mt = 0; mt < 2; mt++)
        #pragma unroll
        for (int nt = 0; nt < 8; nt++)
            #pragma unroll
            for (int q = 0; q < 4; q++) acc[mt][nt][q] = 0.f;

    const uint32_t aLdOff = (warpm*32 + (lane & 15)) * ROWB + (lane >> 4) * 16;
    const uint32_t bLdOff = (warpn*64 + (lane & 7) + ((lane >> 4) & 1) * 8) * ROWB
                          + (((lane >> 3) & 1) * 8) * 2;

    issue(0);

    for (int it = 0; it < 14; it++) {
        if (it + 1 < 14) { issue(it + 1); CP_WAIT(1); }
        else             { CP_WAIT(0); }
        __syncthreads();

        const uint32_t stg = sbase + (it & 1) * STAGE_B;
        #pragma unroll
        for (int k16 = 0; k16 < 4; k16++) {
            const uint32_t kByte = k16 * 32;
            uint32_t ah[2][4];
            #pragma unroll
            for (int mt = 0; mt < 2; mt++)
                LDSM4(ah[mt], stg + OFF_A + aLdOff + mt * 16 * ROWB + kByte);
            #pragma unroll
            for (int np = 0; np < 4; np++) {
                uint32_t bb[4];
                LDSM4(bb, stg + OFF_B + bLdOff + np * 16 * ROWB + kByte);
                #pragma unroll
                for (int mt = 0; mt < 2; mt++) {
                    MMA16816H(acc[mt][2*np],   ah[mt], bb[0], bb[1]);
                    MMA16816H(acc[mt][2*np+1], ah[mt], bb[2], bb[3]);
                }
            }
        }
        __syncthreads();
    }

    const int r = lane >> 2, c2 = (lane & 3) * 2;
    float* Cb = part + (long)zb * FF * EE;
    #pragma unroll
    for (int mt = 0; mt < 2; mt++) {
        #pragma unroll
        for (int nt = 0; nt < 8; nt++) {
            const int m = warpm*32 + mt*16 + r;
            const int n = n0 + warpn*64 + nt*8 + c2;
            float* cp = Cb + (long)m * EE + n;
            *(float2*)cp           = make_float2(acc[mt][nt][0], acc[mt][nt][1]);
            *(float2*)(cp + 8L*EE) = make_float2(acc[mt][nt][2], acc[mt][nt][3]);
        }
    }
}

// ======================= tmp GEMM: tmpT[c][e] split-K HMMA ==================
// part2[b*8+s][c][e] = sum_{v slice} xT[b][c][v] * HDT[b][e][v]
__global__ __launch_bounds__(256, 2) void hgemm_tmp(
    const __half* __restrict__ xT, const __half* __restrict__ HDT,
    float* __restrict__ part)
{
    extern __shared__ __align__(128) char smem[];
    const uint32_t sbase = smem_u32(smem);
    const int tid = threadIdx.x;
    const int wid = tid >> 5, lane = tid & 31;
    const int n0 = blockIdx.x * 128, m0 = blockIdx.y * 128, zb = blockIdx.z;
    const int b = zb / SPLITK_P, s = zb % SPLITK_P;
    const int kbeg = s * (64 / SPLITK_P);            // chunks of 64 v
    const int warpm = wid >> 1, warpn = wid & 1;

    const __half* Ab = xT + (long)b * CIN * VV;
    const __half* Bb = HDT + (long)b * EE * VV;

    const int rowA = tid >> 1, half = (tid & 1) * 32;
    const uint32_t dstRow = rowA * ROWB + half * 2;

    auto issue = [&](int it) {
        const int kc = (kbeg + it) * 64;
        const long aoff = (long)(m0 + rowA) * VV + kc + half;
        const long boff = (long)(n0 + rowA) * VV + kc + half;
        const uint32_t stg = sbase + (it & 1) * STAGE_B;
        #pragma unroll
        for (int j = 0; j < 4; j++) {
            CP_ASYNC16(stg + OFF_A + dstRow + j*16, Ab + aoff + j*8, 16u);
            CP_ASYNC16(stg + OFF_B + dstRow + j*16, Bb + boff + j*8, 16u);
        }
        CP_COMMIT();
    };

    float acc[2][8][4];
    #pragma unroll
    for (int mt = 0; mt < 2; mt++)
        #pragma unroll
        for (int nt = 0; nt < 8; nt++)
            #pragma unroll
            for (int q = 0; q < 4; q++) acc[mt][nt][q] = 0.f;

    const uint32_t aLdOff = (warpm*32 + (lane & 15)) * ROWB + (lane >> 4) * 16;
    const uint32_t bLdOff = (warpn*64 + (lane & 7) + ((lane >> 4) & 1) * 8) * ROWB
                          + (((lane >> 3) & 1) * 8) * 2;

    issue(0);

    const int nk = 64 / SPLITK_P;
    for (int it = 0; it < nk; it++) {
        if (it + 1 < nk) { issue(it + 1); CP_WAIT(1); }
        else             { CP_WAIT(0); }
        __syncthreads();

        const uint32_t stg = sbase + (it & 1) * STAGE_B;
        #pragma unroll
        for (int k16 = 0; k16 < 4; k16++) {
            const uint32_t kByte = k16 * 32;
            uint32_t ah[2][4];
            #pragma unroll
            for (int mt = 0; mt < 2; mt++)
                LDSM4(ah[mt], stg + OFF_A + aLdOff + mt * 16 * ROWB + kByte);
            #pragma unroll
            for (int np = 0; np < 4; np++) {
                uint32_t bb[4];
                LDSM4(bb, stg + OFF_B + bLdOff + np * 16 * ROWB + kByte);
                #pragma unroll
                for (int mt = 0; mt < 2; mt++) {
                    MMA16816H(acc[mt][2*np],   ah[mt], bb[0], bb[1]);
                    MMA16816H(acc[mt][2*np+1], ah[mt], bb[2], bb[3]);
                }
            }
        }
        __syncthreads();
    }

    const int r = lane >> 2, c2 = (lane & 3) * 2;
    float* Cb = part + (long)zb * CIN * EE;
    #pragma unroll
    for (int mt = 0; mt < 2; mt++) {
        #pragma unroll
        for (int nt = 0; nt < 8; nt++) {
            const int m = m0 + warpm*32 + mt*16 + r;
            const int n = n0 + warpn*64 + nt*8 + c2;
            float* cp = Cb + (long)m * EE + n;
            *(float2*)cp           = make_float2(acc[mt][nt][0], acc[mt][nt][1]);
            *(float2*)(cp + 8L*EE) = make_float2(acc[mt][nt][2], acc[mt][nt][3]);
        }
    }
}

// ======================= R-GEMM: 2-product, hi/lo fp16 out ==================
// R[b][v][c] = x - D[v] * sum_e H[v][e]*(btmpH+btmpL)[c][e]; write Rh/Rl.
__global__ __launch_bounds__(256, 2) void hgemm_rgemm(
    const __half* __restrict__ H, const __half* __restrict__ BH,
    const __half* __restrict__ BL, const float* __restrict__ D,
    const float* __restrict__ x, __half* __restrict__ Rh, __half* __restrict__ Rl)
{
    extern __shared__ __align__(128) char smem[];
    const uint32_t sbase = smem_u32(smem);
    const int tid = threadIdx.x;
    const int wid = tid >> 5, lane = tid & 31;
    const int n0 = blockIdx.x * 128, m0 = blockIdx.y * 128, b = blockIdx.z;
    const int warpm = wid >> 1, warpn = wid & 1;

    const __half* Ab = H + (long)b * VV * EE;
    const __half* BHb = BH + (long)b * CIN * EE;
    const __half* BLb = BL + (long)b * CIN * EE;

    const int rowA = tid >> 1, half = (tid & 1) * 32;
    const uint32_t dstRow = rowA * ROWB + half * 2;

    auto issue = [&](int it) {
        const int kc = it * 64;
        const long aoff = (long)(m0 + rowA) * EE + kc + half;
        const long boff = (long)(n0 + rowA) * EE + kc + half;
        const uint32_t stg = sbase + (it & 1) * STAGE3_B;
        #pragma unroll
        for (int j = 0; j < 4; j++) {
            CP_ASYNC16(stg + OFF_A  + dstRow + j*16, Ab  + aoff + j*8, 16u);
            CP_ASYNC16(stg + OFF_B  + dstRow + j*16, BHb + boff + j*8, 16u);
            CP_ASYNC16(stg + OFF_BL + dstRow + j*16, BLb + boff + j*8, 16u);
        }
        CP_COMMIT();
    };

    float acc[2][8][4];
    #pragma unroll
    for (int mt = 0; mt < 2; mt++)
        #pragma unroll
        for (int nt = 0; nt < 8; nt++)
            #pragma unroll
            for (int q = 0; q < 4; q++) acc[mt][nt][q] = 0.f;

    const uint32_t aLdOff = (warpm*32 + (lane & 15)) * ROWB + (lane >> 4) * 16;
    const uint32_t bLdOff = (warpn*64 + (lane & 7) + ((lane >> 4) & 1) * 8) * ROWB
                          + (((lane >> 3) & 1) * 8) * 2;

    issue(0);

    for (int it = 0; it < 4; it++) {
        if (it + 1 < 4) { issue(it + 1); CP_WAIT(1); }
        else            { CP_WAIT(0); }
        __syncthreads();

        const uint32_t stg = sbase + (it & 1) * STAGE3_B;
        #pragma unroll
        for (int k16 = 0; k16 < 4; k16++) {
            const uint32_t kByte = k16 * 32;
            uint32_t ah[2][4];
            #pragma unroll
            for (int mt = 0; mt < 2; mt++)
                LDSM4(ah[mt], stg + OFF_A + aLdOff + mt * 16 * ROWB + kByte);
            #pragma unroll
            for (int np = 0; np < 4; np++) {
                uint32_t bh[4], bl[4];
                LDSM4(bh, stg + OFF_B  + bLdOff + np * 16 * ROWB + kByte);
                LDSM4(bl, stg + OFF_BL + bLdOff + np * 16 * ROWB + kByte);
                #pragma unroll
                for (int mt = 0; mt < 2; mt++) {
                    MMA16816H(acc[mt][2*np],   ah[mt], bh[0], bh[1]);
                    MMA16816H(acc[mt][2*np+1], ah[mt], bh[2], bh[3]);
                    MMA16816H(acc[mt][2*np],   ah[mt], bl[0], bl[1]);
                    MMA16816H(acc[mt][2*np+1], ah[mt], bl[2], bl[3]);
                }
            }
        }
        __syncthreads();
    }

    const int r = lane >> 2, c2 = (lane & 3) * 2;
    #pragma unroll
    for (int mt = 0; mt < 2; mt++) {
        #pragma unroll
        for (int nt = 0; nt < 8; nt++) {
            const int m = m0 + warpm*32 + mt*16 + r;
            const int n = n0 + warpn*64 + nt*8 + c2;
            const float d0 = D[b*VV + m], d1 = D[b*VV + m + 8];
            const float* xp0 = x + (long)b*VV*CIN + (long)m * CIN + n;
            float2 x0 = *(const float2*)xp0;
            float2 x1 = *(const float2*)(xp0 + 8L*CIN);
            float v00 = x0.x - d0*acc[mt][nt][0], v01 = x0.y - d0*acc[mt][nt][1];
            float v10 = x1.x - d1*acc[mt][nt][2], v11 = x1.y - d1*acc[mt][nt][3];
            long off = (long)b*VV*CIN + (long)m * CIN + n;
            __half2 h2a = __floats2half2_rn(v00, v01);
            __half2 h2b = __floats2half2_rn(v10, v11);
            *(__half2*)&Rh[off]          = h2a;
            *(__half2*)&Rh[off + 8L*CIN] = h2b;
            float2 fa = __half22float2(h2a);
            float2 fb = __half22float2(h2b);
            *(__half2*)&Rl[off]          = __floats2half2_rn(v00 - fa.x, v01 - fa.y);
            *(__half2*)&Rl[off + 8L*CIN] = __floats2half2_rn(v10 - fb.x, v11 - fb.y);
        }
    }
}

// ======================= out-GEMM: 3-product HMMA, fp32 out =================
// out[m][o] = (Rh+Rl)[m][c] * (w2h+w2l)[o][c] + b2  (drop Rl*w2l)
__global__ __launch_bounds__(256) void hgemm_out3(
    const __half* __restrict__ Rh, const __half* __restrict__ Rl,
    const __half* __restrict__ W2h, const __half* __restrict__ W2l,
    const float* __restrict__ bias, float* __restrict__ out)
{
    extern __shared__ __align__(128) char smem[];
    const uint32_t sbase = smem_u32(smem);
    const int tid = threadIdx.x;
    const int wid = tid >> 5, lane = tid & 31;
    const int n0 = blockIdx.x * 128, m0 = blockIdx.y * 128;
    const int warpm = wid >> 1, warpn = wid & 1;

    const int rowA = tid >> 1, half = (tid & 1) * 32;
    const uint32_t dstRow = rowA * ROWB + half * 2;

    auto issue = [&](int it) {
        const int kc = it * 64;
        const long aoff = (long)(m0 + rowA) * CIN + kc + half;
        const long boff = (long)(n0 + rowA) * CIN + kc + half;
        const uint32_t stg = sbase + (it & 1) * STAGE4_B;
        #pragma unroll
        for (int j = 0; j < 4; j++) {
            CP_ASYNC16(stg + OFF_A   + dstRow + j*16, Rh  + aoff + j*8, 16u);
            CP_ASYNC16(stg + OFF_AL4 + dstRow + j*16, Rl  + aoff + j*8, 16u);
            CP_ASYNC16(stg + OFF_BH4 + dstRow + j*16, W2h + boff + j*8, 16u);
            CP_ASYNC16(stg + OFF_BL4 + dstRow + j*16, W2l + boff + j*8, 16u);
        }
        CP_COMMIT();
    };

    float acc[2][8][4];
    #pragma unroll
    for (int mt = 0; mt < 2; mt++)
        #pragma unroll
        for (int nt = 0; nt < 8; nt++)
            #pragma unroll
            for (int q = 0; q < 4; q++) acc[mt][nt][q] = 0.f;

    const uint32_t aLdOff = (warpm*32 + (lane & 15)) * ROWB + (lane >> 4) * 16;
    const uint32_t bLdOff = (warpn*64 + (lane & 7) + ((lane >> 4) & 1) * 8) * ROWB
                          + (((lane >> 3) & 1) * 8) * 2;

    issue(0);

    for (int it = 0; it < 4; it++) {          // K = CIN = 256
        if (it + 1 < 4) { issue(it + 1); CP_WAIT(1); }
        else            { CP_WAIT(0); }
        __syncthreads();

        const uint32_t stg = sbase + (it & 1) * STAGE4_B;
        #pragma unroll
        for (int k16 = 0; k16 < 4; k16++) {
            const uint32_t kByte = k16 * 32;
            uint32_t ah[2][4], al[2][4];
            #pragma unroll
            for (int mt = 0; mt < 2; mt++) {
                LDSM4(ah[mt], stg + OFF_A   + aLdOff + mt * 16 * ROWB + kByte);
                LDSM4(al[mt], stg + OFF_AL4 + aLdOff + mt * 16 * ROWB + kByte);
            }
            #pragma unroll
            for (int np = 0; np < 4; np++) {
                uint32_t bh[4], bl[4];
                LDSM4(bh, stg + OFF_BH4 + bLdOff + np * 16 * ROWB + kByte);
                LDSM4(bl, stg + OFF_BL4 + bLdOff + np * 16 * ROWB + kByte);
                #pragma unroll
                for (int mt = 0; mt < 2; mt++) {
                    MMA16816H(acc[mt][2*np],   ah[mt], bh[0], bh[1]);
                    MMA16816H(acc[mt][2*np+1], ah[mt], bh[2], bh[3]);
                    MMA16816H(acc[mt][2*np],   ah[mt], bl[0], bl[1]);
                    MMA16816H(acc[mt][2*np+1], ah[mt], bl[2], bl[3]);
                    MMA16816H(acc[mt][2*np],   al[mt], bh[0], bh[1]);
                    MMA16816H(acc[mt][2*np+1], al[mt], bh[2], bh[3]);
                }
            }
        }
        __syncthreads();
    }

    const int r = lane >> 2, c2 = (lane & 3) * 2;
    #pragma unroll
    for (int mt = 0; mt < 2; mt++) {
        #pragma unroll
        for (int nt = 0; nt < 8; nt++) {
            const int m = m0 + warpm*32 + mt*16 + r;
            const int n = n0 + warpn*64 + nt*8 + c2;
            const float bx = bias[n], by = bias[n+1];
            float* cp = out + (long)m * COUT + n;
            *(float2*)cp             = make_float2(acc[mt][nt][0] + bx, acc[mt][nt][1] + by);
            *(float2*)(cp + 8L*COUT) = make_float2(acc[mt][nt][2] + bx, acc[mt][nt][3] + by);
        }
    }
}

// -------------------- small reduction / pointwise kernels -------------------
__global__ void k_xpart(const float* __restrict__ x, float* __restrict__ P)
{
    const int b = blockIdx.x, p = blockIdx.y, c = threadIdx.x;
    const float* base = x + ((long)b * VV + p * 128) * CIN + c;
    float s = 0.f;
    for (int v = 0; v < 128; v++) s += base[(long)v * CIN];
    P[(b * 32 + p) * CIN + c] = s;
}

__global__ void k_xmean(const float* __restrict__ P, float* __restrict__ xm)
{
    const int b = blockIdx.x, c = threadIdx.x;
    float s = 0.f;
    for (int p = 0; p < 32; p++) s += P[(b * 32 + p) * CIN + c];
    xm[b * CIN + c] = s * (1.0f / VV);
}

__global__ void k_a(const float* __restrict__ xmg, const float* __restrict__ wa,
                    const float* __restrict__ ba, float* __restrict__ a)
{
    __shared__ float xm[CIN];
    const int b = blockIdx.x, f = threadIdx.x;
    xm[f] = xmg[b * CIN + f];
    xm[f + 128] = xmg[b * CIN + f + 128];
    __syncthreads();
    float s = ba[f];
    #pragma unroll 8
    for (int c = 0; c < CIN; c++) s += xm[c] * wa[c * FF + f];
    a[b * FF + f] = s;
}

__global__ void k_degD(const __half* __restrict__ H, float* __restrict__ D)
{
    const int row  = blockIdx.x * 8 + (threadIdx.x >> 5);
    const int lane = threadIdx.x & 31;
    if (row >= BB * VV) return;
    const __half2* r = (const __half2*)(H + (long)row * EE);
    float s = 0.f;
    for (int c = lane; c < EE/2; c += 32) {
        float2 f = __half22float2(r[c]);
        s += f.x + f.y;
    }
    for (int o = 16; o; o >>= 1) s += __shfl_xor_sync(0xFFFFFFFFu, s, o);
    if (lane == 0) D[row] = rsqrtf(s);
}

__global__ void k_bpart(const __half* __restrict__ H, float* __restrict__ P)
{
    const int b = blockIdx.x, p = blockIdx.y, e = threadIdx.x;
    const __half* base = H + ((long)b * VV + p * 256) * EE + e;
    float s = 0.f;
    for (int v = 0; v < 256; v++) s += __half2float(base[(long)v * EE]);
    P[(b * 16 + p) * EE + e] = s;
}

__global__ void k_finishBe(const float* __restrict__ P, float* __restrict__ Be)
{
    const int b = blockIdx.x, e = threadIdx.x;
    float s = 0.f;
    for (int p = 0; p < 16; p++) s += P[(b * 16 + p) * EE + e];
    Be[b * EE + e] = 1.0f / s;
}

// ---------------------------------------------------------------------------
extern "C" void kernel_launch(void* const* d_in, const int* in_sizes, int n_in,
                              void* d_out, int out_size)
{
    const float* x   = (const float*)d_in[0];
    const float* wph = (const float*)d_in[1];
    const float* bph = (const float*)d_in[2];
    const float* wa  = (const float*)d_in[3];
    const float* ba  = (const float*)d_in[4];
    const float* wm  = (const float*)d_in[5];
    const float* bm  = (const float*)d_in[6];
    const float* w2  = (const float*)d_in[7];
    const float* b2  = (const float*)d_in[8];
    float* out = (float*)d_out;

    float *Db, *Beb, *ab, *Pb, *xp, *xmg, *bp, *p1, *p2;
    __half *xh, *xT, *xT7, *phi16, *phiT, *H16, *HDT, *Rh, *Rl;
    __half *G, *wte, *wpht, *at16, *btH, *btL, *w2th, *w2tl;
    cudaGetSymbolAddress((void**)&phi16, g_phi16);
    cudaGetSymbolAddress((void**)&phiT, g_phiT);
    cudaGetSymbolAddress((void**)&H16,  g_H16);
    cudaGetSymbolAddress((void**)&HDT,  g_HDT);
    cudaGetSymbolAddress((void**)&Rh,   g_Rh);
    cudaGetSymbolAddress((void**)&Rl,   g_Rl);
    cudaGetSymbolAddress((void**)&Db,   g_D);
    cudaGetSymbolAddress((void**)&Beb,  g_Be);
    cudaGetSymbolAddress((void**)&ab,   g_a);
    cudaGetSymbolAddress((void**)&Pb,   g_P);
    cudaGetSymbolAddress((void**)&xp,   g_xpart);
    cudaGetSymbolAddress((void**)&xmg,  g_xmean);
    cudaGetSymbolAddress((void**)&bp,   g_bpart);
    cudaGetSymbolAddress((void**)&p1,   g_part1);
    cudaGetSymbolAddress((void**)&p2,   g_part2);
    cudaGetSymbolAddress((void**)&xh,   g_xh);
    cudaGetSymbolAddress((void**)&xT,   g_xT);
    cudaGetSymbolAddress((void**)&xT7,  g_xT7);
    cudaGetSymbolAddress((void**)&G,    g_G);
    cudaGetSymbolAddress((void**)&wte,  g_wte);
    cudaGetSymbolAddress((void**)&wpht, g_wpht);
    cudaGetSymbolAddress((void**)&at16, g_at);
    cudaGetSymbolAddress((void**)&btH,  g_btmpH);
    cudaGetSymbolAddress((void**)&btL,  g_btmpL);
    cudaGetSymbolAddress((void**)&w2th, g_w2th);
    cudaGetSymbolAddress((void**)&w2tl, g_w2tl);

    cudaFuncSetAttribute(hgemm_nn<0>, cudaFuncAttributeMaxDynamicSharedMemorySize, STAGE_B*2);
    cudaFuncSetAttribute(hgemm_nn<1>, cudaFuncAttributeMaxDynamicSharedMemorySize, STAGE_B*2);
    cudaFuncSetAttribute(gconv_mma,   cudaFuncAttributeMaxDynamicSharedMemorySize, STAGE_B*2);
    cudaFuncSetAttribute(hgemm_s2,    cudaFuncAttributeMaxDynamicSharedMemorySize, STAGE_B*2);
    cudaFuncSetAttribute(hgemm_tmp,   cudaFuncAttributeMaxDynamicSharedMemorySize, STAGE_B*2);
    cudaFuncSetAttribute(hgemm_rgemm, cudaFuncAttributeMaxDynamicSharedMemorySize, STAGE3_B*2);
    cudaFuncSetAttribute(hgemm_out3,  cudaFuncAttributeMaxDynamicSharedMemorySize, STAGE4_B*2);

    // 0) conversions / transposes / shifted copies
    k_prep_x<<<dim3(VV/32, CIN/32, BB), dim3(32, 8)>>>(x, xh, xT);
    k_shift7<<<dim3((unsigned)(((long)BB*VV*CIN + 2047)/2048), 7), 256>>>(xT, xT7);
    k_cvt_wte<<<dim3(LD2/32, EE/32), dim3(32, 8)>>>(wm, wte);
    k_cvt_wpht<<<(FF*CIN + 255)/256, 256>>>(wph, wpht);
    k_cvt_w2t2<<<(COUT*CIN + 255)/256, 256>>>(w2, w2th, w2tl);

    // 1) pooled mean + a vector
    k_xpart<<<dim3(BB, 32), 256>>>(x, xp);
    k_xmean<<<BB, 256>>>(xp, xmg);
    k_a<<<BB, 128>>>(xmg, wa, ba, ab);

    // 2) phi = x @ w_phi + b_phi  (HMMA), then transpose + column sums
    hgemm_nn<0><<<dim3(1, 256, 1), 256, STAGE_B*2>>>(
        xh, wpht, phi16, bph, CIN, FF, 4, 0, 0, 0);
    k_tr_phi<<<dim3(VV/32, FF/32, BB), dim3(32, 8)>>>(phi16, phiT);
    k_rowsum_phi<<<BB*FF/8, 256>>>(phiT, Pb);

    // 3) G = 49 shifted correlations phi^T (x) x
    gconv_mma<<<dim3(CIN/128, 49, BB), 256, STAGE_B*2>>>(phiT, xT7, G);

    // 4) t = G @ w (+ rank-1 bias), split-K, fold a -> at16
    hgemm_s2<<<dim3(EE/128, 1, BB*SPLITS2), 256, STAGE_B*2>>>(G, wte, p1);
    k_at_reduce<<<(BB*EE*FF + 255)/256, 256>>>(p1, Pb, bm, ab, at16);

    // 5) H = | phi @ (diag(a) t) |
    hgemm_nn<1><<<dim3(2, 32, BB), 256, STAGE_B*2>>>(
        phi16, at16, H16, nullptr, FF, EE, 2,
        (long)VV*FF, (long)EE*FF, (long)VV*EE);

    // 6) degrees + HDT
    k_degD<<<(BB*VV)/8, 256>>>(H16, Db);
    k_bpart<<<dim3(BB, 16), 256>>>(H16, bp);
    k_finishBe<<<BB, 256>>>(bp, Beb);
    k_tr_hd<<<dim3(VV/32, EE/32, BB), dim3(32, 8)>>>(H16, Db, HDT);

    // 7) tmpT = xT @ HDT^T  (split-K HMMA), reduce + Binv fold -> btmp hi/lo
    hgemm_tmp<<<dim3(EE/128, CIN/128, BB*SPLITK_P), 256, STAGE_B*2>>>(xT, HDT, p2);
    k_btmp_reduce<<<(BB*CIN*EE + 255)/256, 256>>>(p2, Beb, btH, btL);

    // 8) R = x - D^-1/2 * (H @ (btmpH+btmpL)^T)   -> Rh/Rl fp16 pair
    hgemm_rgemm<<<dim3(2, 32, BB), 256, STAGE3_B*2>>>(H16, btH, btL, Db, x, Rh, Rl);

    // 9) out = (Rh+Rl) @ (w2h+w2l) + b2   (3-product HMMA, fp32 out)
    hgemm_out3<<<dim3(COUT/128, (BB*VV)/128, 1), 256, STAGE4_B*2>>>(
        Rh, Rl, w2th, w2tl, b2, out);
}